// round 2
// baseline (speedup 1.0000x reference)
#include <cuda_runtime.h>
#include <math.h>

#define SCALE 0.08838834764831845f  // 1/sqrt(128)

// ---------------- scratch (__device__ globals; no allocation allowed) ----------------
__device__ float g_hl[512];                         // LN(token)
__device__ float g_qpart[16][512];                  // q partials
__device__ float g_g[4][512];                       // g_h = Wk[:,head] . q_head
__device__ float g_gs[4][512];                      // s1 * g
__device__ float2 g_stats[32][512];                 // (alpha, beta) per key row
__device__ __align__(16) float g_scores[32][512][4];
__device__ __align__(16) float g_wts[32][512][4];   // e * alpha (unnormalized)
__device__ float g_wmisc[32][16];                   // [ewb(4), sev(4), ecls(4), invS(4)]
__device__ __align__(16) float g_ppart[4][32][4][512];
__device__ float g_ctxpart[8][32][512];
__device__ float g_wopart[8][32][512];
__device__ float g_h1[32][512];
__device__ float2 g_ln2[32];                        // (mean, rstd)
__device__ float g_w1part[8][32][2048];
__device__ float g_w2part[16][32][512];

static __device__ __forceinline__ float wred(float v) {
#pragma unroll
    for (int o = 16; o; o >>= 1) v += __shfl_xor_sync(0xffffffffu, v, o);
    return v;
}

static __device__ __forceinline__ float geluf(float t) {
    float t3 = t * t * t;
    return 0.5f * t * (1.f + tanhf(0.7978845608028654f * (t + 0.044715f * t3)));
}

// ---------------- P1: LN(token) + q partials (q = LN(token)@Wq + bq) ----------------
__global__ void k_p1(const float* __restrict__ token, const float* __restrict__ s1,
                     const float* __restrict__ b1, const float* __restrict__ Wq) {
    __shared__ float red[512];
    __shared__ float shl[512];
    int tid = threadIdx.x;  // 512
    float t = token[tid];
    red[tid] = t;
    __syncthreads();
#pragma unroll
    for (int o = 256; o; o >>= 1) {
        if (tid < o) red[tid] += red[tid + o];
        __syncthreads();
    }
    float mean = red[0] * (1.f / 512.f);
    __syncthreads();
    float d = t - mean;
    red[tid] = d * d;
    __syncthreads();
#pragma unroll
    for (int o = 256; o; o >>= 1) {
        if (tid < o) red[tid] += red[tid + o];
        __syncthreads();
    }
    float var = red[0] * (1.f / 512.f);
    float rstd = rsqrtf(var + 1e-5f);
    float hl = d * rstd * s1[tid] + b1[tid];
    shl[tid] = hl;
    if (blockIdx.x == 0) g_hl[tid] = hl;
    __syncthreads();
    int i0 = blockIdx.x * 32;
    float acc = 0.f;
#pragma unroll
    for (int j = 0; j < 32; j++)
        acc = fmaf(shl[i0 + j], Wq[(size_t)(i0 + j) * 512 + tid], acc);
    g_qpart[blockIdx.x][tid] = acc;
}

// ---------------- P2: combine q; g[h][r] = Wk[r, head h] . q_head ----------------
__global__ void k_p2(const float* __restrict__ Wk, const float* __restrict__ bq,
                     const float* __restrict__ s1) {
    __shared__ __align__(16) float sq[512];
    int tid = threadIdx.x;  // 256
    for (int c = tid; c < 512; c += 256) {
        float v = bq[c];
#pragma unroll
        for (int s = 0; s < 16; s++) v += g_qpart[s][c];
        sq[c] = v;
    }
    __syncthreads();
    int wp = tid >> 5, lane = tid & 31;
    const float4* q4 = (const float4*)sq;
#pragma unroll
    for (int it = 0; it < 8; it++) {
        int r = blockIdx.x * 64 + it * 8 + wp;
        const float4* wr = (const float4*)(Wk + (size_t)r * 512);
        float dt[4];
#pragma unroll
        for (int t = 0; t < 4; t++) {
            float4 w = __ldg(wr + lane + 32 * t);
            float4 q = q4[lane + 32 * t];
            dt[t] = w.x * q.x + w.y * q.y + w.z * q.z + w.w * q.w;
        }
#pragma unroll
        for (int t = 0; t < 4; t++) dt[t] = wred(dt[t]);
        if (lane == 0) {
            float sr = s1[r];
#pragma unroll
            for (int t = 0; t < 4; t++) {
                g_g[t][r] = dt[t];
                g_gs[t][r] = dt[t] * sr;
            }
        }
    }
}

// ---------------- K1: per-key stats + raw score dots (warp per row) ----------------
__global__ void k_scores(const float* __restrict__ x, const int* __restrict__ mask) {
    int wp = threadIdx.x >> 5, lane = threadIdx.x & 31;
    int r = blockIdx.x * 8 + wp;
    int b = r >> 9, k = r & 511;
    if (k >= __ldg(&mask[b])) return;
    const float4* xr = (const float4*)(x + (size_t)r * 512);
    float4 xv[4];
#pragma unroll
    for (int t = 0; t < 4; t++) xv[t] = __ldg(xr + lane + 32 * t);
    float ss = 0.f, sm = 0.f;
#pragma unroll
    for (int t = 0; t < 4; t++) {
        ss += xv[t].x * xv[t].x + xv[t].y * xv[t].y + xv[t].z * xv[t].z + xv[t].w * xv[t].w;
        sm += xv[t].x + xv[t].y + xv[t].z + xv[t].w;
    }
    ss = wred(ss);
    sm = wred(sm);
    float inv = 1.f / fmaxf(sqrtf(ss), 1e-12f);
    float meany = sm * inv * (1.f / 512.f);
    float vary = ss * inv * inv * (1.f / 512.f) - meany * meany;
    float rstd = rsqrtf(vary + 1e-5f);
    float alpha = inv * rstd, beta = -meany * rstd;
    float d[4];
#pragma unroll
    for (int h = 0; h < 4; h++) {
        const float4* g4 = (const float4*)g_gs[h];
        float a = 0.f;
#pragma unroll
        for (int t = 0; t < 4; t++) {
            float4 g = g4[lane + 32 * t];
            a += xv[t].x * g.x + xv[t].y * g.y + xv[t].z * g.z + xv[t].w * g.w;
        }
        d[h] = wred(a);
    }
    if (lane == 0) {
        g_stats[b][k] = make_float2(alpha, beta);
        *(float4*)&g_scores[b][k][0] = make_float4(d[0], d[1], d[2], d[3]);
    }
}

// ---------------- K2: softmax (one block per batch) ----------------
__global__ void k_softmax(const int* __restrict__ mask, const float* __restrict__ s1,
                          const float* __restrict__ b1) {
    __shared__ float sred[128][12];
    __shared__ float sbc[12];
    int b = blockIdx.x, tid = threadIdx.x;  // 128
    int L = __ldg(&mask[b]);
    float pc[12];
#pragma unroll
    for (int j = 0; j < 12; j++) pc[j] = 0.f;
#pragma unroll
    for (int t = 0; t < 4; t++) {
        int i = tid + 128 * t;
        float s = s1[i], bb = b1[i], hl = g_hl[i];
#pragma unroll
        for (int h = 0; h < 4; h++) {
            float g = g_g[h][i];
            pc[h] += s * g;        // C1
            pc[4 + h] += bb * g;   // C2
            pc[8 + h] += hl * g;   // cls dot
        }
    }
#pragma unroll
    for (int j = 0; j < 12; j++) sred[tid][j] = pc[j];
    __syncthreads();
    for (int o = 64; o; o >>= 1) {
        if (tid < o)
#pragma unroll
            for (int j = 0; j < 12; j++) sred[tid][j] += sred[tid + o][j];
        __syncthreads();
    }
    if (tid < 12) sbc[tid] = sred[0][tid];
    __syncthreads();
    float C1[4], C2[4], scls[4];
#pragma unroll
    for (int h = 0; h < 4; h++) {
        C1[h] = sbc[h];
        C2[h] = sbc[4 + h];
        scls[h] = sbc[8 + h] * SCALE;
    }
    __syncthreads();
    // compose scores + running max
    float mx[4];
#pragma unroll
    for (int h = 0; h < 4; h++) mx[h] = scls[h];
    for (int k = tid; k < L; k += 128) {
        float4 d = *(const float4*)&g_scores[b][k][0];
        float2 ab = g_stats[b][k];
        float4 s;
        s.x = SCALE * (ab.x * d.x + ab.y * C1[0] + C2[0]);
        s.y = SCALE * (ab.x * d.y + ab.y * C1[1] + C2[1]);
        s.z = SCALE * (ab.x * d.z + ab.y * C1[2] + C2[2]);
        s.w = SCALE * (ab.x * d.w + ab.y * C1[3] + C2[3]);
        *(float4*)&g_scores[b][k][0] = s;
        mx[0] = fmaxf(mx[0], s.x);
        mx[1] = fmaxf(mx[1], s.y);
        mx[2] = fmaxf(mx[2], s.z);
        mx[3] = fmaxf(mx[3], s.w);
    }
#pragma unroll
    for (int h = 0; h < 4; h++) sred[tid][h] = mx[h];
    __syncthreads();
    for (int o = 64; o; o >>= 1) {
        if (tid < o)
#pragma unroll
            for (int h = 0; h < 4; h++)
                sred[tid][h] = fmaxf(sred[tid][h], sred[tid + o][h]);
        __syncthreads();
    }
    float M[4];
#pragma unroll
    for (int h = 0; h < 4; h++) M[h] = sred[0][h];
    __syncthreads();
    // exp pass: store e*alpha, accumulate sums
    float se[4] = {0, 0, 0, 0}, ewb[4] = {0, 0, 0, 0};
    for (int k = tid; k < L; k += 128) {
        float4 s = *(const float4*)&g_scores[b][k][0];
        float2 ab = g_stats[b][k];
        float e0 = __expf(s.x - M[0]);
        float e1 = __expf(s.y - M[1]);
        float e2 = __expf(s.z - M[2]);
        float e3 = __expf(s.w - M[3]);
        float4 w = make_float4(e0 * ab.x, e1 * ab.x, e2 * ab.x, e3 * ab.x);
        *(float4*)&g_wts[b][k][0] = w;
        se[0] += e0; se[1] += e1; se[2] += e2; se[3] += e3;
        ewb[0] += e0 * ab.y; ewb[1] += e1 * ab.y; ewb[2] += e2 * ab.y; ewb[3] += e3 * ab.y;
    }
#pragma unroll
    for (int h = 0; h < 4; h++) {
        sred[tid][h] = se[h];
        sred[tid][4 + h] = ewb[h];
    }
    __syncthreads();
    for (int o = 64; o; o >>= 1) {
        if (tid < o)
#pragma unroll
            for (int j = 0; j < 8; j++) sred[tid][j] += sred[tid + o][j];
        __syncthreads();
    }
    if (tid < 4) {
        int h = tid;
        float ec = __expf(scls[h] - M[h]);
        float S = sred[0][h] + ec;
        float invS = 1.f / S;
        g_wmisc[b][h] = sred[0][4 + h];   // sum e*beta
        g_wmisc[b][4 + h] = sred[0][h];   // sum e
        g_wmisc[b][8 + h] = ec;           // e_cls
        g_wmisc[b][12 + h] = invS;
    }
}

// ---------------- K3: accumulate A[h][i] = sum_k (e*alpha)_k * x_k[i] ----------------
__global__ void k_pacc(const float* __restrict__ x, const int* __restrict__ mask) {
    int ks = blockIdx.x, b = blockIdx.y, tid = threadIdx.x;  // 128
    int L = __ldg(&mask[b]);
    int k0 = ks * 128;
    int k1 = min(L, k0 + 128);
    float4 acc[4];
#pragma unroll
    for (int h = 0; h < 4; h++) acc[h] = make_float4(0.f, 0.f, 0.f, 0.f);
#pragma unroll 4
    for (int k = k0; k < k1; k++) {
        float4 xv = __ldg((const float4*)(x + ((size_t)b * 512 + k) * 512) + tid);
        float4 wa = *(const float4*)&g_wts[b][k][0];
        acc[0].x += wa.x * xv.x; acc[0].y += wa.x * xv.y; acc[0].z += wa.x * xv.z; acc[0].w += wa.x * xv.w;
        acc[1].x += wa.y * xv.x; acc[1].y += wa.y * xv.y; acc[1].z += wa.y * xv.z; acc[1].w += wa.y * xv.w;
        acc[2].x += wa.z * xv.x; acc[2].y += wa.z * xv.y; acc[2].z += wa.z * xv.z; acc[2].w += wa.z * xv.w;
        acc[3].x += wa.w * xv.x; acc[3].y += wa.w * xv.y; acc[3].z += wa.w * xv.z; acc[3].w += wa.w * xv.w;
    }
    int i = tid * 4;
#pragma unroll
    for (int h = 0; h < 4; h++) *(float4*)&g_ppart[ks][b][h][i] = acc[h];
}

// ---------------- T1: ctx partials = p @ Wv (per head) ----------------
__global__ void k_T1(const float* __restrict__ Wv, const float* __restrict__ s1,
                     const float* __restrict__ b1) {
    int hh = blockIdx.x, iy = blockIdx.y, tid = threadIdx.x;  // 128
    int i0 = iy * 64, f = hh * 128 + tid;
    __shared__ __align__(16) float sp[32][64];
    for (int idx = tid; idx < 2048; idx += 128) {
        int b = idx >> 6, ii = idx & 63, i = i0 + ii;
        float A = g_ppart[0][b][hh][i] + g_ppart[1][b][hh][i] +
                  g_ppart[2][b][hh][i] + g_ppart[3][b][hh][i];
        const float* wm = g_wmisc[b];
        float ewb = wm[hh], sev = wm[4 + hh], ecls = wm[8 + hh], invS = wm[12 + hh];
        sp[b][ii] = invS * (s1[i] * (A + ewb) + b1[i] * sev + ecls * g_hl[i]);
    }
    __syncthreads();
    float acc[32];
#pragma unroll
    for (int b = 0; b < 32; b++) acc[b] = 0.f;
    for (int ii = 0; ii < 64; ii += 4) {
        int i = i0 + ii;
        float w0 = Wv[(size_t)i * 512 + f];
        float w1 = Wv[(size_t)(i + 1) * 512 + f];
        float w2 = Wv[(size_t)(i + 2) * 512 + f];
        float w3 = Wv[(size_t)(i + 3) * 512 + f];
#pragma unroll
        for (int b = 0; b < 32; b++) {
            float4 p = *(const float4*)&sp[b][ii];
            acc[b] += p.x * w0 + p.y * w1 + p.z * w2 + p.w * w3;
        }
    }
#pragma unroll
    for (int b = 0; b < 32; b++) g_ctxpart[iy][b][f] = acc[b];
}

// ---------------- T2: o partials = (ctx+bv) @ Wo ----------------
__global__ void k_T2(const float* __restrict__ Wo, const float* __restrict__ bv) {
    int cx = blockIdx.x, iy = blockIdx.y, tid = threadIdx.x;  // 128
    int i0 = iy * 64, f = cx * 128 + tid;
    __shared__ __align__(16) float sc[32][64];
    for (int idx = tid; idx < 2048; idx += 128) {
        int b = idx >> 6, ii = idx & 63, i = i0 + ii;
        float v = bv[i];
#pragma unroll
        for (int s = 0; s < 8; s++) v += g_ctxpart[s][b][i];
        sc[b][ii] = v;
    }
    __syncthreads();
    float acc[32];
#pragma unroll
    for (int b = 0; b < 32; b++) acc[b] = 0.f;
    for (int ii = 0; ii < 64; ii += 4) {
        int i = i0 + ii;
        float w0 = Wo[(size_t)i * 512 + f];
        float w1 = Wo[(size_t)(i + 1) * 512 + f];
        float w2 = Wo[(size_t)(i + 2) * 512 + f];
        float w3 = Wo[(size_t)(i + 3) * 512 + f];
#pragma unroll
        for (int b = 0; b < 32; b++) {
            float4 p = *(const float4*)&sc[b][ii];
            acc[b] += p.x * w0 + p.y * w1 + p.z * w2 + p.w * w3;
        }
    }
#pragma unroll
    for (int b = 0; b < 32; b++) g_wopart[iy][b][f] = acc[b];
}

// ---------------- T3: h1 = token + o + bo; LN2 stats ----------------
__global__ void k_T3(const float* __restrict__ token, const float* __restrict__ bo) {
    __shared__ float sred[128][2];
    int b = blockIdx.x, tid = threadIdx.x;  // 128
    float sum = 0.f, ssq = 0.f;
#pragma unroll
    for (int t = 0; t < 4; t++) {
        int c = tid + 128 * t;
        float v = token[c] + bo[c];
#pragma unroll
        for (int s = 0; s < 8; s++) v += g_wopart[s][b][c];
        g_h1[b][c] = v;
        sum += v;
        ssq += v * v;
    }
    sred[tid][0] = sum;
    sred[tid][1] = ssq;
    __syncthreads();
    for (int o = 64; o; o >>= 1) {
        if (tid < o) {
            sred[tid][0] += sred[tid + o][0];
            sred[tid][1] += sred[tid + o][1];
        }
        __syncthreads();
    }
    if (tid == 0) {
        float m = sred[0][0] * (1.f / 512.f);
        float var = sred[0][1] * (1.f / 512.f) - m * m;
        g_ln2[b] = make_float2(m, rsqrtf(var + 1e-5f));
    }
}

// ---------------- T4: W1 partials (h2 @ W1) ----------------
__global__ void k_T4(const float* __restrict__ W1, const float* __restrict__ s2,
                     const float* __restrict__ b2l) {
    int fx = blockIdx.x, iy = blockIdx.y, tid = threadIdx.x;  // 128
    int i0 = iy * 64, f = fx * 128 + tid;
    __shared__ __align__(16) float sh2[32][64];
    for (int idx = tid; idx < 2048; idx += 128) {
        int b = idx >> 6, ii = idx & 63, i = i0 + ii;
        float2 mr = g_ln2[b];
        sh2[b][ii] = (g_h1[b][i] - mr.x) * mr.y * s2[i] + b2l[i];
    }
    __syncthreads();
    float acc[32];
#pragma unroll
    for (int b = 0; b < 32; b++) acc[b] = 0.f;
    for (int ii = 0; ii < 64; ii += 4) {
        int i = i0 + ii;
        float w0 = W1[(size_t)i * 2048 + f];
        float w1 = W1[(size_t)(i + 1) * 2048 + f];
        float w2 = W1[(size_t)(i + 2) * 2048 + f];
        float w3 = W1[(size_t)(i + 3) * 2048 + f];
#pragma unroll
        for (int b = 0; b < 32; b++) {
            float4 p = *(const float4*)&sh2[b][ii];
            acc[b] += p.x * w0 + p.y * w1 + p.z * w2 + p.w * w3;
        }
    }
#pragma unroll
    for (int b = 0; b < 32; b++) g_w1part[iy][b][f] = acc[b];
}

// ---------------- T5: gelu + W2 partials ----------------
__global__ void k_T5(const float* __restrict__ W2, const float* __restrict__ b1f) {
    int fx = blockIdx.x, iy = blockIdx.y, tid = threadIdx.x;  // 128
    int i0 = iy * 128, f = fx * 128 + tid;
    __shared__ __align__(16) float su[32][128];
    for (int idx = tid; idx < 4096; idx += 128) {
        int b = idx >> 7, ii = idx & 127, i = i0 + ii;
        float v = b1f[i];
#pragma unroll
        for (int s = 0; s < 8; s++) v += g_w1part[s][b][i];
        su[b][ii] = geluf(v);
    }
    __syncthreads();
    float acc[32];
#pragma unroll
    for (int b = 0; b < 32; b++) acc[b] = 0.f;
    for (int ii = 0; ii < 128; ii += 4) {
        int i = i0 + ii;
        float w0 = W2[(size_t)i * 512 + f];
        float w1 = W2[(size_t)(i + 1) * 512 + f];
        float w2 = W2[(size_t)(i + 2) * 512 + f];
        float w3 = W2[(size_t)(i + 3) * 512 + f];
#pragma unroll
        for (int b = 0; b < 32; b++) {
            float4 p = *(const float4*)&su[b][ii];
            acc[b] += p.x * w0 + p.y * w1 + p.z * w2 + p.w * w3;
        }
    }
#pragma unroll
    for (int b = 0; b < 32; b++) g_w2part[iy][b][f] = acc[b];
}

// ---------------- OUT: out = h1 + ffn_out + b2 ----------------
__global__ void k_out(const float* __restrict__ b2o, float* __restrict__ out) {
    int b = blockIdx.x, tid = threadIdx.x;  // 128
#pragma unroll
    for (int t = 0; t < 4; t++) {
        int c = tid + 128 * t;
        float v = g_h1[b][c] + b2o[c];
#pragma unroll
        for (int s = 0; s < 16; s++) v += g_w2part[s][b][c];
        out[b * 512 + c] = v;
    }
}

extern "C" void kernel_launch(void* const* d_in, const int* in_sizes, int n_in,
                              void* d_out, int out_size) {
    const float* x     = (const float*)d_in[0];
    const int*   mask  = (const int*)d_in[1];
    const float* token = (const float*)d_in[2];
    const float* Wq    = (const float*)d_in[3];
    const float* bq    = (const float*)d_in[4];
    const float* Wk    = (const float*)d_in[5];
    // d_in[6] = bk: provably cancels under softmax (uniform shift) — unused
    const float* Wv    = (const float*)d_in[7];
    const float* bv    = (const float*)d_in[8];
    const float* Wo    = (const float*)d_in[9];
    const float* bo    = (const float*)d_in[10];
    const float* s1    = (const float*)d_in[11];
    const float* b1    = (const float*)d_in[12];
    const float* s2    = (const float*)d_in[13];
    const float* b2l   = (const float*)d_in[14];
    const float* W1    = (const float*)d_in[15];
    const float* b1f   = (const float*)d_in[16];
    const float* W2    = (const float*)d_in[17];
    const float* b2o   = (const float*)d_in[18];
    float* out = (float*)d_out;

    k_p1<<<16, 512>>>(token, s1, b1, Wq);
    k_p2<<<8, 256>>>(Wk, bq, s1);
    k_scores<<<2048, 256>>>(x, mask);
    k_softmax<<<32, 128>>>(mask, s1, b1);
    k_pacc<<<dim3(4, 32), 128>>>(x, mask);
    k_T1<<<dim3(4, 8), 128>>>(Wv, s1, b1);
    k_T2<<<dim3(4, 8), 128>>>(Wo, bv);
    k_T3<<<32, 128>>>(token, bo);
    k_T4<<<dim3(16, 8), 128>>>(W1, s2, b2l);
    k_T5<<<dim3(4, 16), 128>>>(W2, b1f);
    k_out<<<32, 128>>>(b2o, out);
}

// round 3
// speedup vs baseline: 1.2938x; 1.2938x over previous
#include <cuda_runtime.h>
#include <math.h>

#define SCALE 0.08838834764831845f  // 1/sqrt(128)
#define NB 128
#define NT 256

// ---------------- grid barrier state ----------------
__device__ unsigned g_count;
__device__ unsigned g_release;

// ---------------- scratch ----------------
__device__ __align__(16) float g_hl[512];
__device__ __align__(16) float g_qpart[16][512];
__device__ __align__(16) float g_g[4][512];
__device__ __align__(16) float g_gs[4][512];
__device__ __align__(16) float2 g_stats[32][512];
__device__ __align__(16) float g_scores[32][512][4];
__device__ __align__(16) float g_wts[32][512][4];
__device__ __align__(16) float g_wmisc[32][16];
__device__ __align__(16) float g_ppart[8][32][4][512];
__device__ __align__(16) float g_ctxpart[16][32][512];
__device__ __align__(16) float g_wopart[16][32][512];
__device__ __align__(16) float g_h1[32][512];
__device__ __align__(16) float2 g_ln2[32];
__device__ __align__(16) float g_w1part[16][32][2048];
__device__ __align__(16) float g_w2part[64][32][512];

static __device__ __forceinline__ float wred(float v) {
#pragma unroll
    for (int o = 16; o; o >>= 1) v += __shfl_xor_sync(0xffffffffu, v, o);
    return v;
}

static __device__ __forceinline__ float geluf(float t) {
    float t3 = t * t * t;
    return 0.5f * t * (1.f + tanhf(0.7978845608028654f * (t + 0.044715f * t3)));
}

__device__ __forceinline__ void gridbar(unsigned base, unsigned idx) {
    __syncthreads();
    if (threadIdx.x == 0) {
        __threadfence();
        if (atomicAdd(&g_count, 1u) == NB - 1) {
            g_count = 0;
            __threadfence();
            atomicExch(&g_release, base + idx);
        } else {
            while (atomicAdd(&g_release, 0u) - base < idx) __nanosleep(64);
            __threadfence();
        }
    }
    __syncthreads();
}

__global__ void __launch_bounds__(NT, 1) fused_kernel(
    const float* __restrict__ x, const int* __restrict__ mask,
    const float* __restrict__ token,
    const float* __restrict__ Wq, const float* __restrict__ bq,
    const float* __restrict__ Wk,
    const float* __restrict__ Wv, const float* __restrict__ bv,
    const float* __restrict__ Wo, const float* __restrict__ bo,
    const float* __restrict__ s1, const float* __restrict__ b1,
    const float* __restrict__ s2, const float* __restrict__ b2l,
    const float* __restrict__ W1, const float* __restrict__ b1f,
    const float* __restrict__ W2, const float* __restrict__ b2o,
    float* __restrict__ out) {
    __shared__ float SM[4160];
    __shared__ unsigned s_base_sh;
    int tid = threadIdx.x;
    int bid = blockIdx.x;
    int wid = tid >> 5, lane = tid & 31;
    if (tid == 0) s_base_sh = atomicAdd(&g_release, 0u);
    __syncthreads();
    unsigned base = s_base_sh;

    // ============ P1: LN(token) + q partials ============
    if (bid < 16) {
        float t0 = token[tid], t1 = token[tid + 256];
        float* red = SM;
        red[tid] = t0 + t1;
        __syncthreads();
#pragma unroll
        for (int o = 128; o; o >>= 1) {
            if (tid < o) red[tid] += red[tid + o];
            __syncthreads();
        }
        float mean = red[0] * (1.f / 512.f);
        __syncthreads();
        float d0 = t0 - mean, d1 = t1 - mean;
        red[tid] = d0 * d0 + d1 * d1;
        __syncthreads();
#pragma unroll
        for (int o = 128; o; o >>= 1) {
            if (tid < o) red[tid] += red[tid + o];
            __syncthreads();
        }
        float rstd = rsqrtf(red[0] * (1.f / 512.f) + 1e-5f);
        __syncthreads();
        float* shl = SM;
        float hl0 = d0 * rstd * s1[tid] + b1[tid];
        float hl1 = d1 * rstd * s1[tid + 256] + b1[tid + 256];
        shl[tid] = hl0;
        shl[tid + 256] = hl1;
        if (bid == 0) {
            g_hl[tid] = hl0;
            g_hl[tid + 256] = hl1;
        }
        __syncthreads();
        int j0 = bid * 32;
        float a0 = 0.f, a1 = 0.f;
#pragma unroll
        for (int j = 0; j < 32; j++) {
            float h = shl[j0 + j];
            a0 = fmaf(h, Wq[(size_t)(j0 + j) * 512 + tid], a0);
            a1 = fmaf(h, Wq[(size_t)(j0 + j) * 512 + tid + 256], a1);
        }
        g_qpart[bid][tid] = a0;
        g_qpart[bid][tid + 256] = a1;
    }
    gridbar(base, 1);

    // ============ P2: combine q; g[h][r] = Wk[r, head h] . q_head ============
    if (bid < 64) {
        float* sq = SM;
        float q0 = bq[tid], q1 = bq[tid + 256];
#pragma unroll
        for (int s = 0; s < 16; s++) {
            q0 += g_qpart[s][tid];
            q1 += g_qpart[s][tid + 256];
        }
        sq[tid] = q0;
        sq[tid + 256] = q1;
        __syncthreads();
        int r = bid * 8 + wid;
        const float4* wr = (const float4*)(Wk + (size_t)r * 512);
        const float4* q4 = (const float4*)sq;
        float dt[4];
#pragma unroll
        for (int t = 0; t < 4; t++) {
            float4 w = __ldg(wr + lane + 32 * t);
            float4 q = q4[lane + 32 * t];
            dt[t] = w.x * q.x + w.y * q.y + w.z * q.z + w.w * q.w;
        }
#pragma unroll
        for (int t = 0; t < 4; t++) dt[t] = wred(dt[t]);
        if (lane == 0) {
            float sr = s1[r];
#pragma unroll
            for (int t = 0; t < 4; t++) {
                g_g[t][r] = dt[t];
                g_gs[t][r] = dt[t] * sr;
            }
        }
    }
    gridbar(base, 2);

    // ============ P3: per-key stats + raw score dots (warp per row) ============
    {
        int wg = bid * 8 + wid;  // 0..1023
        int b = wg >> 5;
        int L = __ldg(&mask[b]);
        int kbase = (wg & 31) * 16;
        for (int it = 0; it < 16; it++) {
            int k = kbase + it;
            if (k >= L) break;
            const float4* xr = (const float4*)(x + ((size_t)b * 512 + k) * 512);
            float4 xv[4];
#pragma unroll
            for (int t = 0; t < 4; t++) xv[t] = __ldg(xr + lane + 32 * t);
            float ss = 0.f, sm = 0.f;
#pragma unroll
            for (int t = 0; t < 4; t++) {
                ss += xv[t].x * xv[t].x + xv[t].y * xv[t].y + xv[t].z * xv[t].z + xv[t].w * xv[t].w;
                sm += xv[t].x + xv[t].y + xv[t].z + xv[t].w;
            }
            ss = wred(ss);
            sm = wred(sm);
            float inv = 1.f / fmaxf(sqrtf(ss), 1e-12f);
            float meany = sm * inv * (1.f / 512.f);
            float vary = ss * inv * inv * (1.f / 512.f) - meany * meany;
            float rstd = rsqrtf(vary + 1e-5f);
            float alpha = inv * rstd, beta = -meany * rstd;
            float d[4];
#pragma unroll
            for (int h = 0; h < 4; h++) {
                const float4* g4 = (const float4*)g_gs[h];
                float a = 0.f;
#pragma unroll
                for (int t = 0; t < 4; t++) {
                    float4 g = g4[lane + 32 * t];
                    a += xv[t].x * g.x + xv[t].y * g.y + xv[t].z * g.z + xv[t].w * g.w;
                }
                d[h] = wred(a);
            }
            if (lane == 0) {
                g_stats[b][k] = make_float2(alpha, beta);
                *(float4*)&g_scores[b][k][0] = make_float4(d[0], d[1], d[2], d[3]);
            }
        }
    }
    gridbar(base, 3);

    // ============ P4: softmax per batch ============
    if (bid < 32) {
        int b = bid;
        int L = __ldg(&mask[b]);
        float pc[12];
#pragma unroll
        for (int j = 0; j < 12; j++) pc[j] = 0.f;
#pragma unroll
        for (int t = 0; t < 2; t++) {
            int i = tid + 256 * t;
            float s = s1[i], bb = b1[i], hl = g_hl[i];
#pragma unroll
            for (int h = 0; h < 4; h++) {
                float g = g_g[h][i];
                pc[h] = fmaf(s, g, pc[h]);
                pc[4 + h] = fmaf(bb, g, pc[4 + h]);
                pc[8 + h] = fmaf(hl, g, pc[8 + h]);
            }
        }
        float* r12 = SM;
#pragma unroll
        for (int j = 0; j < 12; j++) r12[tid * 12 + j] = pc[j];
        __syncthreads();
        for (int o = 128; o; o >>= 1) {
            if (tid < o)
#pragma unroll
                for (int j = 0; j < 12; j++) r12[tid * 12 + j] += r12[(tid + o) * 12 + j];
            __syncthreads();
        }
        float C1[4], C2[4], scls[4];
#pragma unroll
        for (int h = 0; h < 4; h++) {
            C1[h] = r12[h];
            C2[h] = r12[4 + h];
            scls[h] = r12[8 + h] * SCALE;
        }
        __syncthreads();
        float mx[4] = {scls[0], scls[1], scls[2], scls[3]};
        for (int k = tid; k < L; k += 256) {
            float4 d = *(const float4*)&g_scores[b][k][0];
            float2 ab = g_stats[b][k];
            float4 s;
            s.x = SCALE * (ab.x * d.x + ab.y * C1[0] + C2[0]);
            s.y = SCALE * (ab.x * d.y + ab.y * C1[1] + C2[1]);
            s.z = SCALE * (ab.x * d.z + ab.y * C1[2] + C2[2]);
            s.w = SCALE * (ab.x * d.w + ab.y * C1[3] + C2[3]);
            *(float4*)&g_scores[b][k][0] = s;
            mx[0] = fmaxf(mx[0], s.x);
            mx[1] = fmaxf(mx[1], s.y);
            mx[2] = fmaxf(mx[2], s.z);
            mx[3] = fmaxf(mx[3], s.w);
        }
        float* r4 = SM;
#pragma unroll
        for (int h = 0; h < 4; h++) r4[tid * 4 + h] = mx[h];
        __syncthreads();
        for (int o = 128; o; o >>= 1) {
            if (tid < o)
#pragma unroll
                for (int h = 0; h < 4; h++)
                    r4[tid * 4 + h] = fmaxf(r4[tid * 4 + h], r4[(tid + o) * 4 + h]);
            __syncthreads();
        }
        float M[4];
#pragma unroll
        for (int h = 0; h < 4; h++) M[h] = r4[h];
        __syncthreads();
        float se[4] = {0, 0, 0, 0}, ewb[4] = {0, 0, 0, 0};
        for (int k = tid; k < L; k += 256) {
            float4 s = *(const float4*)&g_scores[b][k][0];
            float2 ab = g_stats[b][k];
            float e0 = __expf(s.x - M[0]);
            float e1 = __expf(s.y - M[1]);
            float e2 = __expf(s.z - M[2]);
            float e3 = __expf(s.w - M[3]);
            *(float4*)&g_wts[b][k][0] = make_float4(e0 * ab.x, e1 * ab.x, e2 * ab.x, e3 * ab.x);
            se[0] += e0; se[1] += e1; se[2] += e2; se[3] += e3;
            ewb[0] += e0 * ab.y; ewb[1] += e1 * ab.y; ewb[2] += e2 * ab.y; ewb[3] += e3 * ab.y;
        }
        float* r8 = SM;
#pragma unroll
        for (int h = 0; h < 4; h++) {
            r8[tid * 8 + h] = se[h];
            r8[tid * 8 + 4 + h] = ewb[h];
        }
        __syncthreads();
        for (int o = 128; o; o >>= 1) {
            if (tid < o)
#pragma unroll
                for (int j = 0; j < 8; j++) r8[tid * 8 + j] += r8[(tid + o) * 8 + j];
            __syncthreads();
        }
        if (tid < 4) {
            int h = tid;
            float ec = __expf(scls[h] - M[h]);
            float S = r8[h] + ec;
            g_wmisc[b][h] = r8[4 + h];     // sum e*beta
            g_wmisc[b][4 + h] = r8[h];     // sum e
            g_wmisc[b][8 + h] = ec;        // e_cls
            g_wmisc[b][12 + h] = 1.f / S;  // invS
        }
    }
    gridbar(base, 4);

    // ============ P5: A[h][i] = sum_k (e*alpha)_k x_k[i] (8 k-splits x 32 b) ============
    {
        int half = tid >> 7, t128 = tid & 127;
        int vb = bid * 2 + half;  // 0..255
        int ks = vb & 7, b = vb >> 3;
        int L = __ldg(&mask[b]);
        int k0 = ks * 64, k1 = min(L, k0 + 64);
        float4 a0 = {0, 0, 0, 0}, a1 = a0, a2 = a0, a3 = a0;
        const float4* xb = (const float4*)(x + (size_t)b * 512 * 512);
        for (int k = k0; k < k1; k++) {
            float4 xv = __ldg(xb + (size_t)k * 128 + t128);
            float4 wa = *(const float4*)&g_wts[b][k][0];
            a0.x = fmaf(wa.x, xv.x, a0.x); a0.y = fmaf(wa.x, xv.y, a0.y);
            a0.z = fmaf(wa.x, xv.z, a0.z); a0.w = fmaf(wa.x, xv.w, a0.w);
            a1.x = fmaf(wa.y, xv.x, a1.x); a1.y = fmaf(wa.y, xv.y, a1.y);
            a1.z = fmaf(wa.y, xv.z, a1.z); a1.w = fmaf(wa.y, xv.w, a1.w);
            a2.x = fmaf(wa.z, xv.x, a2.x); a2.y = fmaf(wa.z, xv.y, a2.y);
            a2.z = fmaf(wa.z, xv.z, a2.z); a2.w = fmaf(wa.z, xv.w, a2.w);
            a3.x = fmaf(wa.w, xv.x, a3.x); a3.y = fmaf(wa.w, xv.y, a3.y);
            a3.z = fmaf(wa.w, xv.z, a3.z); a3.w = fmaf(wa.w, xv.w, a3.w);
        }
        int i = t128 * 4;
        *(float4*)&g_ppart[ks][b][0][i] = a0;
        *(float4*)&g_ppart[ks][b][1][i] = a1;
        *(float4*)&g_ppart[ks][b][2][i] = a2;
        *(float4*)&g_ppart[ks][b][3][i] = a3;
    }
    gridbar(base, 5);

    // ============ T1: ctx partials = p @ Wv ============
    if (bid < 32) {
        int half = tid >> 7, t128 = tid & 127;
        int vb = bid * 2 + half;       // 0..63
        int hh = vb & 3, iy = vb >> 2; // iy 0..15
        int i0 = iy * 32, f = hh * 128 + t128;
        float* sp = SM + half * 1024;  // [32][32]
        for (int idx = t128; idx < 1024; idx += 128) {
            int b = idx >> 5, ii = idx & 31, i = i0 + ii;
            float A = 0.f;
#pragma unroll
            for (int s = 0; s < 8; s++) A += g_ppart[s][b][hh][i];
            const float* wm = g_wmisc[b];
            sp[b * 32 + ii] =
                wm[12 + hh] * (s1[i] * (A + wm[hh]) + b1[i] * wm[4 + hh] + wm[8 + hh] * g_hl[i]);
        }
        __syncthreads();
        float acc[32];
#pragma unroll
        for (int b = 0; b < 32; b++) acc[b] = 0.f;
        for (int ii = 0; ii < 32; ii += 4) {
            int i = i0 + ii;
            float w0 = Wv[(size_t)i * 512 + f];
            float w1 = Wv[(size_t)(i + 1) * 512 + f];
            float w2 = Wv[(size_t)(i + 2) * 512 + f];
            float w3 = Wv[(size_t)(i + 3) * 512 + f];
#pragma unroll
            for (int b = 0; b < 32; b++) {
                float4 p = *(const float4*)&sp[b * 32 + ii];
                acc[b] = fmaf(p.x, w0, fmaf(p.y, w1, fmaf(p.z, w2, fmaf(p.w, w3, acc[b]))));
            }
        }
#pragma unroll
        for (int b = 0; b < 32; b++) g_ctxpart[iy][b][f] = acc[b];
    }
    gridbar(base, 6);

    // ============ T2: o partials = (ctx+bv) @ Wo ============
    if (bid < 32) {
        int half = tid >> 7, t128 = tid & 127;
        int vb = bid * 2 + half;
        int cx = vb & 3, iy = vb >> 2;
        int i0 = iy * 32, f = cx * 128 + t128;
        float* sc = SM + half * 1024;
        for (int idx = t128; idx < 1024; idx += 128) {
            int b = idx >> 5, ii = idx & 31, i = i0 + ii;
            float v = bv[i];
#pragma unroll
            for (int s = 0; s < 16; s++) v += g_ctxpart[s][b][i];
            sc[b * 32 + ii] = v;
        }
        __syncthreads();
        float acc[32];
#pragma unroll
        for (int b = 0; b < 32; b++) acc[b] = 0.f;
        for (int ii = 0; ii < 32; ii += 4) {
            int i = i0 + ii;
            float w0 = Wo[(size_t)i * 512 + f];
            float w1 = Wo[(size_t)(i + 1) * 512 + f];
            float w2 = Wo[(size_t)(i + 2) * 512 + f];
            float w3 = Wo[(size_t)(i + 3) * 512 + f];
#pragma unroll
            for (int b = 0; b < 32; b++) {
                float4 p = *(const float4*)&sc[b * 32 + ii];
                acc[b] = fmaf(p.x, w0, fmaf(p.y, w1, fmaf(p.z, w2, fmaf(p.w, w3, acc[b]))));
            }
        }
#pragma unroll
        for (int b = 0; b < 32; b++) g_wopart[iy][b][f] = acc[b];
    }
    gridbar(base, 7);

    // ============ T3: h1 = token + o + bo; LN2 stats ============
    if (bid < 32) {
        int b = bid;
        float sum = 0.f, ssq = 0.f;
#pragma unroll
        for (int t = 0; t < 2; t++) {
            int c = tid + 256 * t;
            float v = token[c] + bo[c];
#pragma unroll
            for (int s = 0; s < 16; s++) v += g_wopart[s][b][c];
            g_h1[b][c] = v;
            sum += v;
            ssq += v * v;
        }
        float* r2 = SM;
        r2[tid * 2] = sum;
        r2[tid * 2 + 1] = ssq;
        __syncthreads();
        for (int o = 128; o; o >>= 1) {
            if (tid < o) {
                r2[tid * 2] += r2[(tid + o) * 2];
                r2[tid * 2 + 1] += r2[(tid + o) * 2 + 1];
            }
            __syncthreads();
        }
        if (tid == 0) {
            float m = r2[0] * (1.f / 512.f);
            float var = r2[1] * (1.f / 512.f) - m * m;
            g_ln2[b] = make_float2(m, rsqrtf(var + 1e-5f));
        }
    }
    gridbar(base, 8);

    // ============ T4: W1 partials (h2 @ W1), all 128 blocks ============
    {
        int half = tid >> 7, t128 = tid & 127;
        int vb = bid * 2 + half;        // 0..255
        int fx = vb & 15, iy = vb >> 4; // iy 0..15
        int i0 = iy * 32, f = fx * 128 + t128;
        float* sh2 = SM + half * 1024;
        for (int idx = t128; idx < 1024; idx += 128) {
            int b = idx >> 5, ii = idx & 31, i = i0 + ii;
            float2 mr = g_ln2[b];
            sh2[b * 32 + ii] = (g_h1[b][i] - mr.x) * mr.y * s2[i] + b2l[i];
        }
        __syncthreads();
        float acc[32];
#pragma unroll
        for (int b = 0; b < 32; b++) acc[b] = 0.f;
        for (int ii = 0; ii < 32; ii += 4) {
            int i = i0 + ii;
            float w0 = W1[(size_t)i * 2048 + f];
            float w1 = W1[(size_t)(i + 1) * 2048 + f];
            float w2 = W1[(size_t)(i + 2) * 2048 + f];
            float w3 = W1[(size_t)(i + 3) * 2048 + f];
#pragma unroll
            for (int b = 0; b < 32; b++) {
                float4 p = *(const float4*)&sh2[b * 32 + ii];
                acc[b] = fmaf(p.x, w0, fmaf(p.y, w1, fmaf(p.z, w2, fmaf(p.w, w3, acc[b]))));
            }
        }
#pragma unroll
        for (int b = 0; b < 32; b++) g_w1part[iy][b][f] = acc[b];
        __syncthreads();
    }
    gridbar(base, 9);

    // ============ T5: gelu + W2 partials, all 128 blocks ============
    {
        int half = tid >> 7, t128 = tid & 127;
        int vb = bid * 2 + half;       // 0..255
        int fx = vb & 3, iy = vb >> 2; // iy 0..63
        int i0 = iy * 32, f = fx * 128 + t128;
        float* su = SM + half * 1024;
        for (int idx = t128; idx < 1024; idx += 128) {
            int b = idx >> 5, ii = idx & 31, i = i0 + ii;
            float u = b1f[i];
#pragma unroll
            for (int s = 0; s < 16; s++) u += g_w1part[s][b][i];
            su[b * 32 + ii] = geluf(u);
        }
        __syncthreads();
        float acc[32];
#pragma unroll
        for (int b = 0; b < 32; b++) acc[b] = 0.f;
        for (int ii = 0; ii < 32; ii += 4) {
            int i = i0 + ii;
            float w0 = W2[(size_t)i * 512 + f];
            float w1 = W2[(size_t)(i + 1) * 512 + f];
            float w2 = W2[(size_t)(i + 2) * 512 + f];
            float w3 = W2[(size_t)(i + 3) * 512 + f];
#pragma unroll
            for (int b = 0; b < 32; b++) {
                float4 p = *(const float4*)&su[b * 32 + ii];
                acc[b] = fmaf(p.x, w0, fmaf(p.y, w1, fmaf(p.z, w2, fmaf(p.w, w3, acc[b]))));
            }
        }
#pragma unroll
        for (int b = 0; b < 32; b++) g_w2part[iy][b][f] = acc[b];
    }
    gridbar(base, 10);

    // ============ OUT ============
    if (bid < 32) {
        int b = bid;
#pragma unroll
        for (int t = 0; t < 2; t++) {
            int c = tid + 256 * t;
            float v = g_h1[b][c] + b2o[c];
#pragma unroll
            for (int s = 0; s < 64; s++) v += g_w2part[s][b][c];
            out[b * 512 + c] = v;
        }
    }
}

extern "C" void kernel_launch(void* const* d_in, const int* in_sizes, int n_in,
                              void* d_out, int out_size) {
    const float* x     = (const float*)d_in[0];
    const int*   mask  = (const int*)d_in[1];
    const float* token = (const float*)d_in[2];
    const float* Wq    = (const float*)d_in[3];
    const float* bq    = (const float*)d_in[4];
    const float* Wk    = (const float*)d_in[5];
    // d_in[6] = bk: uniform shift across keys -> cancels in softmax; unused
    const float* Wv    = (const float*)d_in[7];
    const float* bv    = (const float*)d_in[8];
    const float* Wo    = (const float*)d_in[9];
    const float* bo    = (const float*)d_in[10];
    const float* s1    = (const float*)d_in[11];
    const float* b1    = (const float*)d_in[12];
    const float* s2    = (const float*)d_in[13];
    const float* b2l   = (const float*)d_in[14];
    const float* W1    = (const float*)d_in[15];
    const float* b1f   = (const float*)d_in[16];
    const float* W2    = (const float*)d_in[17];
    const float* b2o   = (const float*)d_in[18];
    float* out = (float*)d_out;

    fused_kernel<<<NB, NT>>>(x, mask, token, Wq, bq, Wk, Wv, bv, Wo, bo,
                             s1, b1, s2, b2l, W1, b1f, W2, b2o, out);
}

// round 5
// speedup vs baseline: 1.4861x; 1.1486x over previous
#include <cuda_runtime.h>
#include <math.h>

#define SCALE 0.08838834764831845f  // 1/sqrt(128)
#define NB 256
#define NT 256

// ---------------- grid barrier state ----------------
__device__ unsigned g_count;
__device__ unsigned g_release;
__device__ float g_dummy;

// ---------------- scratch ----------------
__device__ __align__(16) float g_hl[512];
__device__ __align__(16) float g_qpart[16][512];
__device__ __align__(16) float g_g[4][512];
__device__ __align__(16) float g_gs[4][512];
__device__ __align__(16) float2 g_stats[32][512];
__device__ __align__(16) float g_scores[32][512][4];
__device__ __align__(16) float g_wts[32][512][4];
__device__ __align__(16) float g_wmisc[32][16];
__device__ __align__(16) float g_ppart[16][32][4][512];
__device__ __align__(16) float g_ctxpart[16][32][512];
__device__ __align__(16) float g_wopart[16][32][512];
__device__ __align__(16) float g_h1[32][512];
__device__ __align__(16) float2 g_ln2[32];
__device__ __align__(16) float g_w1part[16][32][2048];
__device__ __align__(16) float g_w2part[64][32][512];

static __device__ __forceinline__ float wred(float v) {
#pragma unroll
    for (int o = 16; o; o >>= 1) v += __shfl_xor_sync(0xffffffffu, v, o);
    return v;
}

static __device__ __forceinline__ float geluf(float t) {
    float t3 = t * t * t;
    return 0.5f * t * (1.f + tanhf(0.7978845608028654f * (t + 0.044715f * t3)));
}

__device__ __forceinline__ void gridbar(unsigned base, unsigned idx) {
    __syncthreads();
    if (threadIdx.x == 0) {
        __threadfence();
        if (atomicAdd(&g_count, 1u) == NB - 1) {
            g_count = 0;
            __threadfence();
            atomicExch(&g_release, base + idx);
        } else {
            while (atomicAdd(&g_release, 0u) - base < idx) __nanosleep(32);
            __threadfence();
        }
    }
    __syncthreads();
}

__global__ void __launch_bounds__(NT, 2) fused_kernel(
    const float* __restrict__ x, const int* __restrict__ mask,
    const float* __restrict__ token,
    const float* __restrict__ Wq, const float* __restrict__ bq,
    const float* __restrict__ Wk,
    const float* __restrict__ Wv, const float* __restrict__ bv,
    const float* __restrict__ Wo, const float* __restrict__ bo,
    const float* __restrict__ s1, const float* __restrict__ b1,
    const float* __restrict__ s2, const float* __restrict__ b2l,
    const float* __restrict__ W1, const float* __restrict__ b1f,
    const float* __restrict__ W2, const float* __restrict__ b2o,
    float* __restrict__ out) {
    __shared__ float SM[3072];
    __shared__ unsigned s_base_sh;
    int tid = threadIdx.x;
    int bid = blockIdx.x;
    int wid = tid >> 5, lane = tid & 31;
    if (tid == 0) s_base_sh = atomicAdd(&g_release, 0u);
    __syncthreads();
    unsigned base = s_base_sh;

    // ============ P1: LN(token) + q partials; other blocks prefetch x -> L2 ============
    if (bid < 16) {
        float t0 = token[tid], t1 = token[tid + 256];
        float* red = SM;
        red[tid] = t0 + t1;
        __syncthreads();
#pragma unroll
        for (int o = 128; o; o >>= 1) {
            if (tid < o) red[tid] += red[tid + o];
            __syncthreads();
        }
        float mean = red[0] * (1.f / 512.f);
        __syncthreads();
        float d0 = t0 - mean, d1 = t1 - mean;
        red[tid] = d0 * d0 + d1 * d1;
        __syncthreads();
#pragma unroll
        for (int o = 128; o; o >>= 1) {
            if (tid < o) red[tid] += red[tid + o];
            __syncthreads();
        }
        float rstd = rsqrtf(red[0] * (1.f / 512.f) + 1e-5f);
        __syncthreads();
        float* shl = SM;
        float hl0 = d0 * rstd * s1[tid] + b1[tid];
        float hl1 = d1 * rstd * s1[tid + 256] + b1[tid + 256];
        shl[tid] = hl0;
        shl[tid + 256] = hl1;
        if (bid == 0) {
            g_hl[tid] = hl0;
            g_hl[tid + 256] = hl1;
        }
        __syncthreads();
        int j0 = bid * 32;
        float a0 = 0.f, a1 = 0.f;
#pragma unroll
        for (int j = 0; j < 32; j++) {
            float h = shl[j0 + j];
            a0 = fmaf(h, Wq[(size_t)(j0 + j) * 512 + tid], a0);
            a1 = fmaf(h, Wq[(size_t)(j0 + j) * 512 + tid + 256], a1);
        }
        g_qpart[bid][tid] = a0;
        g_qpart[bid][tid + 256] = a1;
    } else {
        // prefetch valid rows of x into L2 (read + keep live)
        int pw = (bid - 16) * 8 + wid;  // 0..1919
        float acc = 0.f;
        for (int r = pw; r < 16384; r += 1920) {
            int b = r >> 9, k = r & 511;
            if (k >= __ldg(&mask[b])) continue;
            const float4* xr = (const float4*)(x + (size_t)r * 512);
#pragma unroll
            for (int t = 0; t < 4; t++) {
                float4 v = __ldg(xr + lane + 32 * t);
                acc += v.x;
            }
        }
        if (acc == 1.2345e30f) g_dummy = acc;  // never true; keeps loads live
    }
    gridbar(base, 1);

    // ============ P2: combine q; g[h][r] = Wk[r, head h] . q_head ============
    if (bid < 64) {
        float* sq = SM;
        float q0 = bq[tid], q1 = bq[tid + 256];
#pragma unroll
        for (int s = 0; s < 16; s++) {
            q0 += g_qpart[s][tid];
            q1 += g_qpart[s][tid + 256];
        }
        sq[tid] = q0;
        sq[tid + 256] = q1;
        __syncthreads();
        int r = bid * 8 + wid;
        const float4* wr = (const float4*)(Wk + (size_t)r * 512);
        const float4* q4 = (const float4*)sq;
        float dt[4];
#pragma unroll
        for (int t = 0; t < 4; t++) {
            float4 w = __ldg(wr + lane + 32 * t);
            float4 q = q4[lane + 32 * t];
            dt[t] = w.x * q.x + w.y * q.y + w.z * q.z + w.w * q.w;
        }
#pragma unroll
        for (int t = 0; t < 4; t++) dt[t] = wred(dt[t]);
        if (lane == 0) {
            float sr = s1[r];
#pragma unroll
            for (int t = 0; t < 4; t++) {
                g_g[t][r] = dt[t];
                g_gs[t][r] = dt[t] * sr;
            }
        }
    }
    gridbar(base, 2);

    // ============ P3: per-key stats + raw score dots (2-row batches) ============
    {
        for (int i = tid; i < 2048; i += NT) SM[i] = ((const float*)g_gs)[i];
        __syncthreads();
        const float4* sgs4 = (const float4*)SM;
        int wg = bid * 8 + wid;  // 0..2047
        int b = wg >> 6;
        int L = __ldg(&mask[b]);
        int kbase = (wg & 63) * 8;
#pragma unroll 1
        for (int it = 0; it < 4; it++) {
            int k0 = kbase + it * 2;
            if (k0 >= L) break;
            bool two = (k0 + 1 < L);
            const float4* xr0 = (const float4*)(x + ((size_t)b * 512 + k0) * 512);
            float4 xa[4], xc[4];
#pragma unroll
            for (int t = 0; t < 4; t++) xa[t] = __ldg(xr0 + lane + 32 * t);
            if (two) {
#pragma unroll
                for (int t = 0; t < 4; t++) xc[t] = __ldg(xr0 + 128 + lane + 32 * t);
            } else {
#pragma unroll
                for (int t = 0; t < 4; t++) xc[t] = make_float4(0.f, 0.f, 0.f, 0.f);
            }
            float ssA = 0.f, smA = 0.f, ssB = 0.f, smB = 0.f;
#pragma unroll
            for (int t = 0; t < 4; t++) {
                ssA += xa[t].x * xa[t].x + xa[t].y * xa[t].y + xa[t].z * xa[t].z + xa[t].w * xa[t].w;
                smA += xa[t].x + xa[t].y + xa[t].z + xa[t].w;
                ssB += xc[t].x * xc[t].x + xc[t].y * xc[t].y + xc[t].z * xc[t].z + xc[t].w * xc[t].w;
                smB += xc[t].x + xc[t].y + xc[t].z + xc[t].w;
            }
            ssA = wred(ssA);
            ssB = wred(ssB);
            smA = wred(smA);
            smB = wred(smB);
            float invA = 1.f / fmaxf(sqrtf(ssA), 1e-12f);
            float invB = 1.f / fmaxf(sqrtf(ssB), 1e-12f);
            float mA = smA * invA * (1.f / 512.f), mB = smB * invB * (1.f / 512.f);
            float vA = ssA * invA * invA * (1.f / 512.f) - mA * mA;
            float vB = ssB * invB * invB * (1.f / 512.f) - mB * mB;
            float rA = rsqrtf(vA + 1e-5f), rB = rsqrtf(vB + 1e-5f);
            float alA = invA * rA, beA = -mA * rA;
            float alB = invB * rB, beB = -mB * rB;
            float dA[4], dB[4];
#pragma unroll
            for (int h = 0; h < 4; h++) {
                float aA = 0.f, aB = 0.f;
#pragma unroll
                for (int t = 0; t < 4; t++) {
                    float4 g = sgs4[h * 128 + lane + 32 * t];
                    aA += xa[t].x * g.x + xa[t].y * g.y + xa[t].z * g.z + xa[t].w * g.w;
                    aB += xc[t].x * g.x + xc[t].y * g.y + xc[t].z * g.z + xc[t].w * g.w;
                }
                dA[h] = wred(aA);
                dB[h] = wred(aB);
            }
            if (lane == 0) {
                g_stats[b][k0] = make_float2(alA, beA);
                *(float4*)&g_scores[b][k0][0] = make_float4(dA[0], dA[1], dA[2], dA[3]);
                if (two) {
                    g_stats[b][k0 + 1] = make_float2(alB, beB);
                    *(float4*)&g_scores[b][k0 + 1][0] = make_float4(dB[0], dB[1], dB[2], dB[3]);
                }
            }
        }
    }
    gridbar(base, 3);

    // ============ P4: softmax per batch ============
    if (bid < 32) {
        int b = bid;
        int L = __ldg(&mask[b]);
        float pc[12];
#pragma unroll
        for (int j = 0; j < 12; j++) pc[j] = 0.f;
#pragma unroll
        for (int t = 0; t < 2; t++) {
            int i = tid + 256 * t;
            float s = s1[i], bb = b1[i], hl = g_hl[i];
#pragma unroll
            for (int h = 0; h < 4; h++) {
                float g = g_g[h][i];
                pc[h] = fmaf(s, g, pc[h]);
                pc[4 + h] = fmaf(bb, g, pc[4 + h]);
                pc[8 + h] = fmaf(hl, g, pc[8 + h]);
            }
        }
        float* r12 = SM;
#pragma unroll
        for (int j = 0; j < 12; j++) r12[tid * 12 + j] = pc[j];
        __syncthreads();
        for (int o = 128; o; o >>= 1) {
            if (tid < o)
#pragma unroll
                for (int j = 0; j < 12; j++) r12[tid * 12 + j] += r12[(tid + o) * 12 + j];
            __syncthreads();
        }
        float C1[4], C2[4], scls[4];
#pragma unroll
        for (int h = 0; h < 4; h++) {
            C1[h] = r12[h];
            C2[h] = r12[4 + h];
            scls[h] = r12[8 + h] * SCALE;
        }
        __syncthreads();
        float mx[4] = {scls[0], scls[1], scls[2], scls[3]};
        for (int k = tid; k < L; k += 256) {
            float4 d = *(const float4*)&g_scores[b][k][0];
            float2 ab = g_stats[b][k];
            float4 s;
            s.x = SCALE * (ab.x * d.x + ab.y * C1[0] + C2[0]);
            s.y = SCALE * (ab.x * d.y + ab.y * C1[1] + C2[1]);
            s.z = SCALE * (ab.x * d.z + ab.y * C1[2] + C2[2]);
            s.w = SCALE * (ab.x * d.w + ab.y * C1[3] + C2[3]);
            *(float4*)&g_scores[b][k][0] = s;
            mx[0] = fmaxf(mx[0], s.x);
            mx[1] = fmaxf(mx[1], s.y);
            mx[2] = fmaxf(mx[2], s.z);
            mx[3] = fmaxf(mx[3], s.w);
        }
        float* r4 = SM;
#pragma unroll
        for (int h = 0; h < 4; h++) r4[tid * 4 + h] = mx[h];
        __syncthreads();
        for (int o = 128; o; o >>= 1) {
            if (tid < o)
#pragma unroll
                for (int h = 0; h < 4; h++)
                    r4[tid * 4 + h] = fmaxf(r4[tid * 4 + h], r4[(tid + o) * 4 + h]);
            __syncthreads();
        }
        float M[4];
#pragma unroll
        for (int h = 0; h < 4; h++) M[h] = r4[h];
        __syncthreads();
        float se[4] = {0, 0, 0, 0}, ewb[4] = {0, 0, 0, 0};
        for (int k = tid; k < L; k += 256) {
            float4 s = *(const float4*)&g_scores[b][k][0];
            float2 ab = g_stats[b][k];
            float e0 = __expf(s.x - M[0]);
            float e1 = __expf(s.y - M[1]);
            float e2 = __expf(s.z - M[2]);
            float e3 = __expf(s.w - M[3]);
            *(float4*)&g_wts[b][k][0] = make_float4(e0 * ab.x, e1 * ab.x, e2 * ab.x, e3 * ab.x);
            se[0] += e0; se[1] += e1; se[2] += e2; se[3] += e3;
            ewb[0] += e0 * ab.y; ewb[1] += e1 * ab.y; ewb[2] += e2 * ab.y; ewb[3] += e3 * ab.y;
        }
        float* r8 = SM;
#pragma unroll
        for (int h = 0; h < 4; h++) {
            r8[tid * 8 + h] = se[h];
            r8[tid * 8 + 4 + h] = ewb[h];
        }
        __syncthreads();
        for (int o = 128; o; o >>= 1) {
            if (tid < o)
#pragma unroll
                for (int j = 0; j < 8; j++) r8[tid * 8 + j] += r8[(tid + o) * 8 + j];
            __syncthreads();
        }
        if (tid < 4) {
            int h = tid;
            float ec = __expf(scls[h] - M[h]);
            float S = r8[h] + ec;
            g_wmisc[b][h] = r8[4 + h];     // sum e*beta
            g_wmisc[b][4 + h] = r8[h];     // sum e
            g_wmisc[b][8 + h] = ec;        // e_cls
            g_wmisc[b][12 + h] = 1.f / S;  // invS
        }
    }
    gridbar(base, 4);

    // ============ P5: A[h][i] = sum_k (e*alpha)_k x_k[i] (16 k-splits x 32 b) ============
    {
        int half = tid >> 7, t128 = tid & 127;
        int vb = bid * 2 + half;  // 0..511
        int ks = vb & 15, b = vb >> 4;
        int L = __ldg(&mask[b]);
        int k0 = ks * 32, k1 = min(L, k0 + 32);
        float4 a0 = {0, 0, 0, 0}, a1 = a0, a2 = a0, a3 = a0;
        const float4* xb4 = (const float4*)(x + (size_t)b * 512 * 512);
#pragma unroll 4
        for (int k = k0; k < k1; k++) {
            float4 xv = __ldg(xb4 + (size_t)k * 128 + t128);
            float4 wa = *(const float4*)&g_wts[b][k][0];
            a0.x = fmaf(wa.x, xv.x, a0.x); a0.y = fmaf(wa.x, xv.y, a0.y);
            a0.z = fmaf(wa.x, xv.z, a0.z); a0.w = fmaf(wa.x, xv.w, a0.w);
            a1.x = fmaf(wa.y, xv.x, a1.x); a1.y = fmaf(wa.y, xv.y, a1.y);
            a1.z = fmaf(wa.y, xv.z, a1.z); a1.w = fmaf(wa.y, xv.w, a1.w);
            a2.x = fmaf(wa.z, xv.x, a2.x); a2.y = fmaf(wa.z, xv.y, a2.y);
            a2.z = fmaf(wa.z, xv.z, a2.z); a2.w = fmaf(wa.z, xv.w, a2.w);
            a3.x = fmaf(wa.w, xv.x, a3.x); a3.y = fmaf(wa.w, xv.y, a3.y);
            a3.z = fmaf(wa.w, xv.z, a3.z); a3.w = fmaf(wa.w, xv.w, a3.w);
        }
        int i = t128 * 4;
        *(float4*)&g_ppart[ks][b][0][i] = a0;
        *(float4*)&g_ppart[ks][b][1][i] = a1;
        *(float4*)&g_ppart[ks][b][2][i] = a2;
        *(float4*)&g_ppart[ks][b][3][i] = a3;
    }
    gridbar(base, 5);

    // ============ T1: ctx partials = p @ Wv ============
    if (bid < 32) {
        int half = tid >> 7, t128 = tid & 127;
        int vb = bid * 2 + half;        // 0..63
        int hh = vb & 3, iy = vb >> 2;  // iy 0..15
        int i0 = iy * 32, f = hh * 128 + t128;
        float* sp = SM + half * 1024;
        for (int idx = t128; idx < 1024; idx += 128) {
            int b = idx >> 5, ii = idx & 31, i = i0 + ii;
            float A = 0.f;
#pragma unroll
            for (int s = 0; s < 16; s++) A += g_ppart[s][b][hh][i];
            const float* wm = g_wmisc[b];
            sp[b * 32 + ii] =
                wm[12 + hh] * (s1[i] * (A + wm[hh]) + b1[i] * wm[4 + hh] + wm[8 + hh] * g_hl[i]);
        }
        __syncthreads();
        float acc[32];
#pragma unroll
        for (int b = 0; b < 32; b++) acc[b] = 0.f;
#pragma unroll 2
        for (int ii = 0; ii < 32; ii += 4) {
            int i = i0 + ii;
            float w0 = Wv[(size_t)i * 512 + f];
            float w1 = Wv[(size_t)(i + 1) * 512 + f];
            float w2 = Wv[(size_t)(i + 2) * 512 + f];
            float w3 = Wv[(size_t)(i + 3) * 512 + f];
#pragma unroll
            for (int b = 0; b < 32; b++) {
                float4 p = *(const float4*)&sp[b * 32 + ii];
                acc[b] = fmaf(p.x, w0, fmaf(p.y, w1, fmaf(p.z, w2, fmaf(p.w, w3, acc[b]))));
            }
        }
#pragma unroll
        for (int b = 0; b < 32; b++) g_ctxpart[iy][b][f] = acc[b];
    }
    gridbar(base, 6);

    // ============ T2: o partials = (ctx+bv) @ Wo ============
    if (bid < 32) {
        int half = tid >> 7, t128 = tid & 127;
        int vb = bid * 2 + half;
        int cx = vb & 3, iy = vb >> 2;
        int i0 = iy * 32, f = cx * 128 + t128;
        float* sc = SM + half * 1024;
        for (int idx = t128; idx < 1024; idx += 128) {
            int b = idx >> 5, ii = idx & 31, i = i0 + ii;
            float v = bv[i];
#pragma unroll
            for (int s = 0; s < 16; s++) v += g_ctxpart[s][b][i];
            sc[b * 32 + ii] = v;
        }
        __syncthreads();
        float acc[32];
#pragma unroll
        for (int b = 0; b < 32; b++) acc[b] = 0.f;
#pragma unroll 2
        for (int ii = 0; ii < 32; ii += 4) {
            int i = i0 + ii;
            float w0 = Wo[(size_t)i * 512 + f];
            float w1 = Wo[(size_t)(i + 1) * 512 + f];
            float w2 = Wo[(size_t)(i + 2) * 512 + f];
            float w3 = Wo[(size_t)(i + 3) * 512 + f];
#pragma unroll
            for (int b = 0; b < 32; b++) {
                float4 p = *(const float4*)&sc[b * 32 + ii];
                acc[b] = fmaf(p.x, w0, fmaf(p.y, w1, fmaf(p.z, w2, fmaf(p.w, w3, acc[b]))));
            }
        }
#pragma unroll
        for (int b = 0; b < 32; b++) g_wopart[iy][b][f] = acc[b];
    }
    gridbar(base, 7);

    // ============ T3: h1 = token + o + bo; LN2 stats ============
    if (bid < 32) {
        int b = bid;
        float sum = 0.f, ssq = 0.f;
#pragma unroll
        for (int t = 0; t < 2; t++) {
            int c = tid + 256 * t;
            float v = token[c] + bo[c];
#pragma unroll
            for (int s = 0; s < 16; s++) v += g_wopart[s][b][c];
            g_h1[b][c] = v;
            sum += v;
            ssq += v * v;
        }
        float* r2 = SM;
        r2[tid * 2] = sum;
        r2[tid * 2 + 1] = ssq;
        __syncthreads();
        for (int o = 128; o; o >>= 1) {
            if (tid < o) {
                r2[tid * 2] += r2[(tid + o) * 2];
                r2[tid * 2 + 1] += r2[(tid + o) * 2 + 1];
            }
            __syncthreads();
        }
        if (tid == 0) {
            float m = r2[0] * (1.f / 512.f);
            float var = r2[1] * (1.f / 512.f) - m * m;
            g_ln2[b] = make_float2(m, rsqrtf(var + 1e-5f));
        }
    }
    gridbar(base, 8);

    // ============ T4: W1 partials (h2 @ W1) ============
    if (bid < 128) {
        int half = tid >> 7, t128 = tid & 127;
        int vb = bid * 2 + half;         // 0..255
        int fx = vb & 15, iy = vb >> 4;  // iy 0..15
        int i0 = iy * 32, f = fx * 128 + t128;
        float* sh2 = SM + half * 1024;
        for (int idx = t128; idx < 1024; idx += 128) {
            int b = idx >> 5, ii = idx & 31, i = i0 + ii;
            float2 mr = g_ln2[b];
            sh2[b * 32 + ii] = (g_h1[b][i] - mr.x) * mr.y * s2[i] + b2l[i];
        }
        __syncthreads();
        float acc[32];
#pragma unroll
        for (int b = 0; b < 32; b++) acc[b] = 0.f;
#pragma unroll 2
        for (int ii = 0; ii < 32; ii += 4) {
            int i = i0 + ii;
            float w0 = W1[(size_t)i * 2048 + f];
            float w1 = W1[(size_t)(i + 1) * 2048 + f];
            float w2 = W1[(size_t)(i + 2) * 2048 + f];
            float w3 = W1[(size_t)(i + 3) * 2048 + f];
#pragma unroll
            for (int b = 0; b < 32; b++) {
                float4 p = *(const float4*)&sh2[b * 32 + ii];
                acc[b] = fmaf(p.x, w0, fmaf(p.y, w1, fmaf(p.z, w2, fmaf(p.w, w3, acc[b]))));
            }
        }
#pragma unroll
        for (int b = 0; b < 32; b++) g_w1part[iy][b][f] = acc[b];
    }
    gridbar(base, 9);

    // ============ T5: gelu + W2 partials ============
    if (bid < 128) {
        int half = tid >> 7, t128 = tid & 127;
        int vb = bid * 2 + half;        // 0..255
        int fx = vb & 3, iy = vb >> 2;  // iy 0..63
        int i0 = iy * 32, f = fx * 128 + t128;
        float* su = SM + half * 1024;
        for (int idx = t128; idx < 1024; idx += 128) {
            int b = idx >> 5, ii = idx & 31, i = i0 + ii;
            float u = b1f[i];
#pragma unroll
            for (int s = 0; s < 16; s++) u += g_w1part[s][b][i];
            su[b * 32 + ii] = geluf(u);
        }
        __syncthreads();
        float acc[32];
#pragma unroll
        for (int b = 0; b < 32; b++) acc[b] = 0.f;
#pragma unroll 2
        for (int ii = 0; ii < 32; ii += 4) {
            int i = i0 + ii;
            float w0 = W2[(size_t)i * 512 + f];
            float w1 = W2[(size_t)(i + 1) * 512 + f];
            float w2 = W2[(size_t)(i + 2) * 512 + f];
            float w3 = W2[(size_t)(i + 3) * 512 + f];
#pragma unroll
            for (int b = 0; b < 32; b++) {
                float4 p = *(const float4*)&su[b * 32 + ii];
                acc[b] = fmaf(p.x, w0, fmaf(p.y, w1, fmaf(p.z, w2, fmaf(p.w, w3, acc[b]))));
            }
        }
#pragma unroll
        for (int b = 0; b < 32; b++) g_w2part[iy][b][f] = acc[b];
    }
    gridbar(base, 10);

    // ============ OUT ============
    if (bid < 32) {
        int b = bid;
        int c0 = tid * 2;
        float2 acc;
        acc.x = g_h1[b][c0] + b2o[c0];
        acc.y = g_h1[b][c0 + 1] + b2o[c0 + 1];
#pragma unroll 16
        for (int s = 0; s < 64; s++) {
            float2 w = *(const float2*)&g_w2part[s][b][c0];
            acc.x += w.x;
            acc.y += w.y;
        }
        *(float2*)&out[b * 512 + c0] = acc;
    }
}

extern "C" void kernel_launch(void* const* d_in, const int* in_sizes, int n_in,
                              void* d_out, int out_size) {
    const float* x     = (const float*)d_in[0];
    const int*   mask  = (const int*)d_in[1];
    const float* token = (const float*)d_in[2];
    const float* Wq    = (const float*)d_in[3];
    const float* bq    = (const float*)d_in[4];
    const float* Wk    = (const float*)d_in[5];
    // d_in[6] = bk: uniform shift across keys -> cancels in softmax; unused
    const float* Wv    = (const float*)d_in[7];
    const float* bv    = (const float*)d_in[8];
    const float* Wo    = (const float*)d_in[9];
    const float* bo    = (const float*)d_in[10];
    const float* s1    = (const float*)d_in[11];
    const float* b1    = (const float*)d_in[12];
    const float* s2    = (const float*)d_in[13];
    const float* b2l   = (const float*)d_in[14];
    const float* W1    = (const float*)d_in[15];
    const float* b1f   = (const float*)d_in[16];
    const float* W2    = (const float*)d_in[17];
    const float* b2o   = (const float*)d_in[18];
    float* out = (float*)d_out;

    fused_kernel<<<NB, NT>>>(x, mask, token, Wq, bq, Wk, Wv, bv, Wo, bo,
                             s1, b1, s2, b2l, W1, b1f, W2, b2o, out);
}

// round 6
// speedup vs baseline: 1.5267x; 1.0273x over previous
#include <cuda_runtime.h>
#include <math.h>

#define SCALE 0.08838834764831845f  // 1/sqrt(128)
#define NB 256
#define NT 256

// ---------------- grid barrier state ----------------
__device__ unsigned g_count;
__device__ volatile unsigned g_release;
__device__ float g_dummy;

// ---------------- scratch ----------------
__device__ __align__(16) float g_hl[512];
__device__ __align__(16) float g_qpart[16][512];
__device__ __align__(16) float g_g[4][512];
__device__ __align__(16) float g_gs[4][512];
__device__ __align__(16) float2 g_stats[32][512];
__device__ __align__(16) float g_scores[32][512][4];
__device__ __align__(16) float g_wts[32][512][4];
__device__ __align__(16) float g_wmisc[32][16];
__device__ __align__(16) float g_ppart[16][32][4][512];
__device__ __align__(16) float g_ctxpart[32][32][512];
__device__ __align__(16) float g_wopart[32][32][512];
__device__ __align__(16) float g_h1[32][512];
__device__ __align__(16) float2 g_ln2[32];
__device__ __align__(16) float g_w1part[32][32][2048];
__device__ __align__(16) float g_w2part[128][32][512];

static __device__ __forceinline__ float wred(float v) {
#pragma unroll
    for (int o = 16; o; o >>= 1) v += __shfl_xor_sync(0xffffffffu, v, o);
    return v;
}

static __device__ __forceinline__ float geluf(float t) {
    float t3 = t * t * t;
    return 0.5f * t * (1.f + tanhf(0.7978845608028654f * (t + 0.044715f * t3)));
}

// Arrive via one atomic per block; spin on a PLAIN volatile load (no L2 atomic
// ALU serialization). Leader resets count, fences, then bumps release.
__device__ __forceinline__ void gridbar(unsigned base, unsigned idx) {
    __syncthreads();
    if (threadIdx.x == 0) {
        __threadfence();
        if (atomicAdd(&g_count, 1u) == NB - 1) {
            g_count = 0;
            __threadfence();
            g_release = base + idx;
        } else {
            while ((unsigned)(g_release - base) < idx) __nanosleep(32);
            __threadfence();
        }
    }
    __syncthreads();
}

__global__ void __launch_bounds__(NT, 2) fused_kernel(
    const float* __restrict__ x, const int* __restrict__ mask,
    const float* __restrict__ token,
    const float* __restrict__ Wq, const float* __restrict__ bq,
    const float* __restrict__ Wk,
    const float* __restrict__ Wv, const float* __restrict__ bv,
    const float* __restrict__ Wo, const float* __restrict__ bo,
    const float* __restrict__ s1, const float* __restrict__ b1,
    const float* __restrict__ s2, const float* __restrict__ b2l,
    const float* __restrict__ W1, const float* __restrict__ b1f,
    const float* __restrict__ W2, const float* __restrict__ b2o,
    float* __restrict__ out) {
    __shared__ float SM[3072];
    __shared__ unsigned s_base_sh;
    int tid = threadIdx.x;
    int bid = blockIdx.x;
    int wid = tid >> 5, lane = tid & 31;
    if (tid == 0) s_base_sh = g_release;
    __syncthreads();
    unsigned base = s_base_sh;

    // ============ P1: LN(token) + q partials; others prefetch x + weights -> L2 ============
    if (bid < 16) {
        float t0 = token[tid], t1 = token[tid + 256];
        float* red = SM;
        red[tid] = t0 + t1;
        __syncthreads();
#pragma unroll
        for (int o = 128; o; o >>= 1) {
            if (tid < o) red[tid] += red[tid + o];
            __syncthreads();
        }
        float mean = red[0] * (1.f / 512.f);
        __syncthreads();
        float d0 = t0 - mean, d1 = t1 - mean;
        red[tid] = d0 * d0 + d1 * d1;
        __syncthreads();
#pragma unroll
        for (int o = 128; o; o >>= 1) {
            if (tid < o) red[tid] += red[tid + o];
            __syncthreads();
        }
        float rstd = rsqrtf(red[0] * (1.f / 512.f) + 1e-5f);
        __syncthreads();
        float* shl = SM;
        float hl0 = d0 * rstd * s1[tid] + b1[tid];
        float hl1 = d1 * rstd * s1[tid + 256] + b1[tid + 256];
        shl[tid] = hl0;
        shl[tid + 256] = hl1;
        if (bid == 0) {
            g_hl[tid] = hl0;
            g_hl[tid + 256] = hl1;
        }
        __syncthreads();
        int j0 = bid * 32;
        float a0 = 0.f, a1 = 0.f;
#pragma unroll
        for (int j = 0; j < 32; j++) {
            float h = shl[j0 + j];
            a0 = fmaf(h, Wq[(size_t)(j0 + j) * 512 + tid], a0);
            a1 = fmaf(h, Wq[(size_t)(j0 + j) * 512 + tid + 256], a1);
        }
        g_qpart[bid][tid] = a0;
        g_qpart[bid][tid + 256] = a1;
    } else if (bid < 224) {
        // prefetch valid rows of x into L2
        int pw = (bid - 16) * 8 + wid;  // 0..1663
        float acc = 0.f;
        for (int r = pw; r < 16384; r += 1664) {
            int b = r >> 9, k = r & 511;
            if (k >= __ldg(&mask[b])) continue;
            const float4* xr = (const float4*)(x + (size_t)r * 512);
#pragma unroll
            for (int t = 0; t < 4; t++) {
                float4 v = __ldg(xr + lane + 32 * t);
                acc += v.x;
            }
        }
        if (acc == 1.2345e30f) g_dummy = acc;
    } else {
        // prefetch Wk, Wv, Wo, W1, W2 (11.25 MB) into L2
        int pw = (bid - 224) * 256 + tid;  // 0..8191
        float acc = 0.f;
        const float4* a0 = (const float4*)Wk;
        const float4* a1 = (const float4*)Wv;
        const float4* a2 = (const float4*)Wo;
        const float4* a3 = (const float4*)W1;
        const float4* a4 = (const float4*)W2;
#pragma unroll 4
        for (int i = pw; i < 65536; i += 8192)
            acc += __ldg(a0 + i).x + __ldg(a1 + i).x + __ldg(a2 + i).x;
#pragma unroll 4
        for (int i = pw; i < 262144; i += 8192)
            acc += __ldg(a3 + i).x + __ldg(a4 + i).x;
        if (acc == 1.2345e30f) g_dummy = acc;
    }
    gridbar(base, 1);

    // ============ P2: combine q; g[h][r] = Wk[r, head h] . q_head ============
    if (bid < 64) {
        float* sq = SM;
        float q0 = bq[tid], q1 = bq[tid + 256];
#pragma unroll
        for (int s = 0; s < 16; s++) {
            q0 += g_qpart[s][tid];
            q1 += g_qpart[s][tid + 256];
        }
        sq[tid] = q0;
        sq[tid + 256] = q1;
        __syncthreads();
        int r = bid * 8 + wid;
        const float4* wr = (const float4*)(Wk + (size_t)r * 512);
        const float4* q4 = (const float4*)sq;
        float dt[4];
#pragma unroll
        for (int t = 0; t < 4; t++) {
            float4 w = __ldg(wr + lane + 32 * t);
            float4 q = q4[lane + 32 * t];
            dt[t] = w.x * q.x + w.y * q.y + w.z * q.z + w.w * q.w;
        }
#pragma unroll
        for (int t = 0; t < 4; t++) dt[t] = wred(dt[t]);
        if (lane == 0) {
            float sr = s1[r];
#pragma unroll
            for (int t = 0; t < 4; t++) {
                g_g[t][r] = dt[t];
                g_gs[t][r] = dt[t] * sr;
            }
        }
    }
    gridbar(base, 2);

    // ============ P3: per-key stats + raw score dots (2-row batches) ============
    {
        for (int i = tid; i < 2048; i += NT) SM[i] = ((const float*)g_gs)[i];
        __syncthreads();
        const float4* sgs4 = (const float4*)SM;
        int wg = bid * 8 + wid;  // 0..2047
        int b = wg >> 6;
        int L = __ldg(&mask[b]);
        int kbase = (wg & 63) * 8;
#pragma unroll 1
        for (int it = 0; it < 4; it++) {
            int k0 = kbase + it * 2;
            if (k0 >= L) break;
            bool two = (k0 + 1 < L);
            const float4* xr0 = (const float4*)(x + ((size_t)b * 512 + k0) * 512);
            float4 xa[4], xc[4];
#pragma unroll
            for (int t = 0; t < 4; t++) xa[t] = __ldg(xr0 + lane + 32 * t);
            if (two) {
#pragma unroll
                for (int t = 0; t < 4; t++) xc[t] = __ldg(xr0 + 128 + lane + 32 * t);
            } else {
#pragma unroll
                for (int t = 0; t < 4; t++) xc[t] = make_float4(0.f, 0.f, 0.f, 0.f);
            }
            float ssA = 0.f, smA = 0.f, ssB = 0.f, smB = 0.f;
#pragma unroll
            for (int t = 0; t < 4; t++) {
                ssA += xa[t].x * xa[t].x + xa[t].y * xa[t].y + xa[t].z * xa[t].z + xa[t].w * xa[t].w;
                smA += xa[t].x + xa[t].y + xa[t].z + xa[t].w;
                ssB += xc[t].x * xc[t].x + xc[t].y * xc[t].y + xc[t].z * xc[t].z + xc[t].w * xc[t].w;
                smB += xc[t].x + xc[t].y + xc[t].z + xc[t].w;
            }
            ssA = wred(ssA);
            ssB = wred(ssB);
            smA = wred(smA);
            smB = wred(smB);
            float invA = 1.f / fmaxf(sqrtf(ssA), 1e-12f);
            float invB = 1.f / fmaxf(sqrtf(ssB), 1e-12f);
            float mA = smA * invA * (1.f / 512.f), mB = smB * invB * (1.f / 512.f);
            float vA = ssA * invA * invA * (1.f / 512.f) - mA * mA;
            float vB = ssB * invB * invB * (1.f / 512.f) - mB * mB;
            float rA = rsqrtf(vA + 1e-5f), rB = rsqrtf(vB + 1e-5f);
            float alA = invA * rA, beA = -mA * rA;
            float alB = invB * rB, beB = -mB * rB;
            float dA[4], dB[4];
#pragma unroll
            for (int h = 0; h < 4; h++) {
                float aA = 0.f, aB = 0.f;
#pragma unroll
                for (int t = 0; t < 4; t++) {
                    float4 g = sgs4[h * 128 + lane + 32 * t];
                    aA += xa[t].x * g.x + xa[t].y * g.y + xa[t].z * g.z + xa[t].w * g.w;
                    aB += xc[t].x * g.x + xc[t].y * g.y + xc[t].z * g.z + xc[t].w * g.w;
                }
                dA[h] = wred(aA);
                dB[h] = wred(aB);
            }
            if (lane == 0) {
                g_stats[b][k0] = make_float2(alA, beA);
                *(float4*)&g_scores[b][k0][0] = make_float4(dA[0], dA[1], dA[2], dA[3]);
                if (two) {
                    g_stats[b][k0 + 1] = make_float2(alB, beB);
                    *(float4*)&g_scores[b][k0 + 1][0] = make_float4(dB[0], dB[1], dB[2], dB[3]);
                }
            }
        }
    }
    gridbar(base, 3);

    // ============ P4: softmax per batch (2 passes) ============
    if (bid < 32) {
        int b = bid;
        int L = __ldg(&mask[b]);
        float pc[12];
#pragma unroll
        for (int j = 0; j < 12; j++) pc[j] = 0.f;
#pragma unroll
        for (int t = 0; t < 2; t++) {
            int i = tid + 256 * t;
            float s = s1[i], bb = b1[i], hl = g_hl[i];
#pragma unroll
            for (int h = 0; h < 4; h++) {
                float g = g_g[h][i];
                pc[h] = fmaf(s, g, pc[h]);
                pc[4 + h] = fmaf(bb, g, pc[4 + h]);
                pc[8 + h] = fmaf(hl, g, pc[8 + h]);
            }
        }
        float* r12 = SM;
#pragma unroll
        for (int j = 0; j < 12; j++) r12[tid * 12 + j] = pc[j];
        __syncthreads();
        for (int o = 128; o; o >>= 1) {
            if (tid < o)
#pragma unroll
                for (int j = 0; j < 12; j++) r12[tid * 12 + j] += r12[(tid + o) * 12 + j];
            __syncthreads();
        }
        float C1[4], C2[4], scls[4];
#pragma unroll
        for (int h = 0; h < 4; h++) {
            C1[h] = r12[h];
            C2[h] = r12[4 + h];
            scls[h] = r12[8 + h] * SCALE;
        }
        __syncthreads();
        // pass A: compose + running max
        float mx[4] = {scls[0], scls[1], scls[2], scls[3]};
        for (int k = tid; k < L; k += 256) {
            float4 d = *(const float4*)&g_scores[b][k][0];
            float2 ab = g_stats[b][k];
            float4 s;
            s.x = SCALE * (ab.x * d.x + ab.y * C1[0] + C2[0]);
            s.y = SCALE * (ab.x * d.y + ab.y * C1[1] + C2[1]);
            s.z = SCALE * (ab.x * d.z + ab.y * C1[2] + C2[2]);
            s.w = SCALE * (ab.x * d.w + ab.y * C1[3] + C2[3]);
            *(float4*)&g_scores[b][k][0] = s;
            mx[0] = fmaxf(mx[0], s.x);
            mx[1] = fmaxf(mx[1], s.y);
            mx[2] = fmaxf(mx[2], s.z);
            mx[3] = fmaxf(mx[3], s.w);
        }
        float* r4 = SM;
#pragma unroll
        for (int h = 0; h < 4; h++) r4[tid * 4 + h] = mx[h];
        __syncthreads();
        for (int o = 128; o; o >>= 1) {
            if (tid < o)
#pragma unroll
                for (int h = 0; h < 4; h++)
                    r4[tid * 4 + h] = fmaxf(r4[tid * 4 + h], r4[(tid + o) * 4 + h]);
            __syncthreads();
        }
        float M[4];
#pragma unroll
        for (int h = 0; h < 4; h++) M[h] = r4[h];
        __syncthreads();
        // pass B: exp + write w + sums
        float se[4] = {0, 0, 0, 0}, ewb[4] = {0, 0, 0, 0};
        for (int k = tid; k < L; k += 256) {
            float4 s = *(const float4*)&g_scores[b][k][0];
            float2 ab = g_stats[b][k];
            float e0 = __expf(s.x - M[0]);
            float e1 = __expf(s.y - M[1]);
            float e2 = __expf(s.z - M[2]);
            float e3 = __expf(s.w - M[3]);
            *(float4*)&g_wts[b][k][0] = make_float4(e0 * ab.x, e1 * ab.x, e2 * ab.x, e3 * ab.x);
            se[0] += e0; se[1] += e1; se[2] += e2; se[3] += e3;
            ewb[0] += e0 * ab.y; ewb[1] += e1 * ab.y; ewb[2] += e2 * ab.y; ewb[3] += e3 * ab.y;
        }
        float* r8 = SM;
#pragma unroll
        for (int h = 0; h < 4; h++) {
            r8[tid * 8 + h] = se[h];
            r8[tid * 8 + 4 + h] = ewb[h];
        }
        __syncthreads();
        for (int o = 128; o; o >>= 1) {
            if (tid < o)
#pragma unroll
                for (int j = 0; j < 8; j++) r8[tid * 8 + j] += r8[(tid + o) * 8 + j];
            __syncthreads();
        }
        if (tid < 4) {
            int h = tid;
            float ec = __expf(scls[h] - M[h]);
            float S = r8[h] + ec;
            g_wmisc[b][h] = r8[4 + h];     // sum e*beta
            g_wmisc[b][4 + h] = r8[h];     // sum e
            g_wmisc[b][8 + h] = ec;        // e_cls
            g_wmisc[b][12 + h] = 1.f / S;  // invS
        }
    }
    gridbar(base, 4);

    // ============ P5: A[h][i] = sum_k (e*alpha)_k x_k[i] (16 k-splits x 32 b) ============
    {
        int half = tid >> 7, t128 = tid & 127;
        int vb = bid * 2 + half;  // 0..511
        int ks = vb & 15, b = vb >> 4;
        int L = __ldg(&mask[b]);
        int k0 = ks * 32, k1 = min(L, k0 + 32);
        float4 a0 = {0, 0, 0, 0}, a1 = a0, a2 = a0, a3 = a0;
        const float4* xb4 = (const float4*)(x + (size_t)b * 512 * 512);
#pragma unroll 4
        for (int k = k0; k < k1; k++) {
            float4 xv = __ldg(xb4 + (size_t)k * 128 + t128);
            float4 wa = *(const float4*)&g_wts[b][k][0];
            a0.x = fmaf(wa.x, xv.x, a0.x); a0.y = fmaf(wa.x, xv.y, a0.y);
            a0.z = fmaf(wa.x, xv.z, a0.z); a0.w = fmaf(wa.x, xv.w, a0.w);
            a1.x = fmaf(wa.y, xv.x, a1.x); a1.y = fmaf(wa.y, xv.y, a1.y);
            a1.z = fmaf(wa.y, xv.z, a1.z); a1.w = fmaf(wa.y, xv.w, a1.w);
            a2.x = fmaf(wa.z, xv.x, a2.x); a2.y = fmaf(wa.z, xv.y, a2.y);
            a2.z = fmaf(wa.z, xv.z, a2.z); a2.w = fmaf(wa.z, xv.w, a2.w);
            a3.x = fmaf(wa.w, xv.x, a3.x); a3.y = fmaf(wa.w, xv.y, a3.y);
            a3.z = fmaf(wa.w, xv.z, a3.z); a3.w = fmaf(wa.w, xv.w, a3.w);
        }
        int i = t128 * 4;
        *(float4*)&g_ppart[ks][b][0][i] = a0;
        *(float4*)&g_ppart[ks][b][1][i] = a1;
        *(float4*)&g_ppart[ks][b][2][i] = a2;
        *(float4*)&g_ppart[ks][b][3][i] = a3;
    }
    gridbar(base, 5);

    // ============ T1: ctx partials = p @ Wv (128 vblocks) ============
    if (bid < 64) {
        int half = tid >> 7, t128 = tid & 127;
        int vb = bid * 2 + half;        // 0..127
        int hh = vb & 3, iy = vb >> 2;  // iy 0..31
        int i0 = iy * 16, f = hh * 128 + t128;
        float* sp = SM + half * 512;  // [32][16]
        for (int idx = t128; idx < 512; idx += 128) {
            int b = idx >> 4, ii = idx & 15, i = i0 + ii;
            float A = 0.f;
#pragma unroll
            for (int s = 0; s < 16; s++) A += g_ppart[s][b][hh][i];
            const float* wm = g_wmisc[b];
            sp[b * 16 + ii] =
                wm[12 + hh] * (s1[i] * (A + wm[hh]) + b1[i] * wm[4 + hh] + wm[8 + hh] * g_hl[i]);
        }
        __syncthreads();
        float acc[32];
#pragma unroll
        for (int b = 0; b < 32; b++) acc[b] = 0.f;
#pragma unroll
        for (int ii = 0; ii < 16; ii += 4) {
            int i = i0 + ii;
            float w0 = Wv[(size_t)i * 512 + f];
            float w1 = Wv[(size_t)(i + 1) * 512 + f];
            float w2 = Wv[(size_t)(i + 2) * 512 + f];
            float w3 = Wv[(size_t)(i + 3) * 512 + f];
#pragma unroll
            for (int b = 0; b < 32; b++) {
                float4 p = *(const float4*)&sp[b * 16 + ii];
                acc[b] = fmaf(p.x, w0, fmaf(p.y, w1, fmaf(p.z, w2, fmaf(p.w, w3, acc[b]))));
            }
        }
#pragma unroll
        for (int b = 0; b < 32; b++) g_ctxpart[iy][b][f] = acc[b];
    }
    gridbar(base, 6);

    // ============ T2: o partials = (ctx+bv) @ Wo (128 vblocks) ============
    if (bid < 64) {
        int half = tid >> 7, t128 = tid & 127;
        int vb = bid * 2 + half;
        int cx = vb & 3, iy = vb >> 2;  // iy 0..31
        int i0 = iy * 16, f = cx * 128 + t128;
        float* sc = SM + half * 512;
        for (int idx = t128; idx < 512; idx += 128) {
            int b = idx >> 4, ii = idx & 15, i = i0 + ii;
            float v = bv[i];
#pragma unroll
            for (int s = 0; s < 32; s++) v += g_ctxpart[s][b][i];
            sc[b * 16 + ii] = v;
        }
        __syncthreads();
        float acc[32];
#pragma unroll
        for (int b = 0; b < 32; b++) acc[b] = 0.f;
#pragma unroll
        for (int ii = 0; ii < 16; ii += 4) {
            int i = i0 + ii;
            float w0 = Wo[(size_t)i * 512 + f];
            float w1 = Wo[(size_t)(i + 1) * 512 + f];
            float w2 = Wo[(size_t)(i + 2) * 512 + f];
            float w3 = Wo[(size_t)(i + 3) * 512 + f];
#pragma unroll
            for (int b = 0; b < 32; b++) {
                float4 p = *(const float4*)&sc[b * 16 + ii];
                acc[b] = fmaf(p.x, w0, fmaf(p.y, w1, fmaf(p.z, w2, fmaf(p.w, w3, acc[b]))));
            }
        }
#pragma unroll
        for (int b = 0; b < 32; b++) g_wopart[iy][b][f] = acc[b];
    }
    gridbar(base, 7);

    // ============ T3: h1 = token + o + bo; LN2 stats ============
    if (bid < 32) {
        int b = bid;
        float sum = 0.f, ssq = 0.f;
#pragma unroll
        for (int t = 0; t < 2; t++) {
            int c = tid + 256 * t;
            float v = token[c] + bo[c];
#pragma unroll
            for (int s = 0; s < 32; s++) v += g_wopart[s][b][c];
            g_h1[b][c] = v;
            sum += v;
            ssq += v * v;
        }
        float* r2 = SM;
        r2[tid * 2] = sum;
        r2[tid * 2 + 1] = ssq;
        __syncthreads();
        for (int o = 128; o; o >>= 1) {
            if (tid < o) {
                r2[tid * 2] += r2[(tid + o) * 2];
                r2[tid * 2 + 1] += r2[(tid + o) * 2 + 1];
            }
            __syncthreads();
        }
        if (tid == 0) {
            float m = r2[0] * (1.f / 512.f);
            float var = r2[1] * (1.f / 512.f) - m * m;
            g_ln2[b] = make_float2(m, rsqrtf(var + 1e-5f));
        }
    }
    gridbar(base, 8);

    // ============ T4: W1 partials (h2 @ W1), 512 vblocks ============
    {
        int half = tid >> 7, t128 = tid & 127;
        int vb = bid * 2 + half;         // 0..511
        int fx = vb & 15, iy = vb >> 4;  // iy 0..31
        int i0 = iy * 16, f = fx * 128 + t128;
        float* sh2 = SM + half * 512;
        for (int idx = t128; idx < 512; idx += 128) {
            int b = idx >> 4, ii = idx & 15, i = i0 + ii;
            float2 mr = g_ln2[b];
            sh2[b * 16 + ii] = (g_h1[b][i] - mr.x) * mr.y * s2[i] + b2l[i];
        }
        __syncthreads();
        float acc[32];
#pragma unroll
        for (int b = 0; b < 32; b++) acc[b] = 0.f;
#pragma unroll
        for (int ii = 0; ii < 16; ii += 4) {
            int i = i0 + ii;
            float w0 = W1[(size_t)i * 2048 + f];
            float w1 = W1[(size_t)(i + 1) * 2048 + f];
            float w2 = W1[(size_t)(i + 2) * 2048 + f];
            float w3 = W1[(size_t)(i + 3) * 2048 + f];
#pragma unroll
            for (int b = 0; b < 32; b++) {
                float4 p = *(const float4*)&sh2[b * 16 + ii];
                acc[b] = fmaf(p.x, w0, fmaf(p.y, w1, fmaf(p.z, w2, fmaf(p.w, w3, acc[b]))));
            }
        }
#pragma unroll
        for (int b = 0; b < 32; b++) g_w1part[iy][b][f] = acc[b];
    }
    gridbar(base, 9);

    // ============ T5: gelu + W2 partials, 512 vblocks ============
    {
        int half = tid >> 7, t128 = tid & 127;
        int vb = bid * 2 + half;        // 0..511
        int fx = vb & 3, iy = vb >> 2;  // iy 0..127
        int i0 = iy * 16, f = fx * 128 + t128;
        float* su = SM + half * 512;
        for (int idx = t128; idx < 512; idx += 128) {
            int b = idx >> 4, ii = idx & 15, i = i0 + ii;
            float u = b1f[i];
#pragma unroll
            for (int s = 0; s < 32; s++) u += g_w1part[s][b][i];
            su[b * 16 + ii] = geluf(u);
        }
        __syncthreads();
        float acc[32];
#pragma unroll
        for (int b = 0; b < 32; b++) acc[b] = 0.f;
#pragma unroll
        for (int ii = 0; ii < 16; ii += 4) {
            int i = i0 + ii;
            float w0 = W2[(size_t)i * 512 + f];
            float w1 = W2[(size_t)(i + 1) * 512 + f];
            float w2 = W2[(size_t)(i + 2) * 512 + f];
            float w3 = W2[(size_t)(i + 3) * 512 + f];
#pragma unroll
            for (int b = 0; b < 32; b++) {
                float4 p = *(const float4*)&su[b * 16 + ii];
                acc[b] = fmaf(p.x, w0, fmaf(p.y, w1, fmaf(p.z, w2, fmaf(p.w, w3, acc[b]))));
            }
        }
#pragma unroll
        for (int b = 0; b < 32; b++) g_w2part[iy][b][f] = acc[b];
    }
    gridbar(base, 10);

    // ============ OUT ============
    if (bid < 32) {
        int b = bid;
        int c0 = tid * 2;
        float2 acc;
        acc.x = g_h1[b][c0] + b2o[c0];
        acc.y = g_h1[b][c0 + 1] + b2o[c0 + 1];
#pragma unroll 16
        for (int s = 0; s < 128; s++) {
            float2 w = *(const float2*)&g_w2part[s][b][c0];
            acc.x += w.x;
            acc.y += w.y;
        }
        *(float2*)&out[b * 512 + c0] = acc;
    }
}

extern "C" void kernel_launch(void* const* d_in, const int* in_sizes, int n_in,
                              void* d_out, int out_size) {
    const float* x     = (const float*)d_in[0];
    const int*   mask  = (const int*)d_in[1];
    const float* token = (const float*)d_in[2];
    const float* Wq    = (const float*)d_in[3];
    const float* bq    = (const float*)d_in[4];
    const float* Wk    = (const float*)d_in[5];
    // d_in[6] = bk: uniform shift across keys -> cancels in softmax; unused
    const float* Wv    = (const float*)d_in[7];
    const float* bv    = (const float*)d_in[8];
    const float* Wo    = (const float*)d_in[9];
    const float* bo    = (const float*)d_in[10];
    const float* s1    = (const float*)d_in[11];
    const float* b1    = (const float*)d_in[12];
    const float* s2    = (const float*)d_in[13];
    const float* b2l   = (const float*)d_in[14];
    const float* W1    = (const float*)d_in[15];
    const float* b1f   = (const float*)d_in[16];
    const float* W2    = (const float*)d_in[17];
    const float* b2o   = (const float*)d_in[18];
    float* out = (float*)d_out;

    fused_kernel<<<NB, NT>>>(x, mask, token, Wq, bq, Wk, Wv, bv, Wo, bo,
                             s1, b1, s2, b2l, W1, b1f, W2, b2o, out);
}

// round 7
// speedup vs baseline: 1.7091x; 1.1195x over previous
#include <cuda_runtime.h>
#include <math.h>

#define SCALE 0.08838834764831845f  // 1/sqrt(128)
#define NB 256
#define NT 256

// ---------------- grid barrier state ----------------
__device__ unsigned g_count;
__device__ volatile unsigned g_release;
__device__ float g_dummy;

// ---------------- scratch ----------------
__device__ __align__(16) float g_hl[512];
__device__ __align__(16) float g_qpart[16][512];
__device__ __align__(16) float g_g[4][512];
__device__ __align__(16) float g_gs[4][512];
__device__ __align__(16) float g_cpart[64][12];        // per-P2-block C partials
__device__ __align__(16) float g_pm[16][32][4];        // split-local max
__device__ __align__(16) float g_pse[16][32][4];       // split-local sum e
__device__ __align__(16) float g_pewb[16][32][4];      // split-local sum e*beta
__device__ __align__(16) float g_ppart[16][32][4][512];
__device__ __align__(16) float g_ctxpart[32][32][512];
__device__ __align__(16) float g_wopart[32][32][512];
__device__ __align__(16) float g_h1[32][512];
__device__ __align__(16) float2 g_ln2[32];
__device__ __align__(16) float g_w1part[32][32][2048];
__device__ __align__(16) float g_w2part[128][32][512];

static __device__ __forceinline__ float wred(float v) {
#pragma unroll
    for (int o = 16; o; o >>= 1) v += __shfl_xor_sync(0xffffffffu, v, o);
    return v;
}

static __device__ __forceinline__ float geluf(float t) {
    float t3 = t * t * t;
    return 0.5f * t * (1.f + tanhf(0.7978845608028654f * (t + 0.044715f * t3)));
}

__device__ __forceinline__ void gridbar(unsigned base, unsigned idx) {
    __syncthreads();
    if (threadIdx.x == 0) {
        __threadfence();
        if (atomicAdd(&g_count, 1u) == NB - 1) {
            g_count = 0;
            __threadfence();
            g_release = base + idx;
        } else {
            while ((unsigned)(g_release - base) < idx) __nanosleep(32);
            __threadfence();
        }
    }
    __syncthreads();
}

__global__ void __launch_bounds__(NT, 2) fused_kernel(
    const float* __restrict__ x, const int* __restrict__ mask,
    const float* __restrict__ token,
    const float* __restrict__ Wq, const float* __restrict__ bq,
    const float* __restrict__ Wk,
    const float* __restrict__ Wv, const float* __restrict__ bv,
    const float* __restrict__ Wo, const float* __restrict__ bo,
    const float* __restrict__ s1, const float* __restrict__ b1,
    const float* __restrict__ s2, const float* __restrict__ b2l,
    const float* __restrict__ W1, const float* __restrict__ b1f,
    const float* __restrict__ W2, const float* __restrict__ b2o,
    float* __restrict__ out) {
    __shared__ float SM[3072];
    __shared__ unsigned s_base_sh;
    int tid = threadIdx.x;
    int bid = blockIdx.x;
    int wid = tid >> 5, lane = tid & 31;
    if (tid == 0) s_base_sh = g_release;
    __syncthreads();
    unsigned base = s_base_sh;

    // ============ P1: LN(token) + q partials; others prefetch x + weights -> L2 ============
    if (bid < 16) {
        float t0 = token[tid], t1 = token[tid + 256];
        float* red = SM;
        red[tid] = t0 + t1;
        __syncthreads();
#pragma unroll
        for (int o = 128; o; o >>= 1) {
            if (tid < o) red[tid] += red[tid + o];
            __syncthreads();
        }
        float mean = red[0] * (1.f / 512.f);
        __syncthreads();
        float d0 = t0 - mean, d1 = t1 - mean;
        red[tid] = d0 * d0 + d1 * d1;
        __syncthreads();
#pragma unroll
        for (int o = 128; o; o >>= 1) {
            if (tid < o) red[tid] += red[tid + o];
            __syncthreads();
        }
        float rstd = rsqrtf(red[0] * (1.f / 512.f) + 1e-5f);
        __syncthreads();
        float* shl = SM;
        float hl0 = d0 * rstd * s1[tid] + b1[tid];
        float hl1 = d1 * rstd * s1[tid + 256] + b1[tid + 256];
        shl[tid] = hl0;
        shl[tid + 256] = hl1;
        if (bid == 0) {
            g_hl[tid] = hl0;
            g_hl[tid + 256] = hl1;
        }
        __syncthreads();
        int j0 = bid * 32;
        float a0 = 0.f, a1 = 0.f;
#pragma unroll
        for (int j = 0; j < 32; j++) {
            float h = shl[j0 + j];
            a0 = fmaf(h, Wq[(size_t)(j0 + j) * 512 + tid], a0);
            a1 = fmaf(h, Wq[(size_t)(j0 + j) * 512 + tid + 256], a1);
        }
        g_qpart[bid][tid] = a0;
        g_qpart[bid][tid + 256] = a1;
    } else if (bid < 224) {
        int pw = (bid - 16) * 8 + wid;  // 0..1663
        float acc = 0.f;
        for (int r = pw; r < 16384; r += 1664) {
            int b = r >> 9, k = r & 511;
            if (k >= __ldg(&mask[b])) continue;
            const float4* xr = (const float4*)(x + (size_t)r * 512);
#pragma unroll
            for (int t = 0; t < 4; t++) {
                float4 v = __ldg(xr + lane + 32 * t);
                acc += v.x;
            }
        }
        if (acc == 1.2345e30f) g_dummy = acc;
    } else {
        int pw = (bid - 224) * 256 + tid;  // 0..8191
        float acc = 0.f;
        const float4* a0 = (const float4*)Wk;
        const float4* a1 = (const float4*)Wv;
        const float4* a2 = (const float4*)Wo;
        const float4* a3 = (const float4*)W1;
        const float4* a4 = (const float4*)W2;
#pragma unroll 4
        for (int i = pw; i < 65536; i += 8192)
            acc += __ldg(a0 + i).x + __ldg(a1 + i).x + __ldg(a2 + i).x;
#pragma unroll 4
        for (int i = pw; i < 262144; i += 8192)
            acc += __ldg(a3 + i).x + __ldg(a4 + i).x;
        if (acc == 1.2345e30f) g_dummy = acc;
    }
    gridbar(base, 1);

    // ============ P2: combine q; g[h][r] = Wk[r,head].q_head; C partials ============
    if (bid < 64) {
        float* sq = SM;
        float q0 = bq[tid], q1 = bq[tid + 256];
#pragma unroll
        for (int s = 0; s < 16; s++) {
            q0 += g_qpart[s][tid];
            q1 += g_qpart[s][tid + 256];
        }
        sq[tid] = q0;
        sq[tid + 256] = q1;
        __syncthreads();
        int r = bid * 8 + wid;
        const float4* wr = (const float4*)(Wk + (size_t)r * 512);
        const float4* q4 = (const float4*)sq;
        float dt[4];
#pragma unroll
        for (int t = 0; t < 4; t++) {
            float4 w = __ldg(wr + lane + 32 * t);
            float4 q = q4[lane + 32 * t];
            dt[t] = w.x * q.x + w.y * q.y + w.z * q.z + w.w * q.w;
        }
#pragma unroll
        for (int t = 0; t < 4; t++) dt[t] = wred(dt[t]);
        float* cred = SM + 512;  // [8][12]
        if (lane == 0) {
            float sr = s1[r], br = b1[r], hr = g_hl[r];
#pragma unroll
            for (int t = 0; t < 4; t++) {
                g_g[t][r] = dt[t];
                g_gs[t][r] = dt[t] * sr;
                cred[wid * 12 + t] = sr * dt[t];
                cred[wid * 12 + 4 + t] = br * dt[t];
                cred[wid * 12 + 8 + t] = hr * dt[t];
            }
        }
        __syncthreads();
        if (tid < 12) {
            float c = 0.f;
#pragma unroll
            for (int w = 0; w < 8; w++) c += cred[w * 12 + tid];
            g_cpart[bid][tid] = c;
        }
    }
    gridbar(base, 2);

    // ============ P3': scores + split-local online softmax + A accumulate ============
    {
        for (int i = tid; i < 2048; i += NT) SM[i] = ((const float*)g_gs)[i];
        if (tid < 12) {
            float c = 0.f;
#pragma unroll
            for (int j = 0; j < 64; j++) c += g_cpart[j][tid];
            SM[2976 + tid] = c;
        }
        __syncthreads();
        float C1[4], C2[4];
#pragma unroll
        for (int h = 0; h < 4; h++) {
            C1[h] = SM[2976 + h];
            C2[h] = SM[2980 + h];
        }
        const float4* sgs4 = (const float4*)SM;
        int half = tid >> 7, t128 = tid & 127, w = t128 >> 5;
        float* sS = SM + 2048 + half * 464;  // sc[128], al[32], be[32], w[128], e[128]
        int vb = bid * 2 + half;  // 0..511
        int ks = vb & 15, b = vb >> 4;
        int L = __ldg(&mask[b]);
        int k0 = ks * 32;
        // --- score pass: each warp 8 rows (2-batched) ---
#pragma unroll 1
        for (int it = 0; it < 4; it++) {
            int kl = w * 8 + it * 2;
            int kg = k0 + kl;
            bool v0 = kg < L, v1 = kg + 1 < L;
            const float4* xr0 = (const float4*)(x + ((size_t)b * 512 + kg) * 512);
            float4 xa[4], xc[4];
#pragma unroll
            for (int t = 0; t < 4; t++) xa[t] = make_float4(0.f, 0.f, 0.f, 0.f);
#pragma unroll
            for (int t = 0; t < 4; t++) xc[t] = make_float4(0.f, 0.f, 0.f, 0.f);
            if (v0) {
#pragma unroll
                for (int t = 0; t < 4; t++) xa[t] = __ldg(xr0 + lane + 32 * t);
            }
            if (v1) {
#pragma unroll
                for (int t = 0; t < 4; t++) xc[t] = __ldg(xr0 + 128 + lane + 32 * t);
            }
            float ssA = 0.f, smA = 0.f, ssB = 0.f, smB = 0.f;
#pragma unroll
            for (int t = 0; t < 4; t++) {
                ssA += xa[t].x * xa[t].x + xa[t].y * xa[t].y + xa[t].z * xa[t].z + xa[t].w * xa[t].w;
                smA += xa[t].x + xa[t].y + xa[t].z + xa[t].w;
                ssB += xc[t].x * xc[t].x + xc[t].y * xc[t].y + xc[t].z * xc[t].z + xc[t].w * xc[t].w;
                smB += xc[t].x + xc[t].y + xc[t].z + xc[t].w;
            }
            ssA = wred(ssA);
            ssB = wred(ssB);
            smA = wred(smA);
            smB = wred(smB);
            float invA = 1.f / fmaxf(sqrtf(ssA), 1e-12f);
            float invB = 1.f / fmaxf(sqrtf(ssB), 1e-12f);
            float mA = smA * invA * (1.f / 512.f), mB = smB * invB * (1.f / 512.f);
            float vA = ssA * invA * invA * (1.f / 512.f) - mA * mA;
            float vB = ssB * invB * invB * (1.f / 512.f) - mB * mB;
            float rA = rsqrtf(vA + 1e-5f), rB = rsqrtf(vB + 1e-5f);
            float alA = invA * rA, beA = -mA * rA;
            float alB = invB * rB, beB = -mB * rB;
            float dA[4], dB[4];
#pragma unroll
            for (int h = 0; h < 4; h++) {
                float aA = 0.f, aB = 0.f;
#pragma unroll
                for (int t = 0; t < 4; t++) {
                    float4 g = sgs4[h * 128 + lane + 32 * t];
                    aA += xa[t].x * g.x + xa[t].y * g.y + xa[t].z * g.z + xa[t].w * g.w;
                    aB += xc[t].x * g.x + xc[t].y * g.y + xc[t].z * g.z + xc[t].w * g.w;
                }
                dA[h] = wred(aA);
                dB[h] = wred(aB);
            }
            if (lane == 0) {
#pragma unroll
                for (int h = 0; h < 4; h++) {
                    sS[kl * 4 + h] = v0 ? SCALE * (alA * dA[h] + beA * C1[h] + C2[h]) : -1e30f;
                    sS[(kl + 1) * 4 + h] = v1 ? SCALE * (alB * dB[h] + beB * C1[h] + C2[h]) : -1e30f;
                }
                sS[128 + kl] = v0 ? alA : 0.f;
                sS[128 + kl + 1] = v1 ? alB : 0.f;
                sS[160 + kl] = v0 ? beA : 0.f;
                sS[160 + kl + 1] = v1 ? beB : 0.f;
            }
        }
        __syncthreads();
        // --- e/w compute: thread (k,h) = (t128>>2, t128&3) ---
        {
            int k = t128 >> 2, h = t128 & 3;
            float m = -1e30f;
#pragma unroll 8
            for (int j = 0; j < 32; j++) m = fmaxf(m, sS[j * 4 + h]);
            float e = __expf(sS[k * 4 + h] - m);
            sS[320 + k * 4 + h] = e;
            sS[192 + k * 4 + h] = e * sS[128 + k];
            if (k == 0) g_pm[ks][b][h] = m;
        }
        __syncthreads();
        // --- A accumulate (x rows from L1) ---
        int kv = L - k0;
        kv = kv < 0 ? 0 : (kv > 32 ? 32 : kv);
        float4 A0 = {0, 0, 0, 0}, A1 = A0, A2 = A0, A3 = A0;
        const float4* xb4 = (const float4*)(x + ((size_t)b * 512 + k0) * 512);
#pragma unroll 4
        for (int k = 0; k < kv; k++) {
            float4 w4 = *(const float4*)&sS[192 + k * 4];
            float4 xv = __ldg(xb4 + (size_t)k * 128 + t128);
            A0.x = fmaf(w4.x, xv.x, A0.x); A0.y = fmaf(w4.x, xv.y, A0.y);
            A0.z = fmaf(w4.x, xv.z, A0.z); A0.w = fmaf(w4.x, xv.w, A0.w);
            A1.x = fmaf(w4.y, xv.x, A1.x); A1.y = fmaf(w4.y, xv.y, A1.y);
            A1.z = fmaf(w4.y, xv.z, A1.z); A1.w = fmaf(w4.y, xv.w, A1.w);
            A2.x = fmaf(w4.z, xv.x, A2.x); A2.y = fmaf(w4.z, xv.y, A2.y);
            A2.z = fmaf(w4.z, xv.z, A2.z); A2.w = fmaf(w4.z, xv.w, A2.w);
            A3.x = fmaf(w4.w, xv.x, A3.x); A3.y = fmaf(w4.w, xv.y, A3.y);
            A3.z = fmaf(w4.w, xv.z, A3.z); A3.w = fmaf(w4.w, xv.w, A3.w);
        }
        int i = t128 * 4;
        *(float4*)&g_ppart[ks][b][0][i] = A0;
        *(float4*)&g_ppart[ks][b][1][i] = A1;
        *(float4*)&g_ppart[ks][b][2][i] = A2;
        *(float4*)&g_ppart[ks][b][3][i] = A3;
        if (t128 < 4) {
            float se = 0.f, ewb = 0.f;
#pragma unroll 8
            for (int k = 0; k < 32; k++) {
                float e = sS[320 + k * 4 + t128];
                se += e;
                ewb += e * sS[160 + k];
            }
            g_pse[ks][b][t128] = se;
            g_pewb[ks][b][t128] = ewb;
        }
    }
    gridbar(base, 3);

    // ============ T1': combine scalars + rescale + p @ Wv (128 vblocks) ============
    if (bid < 64) {
        int half = tid >> 7, t128 = tid & 127;
        int vb = bid * 2 + half;        // 0..127
        int hh = vb & 3, iy = vb >> 2;  // iy 0..31
        int i0 = iy * 16, f = hh * 128 + t128;
        float* sb = SM + half * 704;  // fs[32][16]=512, invS[32], Se[32], Ewb[32], ecls[32]
        if (t128 < 32) {
            int b = t128;
            float scls = 0.f;
#pragma unroll
            for (int j = 0; j < 64; j++) scls += g_cpart[j][8 + hh];
            scls *= SCALE;
            float ms[16];
            float M = scls;
#pragma unroll
            for (int s = 0; s < 16; s++) {
                ms[s] = g_pm[s][b][hh];
                M = fmaxf(M, ms[s]);
            }
            float Se = 0.f, Ewb = 0.f;
#pragma unroll
            for (int s = 0; s < 16; s++) {
                float fs = __expf(ms[s] - M);
                sb[b * 16 + s] = fs;
                Se += fs * g_pse[s][b][hh];
                Ewb += fs * g_pewb[s][b][hh];
            }
            float ecls = __expf(scls - M);
            sb[512 + b] = 1.f / (Se + ecls);
            sb[544 + b] = Se;
            sb[576 + b] = Ewb;
            sb[608 + b] = ecls;
        }
        __syncthreads();
        float* sp = SM + 1408 + half * 512;  // [32][16]
        for (int idx = t128; idx < 512; idx += 128) {
            int b = idx >> 4, ii = idx & 15, i = i0 + ii;
            float A = 0.f;
#pragma unroll
            for (int s = 0; s < 16; s++) A = fmaf(sb[b * 16 + s], g_ppart[s][b][hh][i], A);
            sp[idx] = sb[512 + b] *
                      (s1[i] * (A + sb[576 + b]) + b1[i] * sb[544 + b] + sb[608 + b] * g_hl[i]);
        }
        __syncthreads();
        float acc[32];
#pragma unroll
        for (int b = 0; b < 32; b++) acc[b] = 0.f;
#pragma unroll
        for (int ii = 0; ii < 16; ii += 4) {
            int i = i0 + ii;
            float w0 = Wv[(size_t)i * 512 + f];
            float w1 = Wv[(size_t)(i + 1) * 512 + f];
            float w2 = Wv[(size_t)(i + 2) * 512 + f];
            float w3 = Wv[(size_t)(i + 3) * 512 + f];
#pragma unroll
            for (int b = 0; b < 32; b++) {
                float4 p = *(const float4*)&sp[b * 16 + ii];
                acc[b] = fmaf(p.x, w0, fmaf(p.y, w1, fmaf(p.z, w2, fmaf(p.w, w3, acc[b]))));
            }
        }
#pragma unroll
        for (int b = 0; b < 32; b++) g_ctxpart[iy][b][f] = acc[b];
    }
    gridbar(base, 4);

    // ============ T2: o partials = (ctx+bv) @ Wo (128 vblocks) ============
    if (bid < 64) {
        int half = tid >> 7, t128 = tid & 127;
        int vb = bid * 2 + half;
        int cx = vb & 3, iy = vb >> 2;  // iy 0..31
        int i0 = iy * 16, f = cx * 128 + t128;
        float* sc = SM + half * 512;
        for (int idx = t128; idx < 512; idx += 128) {
            int b = idx >> 4, ii = idx & 15, i = i0 + ii;
            float v = bv[i];
#pragma unroll
            for (int s = 0; s < 32; s++) v += g_ctxpart[s][b][i];
            sc[b * 16 + ii] = v;
        }
        __syncthreads();
        float acc[32];
#pragma unroll
        for (int b = 0; b < 32; b++) acc[b] = 0.f;
#pragma unroll
        for (int ii = 0; ii < 16; ii += 4) {
            int i = i0 + ii;
            float w0 = Wo[(size_t)i * 512 + f];
            float w1 = Wo[(size_t)(i + 1) * 512 + f];
            float w2 = Wo[(size_t)(i + 2) * 512 + f];
            float w3 = Wo[(size_t)(i + 3) * 512 + f];
#pragma unroll
            for (int b = 0; b < 32; b++) {
                float4 p = *(const float4*)&sc[b * 16 + ii];
                acc[b] = fmaf(p.x, w0, fmaf(p.y, w1, fmaf(p.z, w2, fmaf(p.w, w3, acc[b]))));
            }
        }
#pragma unroll
        for (int b = 0; b < 32; b++) g_wopart[iy][b][f] = acc[b];
    }
    gridbar(base, 5);

    // ============ T3: h1 = token + o + bo; LN2 stats ============
    if (bid < 32) {
        int b = bid;
        float sum = 0.f, ssq = 0.f;
#pragma unroll
        for (int t = 0; t < 2; t++) {
            int c = tid + 256 * t;
            float v = token[c] + bo[c];
#pragma unroll
            for (int s = 0; s < 32; s++) v += g_wopart[s][b][c];
            g_h1[b][c] = v;
            sum += v;
            ssq += v * v;
        }
        float* r2 = SM;
        r2[tid * 2] = sum;
        r2[tid * 2 + 1] = ssq;
        __syncthreads();
        for (int o = 128; o; o >>= 1) {
            if (tid < o) {
                r2[tid * 2] += r2[(tid + o) * 2];
                r2[tid * 2 + 1] += r2[(tid + o) * 2 + 1];
            }
            __syncthreads();
        }
        if (tid == 0) {
            float m = r2[0] * (1.f / 512.f);
            float var = r2[1] * (1.f / 512.f) - m * m;
            g_ln2[b] = make_float2(m, rsqrtf(var + 1e-5f));
        }
    }
    gridbar(base, 6);

    // ============ T4: W1 partials (h2 @ W1), 512 vblocks ============
    {
        int half = tid >> 7, t128 = tid & 127;
        int vb = bid * 2 + half;         // 0..511
        int fx = vb & 15, iy = vb >> 4;  // iy 0..31
        int i0 = iy * 16, f = fx * 128 + t128;
        float* sh2 = SM + half * 512;
        for (int idx = t128; idx < 512; idx += 128) {
            int b = idx >> 4, ii = idx & 15, i = i0 + ii;
            float2 mr = g_ln2[b];
            sh2[b * 16 + ii] = (g_h1[b][i] - mr.x) * mr.y * s2[i] + b2l[i];
        }
        __syncthreads();
        float acc[32];
#pragma unroll
        for (int b = 0; b < 32; b++) acc[b] = 0.f;
#pragma unroll
        for (int ii = 0; ii < 16; ii += 4) {
            int i = i0 + ii;
            float w0 = W1[(size_t)i * 2048 + f];
            float w1 = W1[(size_t)(i + 1) * 2048 + f];
            float w2 = W1[(size_t)(i + 2) * 2048 + f];
            float w3 = W1[(size_t)(i + 3) * 2048 + f];
#pragma unroll
            for (int b = 0; b < 32; b++) {
                float4 p = *(const float4*)&sh2[b * 16 + ii];
                acc[b] = fmaf(p.x, w0, fmaf(p.y, w1, fmaf(p.z, w2, fmaf(p.w, w3, acc[b]))));
            }
        }
#pragma unroll
        for (int b = 0; b < 32; b++) g_w1part[iy][b][f] = acc[b];
    }
    gridbar(base, 7);

    // ============ T5: gelu + W2 partials, 512 vblocks ============
    {
        int half = tid >> 7, t128 = tid & 127;
        int vb = bid * 2 + half;        // 0..511
        int fx = vb & 3, iy = vb >> 2;  // iy 0..127
        int i0 = iy * 16, f = fx * 128 + t128;
        float* su = SM + half * 512;
        for (int idx = t128; idx < 512; idx += 128) {
            int b = idx >> 4, ii = idx & 15, i = i0 + ii;
            float u = b1f[i];
#pragma unroll
            for (int s = 0; s < 32; s++) u += g_w1part[s][b][i];
            su[b * 16 + ii] = geluf(u);
        }
        __syncthreads();
        float acc[32];
#pragma unroll
        for (int b = 0; b < 32; b++) acc[b] = 0.f;
#pragma unroll
        for (int ii = 0; ii < 16; ii += 4) {
            int i = i0 + ii;
            float w0 = W2[(size_t)i * 512 + f];
            float w1 = W2[(size_t)(i + 1) * 512 + f];
            float w2 = W2[(size_t)(i + 2) * 512 + f];
            float w3 = W2[(size_t)(i + 3) * 512 + f];
#pragma unroll
            for (int b = 0; b < 32; b++) {
                float4 p = *(const float4*)&su[b * 16 + ii];
                acc[b] = fmaf(p.x, w0, fmaf(p.y, w1, fmaf(p.z, w2, fmaf(p.w, w3, acc[b]))));
            }
        }
#pragma unroll
        for (int b = 0; b < 32; b++) g_w2part[iy][b][f] = acc[b];
    }
    gridbar(base, 8);

    // ============ OUT ============
    if (bid < 32) {
        int b = bid;
        int c0 = tid * 2;
        float2 acc;
        acc.x = g_h1[b][c0] + b2o[c0];
        acc.y = g_h1[b][c0 + 1] + b2o[c0 + 1];
#pragma unroll 16
        for (int s = 0; s < 128; s++) {
            float2 w = *(const float2*)&g_w2part[s][b][c0];
            acc.x += w.x;
            acc.y += w.y;
        }
        *(float2*)&out[b * 512 + c0] = acc;
    }
}

extern "C" void kernel_launch(void* const* d_in, const int* in_sizes, int n_in,
                              void* d_out, int out_size) {
    const float* x     = (const float*)d_in[0];
    const int*   mask  = (const int*)d_in[1];
    const float* token = (const float*)d_in[2];
    const float* Wq    = (const float*)d_in[3];
    const float* bq    = (const float*)d_in[4];
    const float* Wk    = (const float*)d_in[5];
    // d_in[6] = bk: uniform shift across keys -> cancels in softmax; unused
    const float* Wv    = (const float*)d_in[7];
    const float* bv    = (const float*)d_in[8];
    const float* Wo    = (const float*)d_in[9];
    const float* bo    = (const float*)d_in[10];
    const float* s1    = (const float*)d_in[11];
    const float* b1    = (const float*)d_in[12];
    const float* s2    = (const float*)d_in[13];
    const float* b2l   = (const float*)d_in[14];
    const float* W1    = (const float*)d_in[15];
    const float* b1f   = (const float*)d_in[16];
    const float* W2    = (const float*)d_in[17];
    const float* b2o   = (const float*)d_in[18];
    float* out = (float*)d_out;

    fused_kernel<<<NB, NT>>>(x, mask, token, Wq, bq, Wk, Wv, bv, Wo, bo,
                             s1, b1, s2, b2l, W1, b1f, W2, b2o, out);
}

// round 8
// speedup vs baseline: 1.8252x; 1.0679x over previous
#include <cuda_runtime.h>
#include <math.h>

#define SCALE 0.08838834764831845f  // 1/sqrt(128)
#define NB 256
#define NT 256

// ---------------- grid barrier state ----------------
__device__ unsigned g_count;
__device__ volatile unsigned g_release;
__device__ float g_dummy;

// ---------------- scratch ----------------
__device__ __align__(16) float g_hl[512];
__device__ __align__(16) float g_qpart[16][512];
__device__ __align__(16) float g_g[4][512];
__device__ __align__(16) float g_gs[4][512];
__device__ __align__(16) float2 g_stats[32][512];
__device__ __align__(16) float g_cpart[64][12];
__device__ __align__(16) float g_pm[16][32][4];
__device__ __align__(16) float g_pse[16][32][4];
__device__ __align__(16) float g_pewb[16][32][4];
__device__ __align__(16) float g_ppart[16][32][4][512];
__device__ __align__(16) float g_ctxpart[32][32][512];
__device__ __align__(16) float g_wopart[32][32][512];
__device__ __align__(16) float g_h1[32][512];
__device__ __align__(16) float2 g_ln2[32];
__device__ __align__(16) float g_w1part[32][32][2048];
__device__ __align__(16) float g_w2part[128][32][512];

static __device__ __forceinline__ float wred(float v) {
#pragma unroll
    for (int o = 16; o; o >>= 1) v += __shfl_xor_sync(0xffffffffu, v, o);
    return v;
}

static __device__ __forceinline__ float geluf(float t) {
    float t3 = t * t * t;
    return 0.5f * t * (1.f + tanhf(0.7978845608028654f * (t + 0.044715f * t3)));
}

__device__ __forceinline__ void gridbar(unsigned base, unsigned idx) {
    __syncthreads();
    if (threadIdx.x == 0) {
        __threadfence();
        if (atomicAdd(&g_count, 1u) == NB - 1) {
            g_count = 0;
            __threadfence();
            g_release = base + idx;
        } else {
            while ((unsigned)(g_release - base) < idx) __nanosleep(32);
            __threadfence();
        }
    }
    __syncthreads();
}

__global__ void __launch_bounds__(NT, 2) fused_kernel(
    const float* __restrict__ x, const int* __restrict__ mask,
    const float* __restrict__ token,
    const float* __restrict__ Wq, const float* __restrict__ bq,
    const float* __restrict__ Wk,
    const float* __restrict__ Wv, const float* __restrict__ bv,
    const float* __restrict__ Wo, const float* __restrict__ bo,
    const float* __restrict__ s1, const float* __restrict__ b1,
    const float* __restrict__ s2, const float* __restrict__ b2l,
    const float* __restrict__ W1, const float* __restrict__ b1f,
    const float* __restrict__ W2, const float* __restrict__ b2o,
    float* __restrict__ out) {
    __shared__ float SM[3072];
    __shared__ unsigned s_base_sh;
    int tid = threadIdx.x;
    int bid = blockIdx.x;
    int wid = tid >> 5, lane = tid & 31;
    if (tid == 0) s_base_sh = g_release;
    __syncthreads();
    unsigned base = s_base_sh;

    // ============ P1: LN(token)+q partials | x stream + row stats | weight prefetch ====
    if (bid < 16) {
        float t0 = token[tid], t1 = token[tid + 256];
        float* red = SM;
        red[tid] = t0 + t1;
        __syncthreads();
#pragma unroll
        for (int o = 128; o; o >>= 1) {
            if (tid < o) red[tid] += red[tid + o];
            __syncthreads();
        }
        float mean = red[0] * (1.f / 512.f);
        __syncthreads();
        float d0 = t0 - mean, d1 = t1 - mean;
        red[tid] = d0 * d0 + d1 * d1;
        __syncthreads();
#pragma unroll
        for (int o = 128; o; o >>= 1) {
            if (tid < o) red[tid] += red[tid + o];
            __syncthreads();
        }
        float rstd = rsqrtf(red[0] * (1.f / 512.f) + 1e-5f);
        __syncthreads();
        float* shl = SM;
        float hl0 = d0 * rstd * s1[tid] + b1[tid];
        float hl1 = d1 * rstd * s1[tid + 256] + b1[tid + 256];
        shl[tid] = hl0;
        shl[tid + 256] = hl1;
        if (bid == 0) {
            g_hl[tid] = hl0;
            g_hl[tid + 256] = hl1;
        }
        __syncthreads();
        int j0 = bid * 32;
        float a0 = 0.f, a1 = 0.f;
#pragma unroll
        for (int j = 0; j < 32; j++) {
            float h = shl[j0 + j];
            a0 = fmaf(h, Wq[(size_t)(j0 + j) * 512 + tid], a0);
            a1 = fmaf(h, Wq[(size_t)(j0 + j) * 512 + tid + 256], a1);
        }
        g_qpart[bid][tid] = a0;
        g_qpart[bid][tid + 256] = a1;
    } else if (bid < 224) {
        // stream x (valid rows) + compute per-row LN stats (alpha,beta)
        int pw = (bid - 16) * 8 + wid;  // 0..1663
        int r0 = pw * 10;
        int rend = min(r0 + 10, 16384);
#pragma unroll 1
        for (int r = r0; r < rend; r += 2) {
            int bA = r >> 9, kA = r & 511;
            bool vA = kA < __ldg(&mask[bA]);
            bool h2 = (r + 1) < rend;
            int bB = (r + 1) >> 9, kB = (r + 1) & 511;
            bool vB = h2 && (kB < __ldg(&mask[bB]));
            float4 xa[4], xc[4];
#pragma unroll
            for (int t = 0; t < 4; t++) xa[t] = make_float4(0.f, 0.f, 0.f, 0.f);
#pragma unroll
            for (int t = 0; t < 4; t++) xc[t] = make_float4(0.f, 0.f, 0.f, 0.f);
            if (vA) {
                const float4* xr = (const float4*)(x + (size_t)r * 512);
#pragma unroll
                for (int t = 0; t < 4; t++) xa[t] = __ldg(xr + lane + 32 * t);
            }
            if (vB) {
                const float4* xr = (const float4*)(x + (size_t)(r + 1) * 512);
#pragma unroll
                for (int t = 0; t < 4; t++) xc[t] = __ldg(xr + lane + 32 * t);
            }
            float ssA = 0.f, smA = 0.f, ssB = 0.f, smB = 0.f;
#pragma unroll
            for (int t = 0; t < 4; t++) {
                ssA += xa[t].x * xa[t].x + xa[t].y * xa[t].y + xa[t].z * xa[t].z + xa[t].w * xa[t].w;
                smA += xa[t].x + xa[t].y + xa[t].z + xa[t].w;
                ssB += xc[t].x * xc[t].x + xc[t].y * xc[t].y + xc[t].z * xc[t].z + xc[t].w * xc[t].w;
                smB += xc[t].x + xc[t].y + xc[t].z + xc[t].w;
            }
            ssA = wred(ssA);
            ssB = wred(ssB);
            smA = wred(smA);
            smB = wred(smB);
            if (lane == 0) {
                if (vA) {
                    float inv = 1.f / fmaxf(sqrtf(ssA), 1e-12f);
                    float m = smA * inv * (1.f / 512.f);
                    float v = ssA * inv * inv * (1.f / 512.f) - m * m;
                    float rs = rsqrtf(v + 1e-5f);
                    g_stats[bA][kA] = make_float2(inv * rs, -m * rs);
                }
                if (vB) {
                    float inv = 1.f / fmaxf(sqrtf(ssB), 1e-12f);
                    float m = smB * inv * (1.f / 512.f);
                    float v = ssB * inv * inv * (1.f / 512.f) - m * m;
                    float rs = rsqrtf(v + 1e-5f);
                    g_stats[bB][kB] = make_float2(inv * rs, -m * rs);
                }
            }
        }
    } else {
        // prefetch Wk, Wv, Wo, W1, W2 into L2
        int pw = (bid - 224) * 256 + tid;  // 0..8191
        float acc = 0.f;
        const float4* a0 = (const float4*)Wk;
        const float4* a1 = (const float4*)Wv;
        const float4* a2 = (const float4*)Wo;
        const float4* a3 = (const float4*)W1;
        const float4* a4 = (const float4*)W2;
#pragma unroll 4
        for (int i = pw; i < 65536; i += 8192)
            acc += __ldg(a0 + i).x + __ldg(a1 + i).x + __ldg(a2 + i).x;
#pragma unroll 4
        for (int i = pw; i < 262144; i += 8192)
            acc += __ldg(a3 + i).x + __ldg(a4 + i).x;
        if (acc == 1.2345e30f) g_dummy = acc;
    }
    gridbar(base, 1);

    // ============ P2: combine q; g[h][r] = Wk[r,head].q_head; C partials ============
    if (bid < 64) {
        float* sq = SM;
        float q0 = bq[tid], q1 = bq[tid + 256];
#pragma unroll
        for (int s = 0; s < 16; s++) {
            q0 += g_qpart[s][tid];
            q1 += g_qpart[s][tid + 256];
        }
        sq[tid] = q0;
        sq[tid + 256] = q1;
        __syncthreads();
        int r = bid * 8 + wid;
        const float4* wr = (const float4*)(Wk + (size_t)r * 512);
        const float4* q4 = (const float4*)sq;
        float dt[4];
#pragma unroll
        for (int t = 0; t < 4; t++) {
            float4 w = __ldg(wr + lane + 32 * t);
            float4 q = q4[lane + 32 * t];
            dt[t] = w.x * q.x + w.y * q.y + w.z * q.z + w.w * q.w;
        }
#pragma unroll
        for (int t = 0; t < 4; t++) dt[t] = wred(dt[t]);
        float* cred = SM + 512;  // [8][12]
        if (lane == 0) {
            float sr = s1[r], br = b1[r], hr = g_hl[r];
#pragma unroll
            for (int t = 0; t < 4; t++) {
                g_g[t][r] = dt[t];
                g_gs[t][r] = dt[t] * sr;
                cred[wid * 12 + t] = sr * dt[t];
                cred[wid * 12 + 4 + t] = br * dt[t];
                cred[wid * 12 + 8 + t] = hr * dt[t];
            }
        }
        __syncthreads();
        if (tid < 12) {
            float c = 0.f;
#pragma unroll
            for (int w = 0; w < 8; w++) c += cred[w * 12 + tid];
            g_cpart[bid][tid] = c;
        }
    }
    gridbar(base, 2);

    // ============ P3': scores (stats precomputed) + split softmax + A accumulate ============
    {
        for (int i = tid; i < 2048; i += NT) SM[i] = ((const float*)g_gs)[i];
        if (tid < 12) {
            float c = 0.f;
#pragma unroll
            for (int j = 0; j < 64; j++) c += g_cpart[j][tid];
            SM[2976 + tid] = c;
        }
        __syncthreads();
        float C1[4], C2[4];
#pragma unroll
        for (int h = 0; h < 4; h++) {
            C1[h] = SM[2976 + h];
            C2[h] = SM[2980 + h];
        }
        const float4* sgs4 = (const float4*)SM;
        int half = tid >> 7, t128 = tid & 127, w = t128 >> 5;
        float* sS = SM + 2048 + half * 464;  // sc[128], al[32], be[32], w[128], e[128]
        int vb = bid * 2 + half;  // 0..511
        int ks = vb & 15, b = vb >> 4;
        int L = __ldg(&mask[b]);
        int k0 = ks * 32;
        // --- score pass: each warp 8 rows (2-batched); stats from g_stats ---
#pragma unroll 1
        for (int it = 0; it < 4; it++) {
            int kl = w * 8 + it * 2;
            int kg = k0 + kl;
            bool v0 = kg < L, v1 = kg + 1 < L;
            const float4* xr0 = (const float4*)(x + ((size_t)b * 512 + kg) * 512);
            float4 xa[4], xc[4];
#pragma unroll
            for (int t = 0; t < 4; t++) xa[t] = make_float4(0.f, 0.f, 0.f, 0.f);
#pragma unroll
            for (int t = 0; t < 4; t++) xc[t] = make_float4(0.f, 0.f, 0.f, 0.f);
            float2 ab0 = make_float2(0.f, 0.f), ab1 = make_float2(0.f, 0.f);
            if (v0) {
                ab0 = g_stats[b][kg];
#pragma unroll
                for (int t = 0; t < 4; t++) xa[t] = __ldg(xr0 + lane + 32 * t);
            }
            if (v1) {
                ab1 = g_stats[b][kg + 1];
#pragma unroll
                for (int t = 0; t < 4; t++) xc[t] = __ldg(xr0 + 128 + lane + 32 * t);
            }
            float dA[4], dB[4];
#pragma unroll
            for (int h = 0; h < 4; h++) {
                float aA = 0.f, aB = 0.f;
#pragma unroll
                for (int t = 0; t < 4; t++) {
                    float4 g = sgs4[h * 128 + lane + 32 * t];
                    aA += xa[t].x * g.x + xa[t].y * g.y + xa[t].z * g.z + xa[t].w * g.w;
                    aB += xc[t].x * g.x + xc[t].y * g.y + xc[t].z * g.z + xc[t].w * g.w;
                }
                dA[h] = wred(aA);
                dB[h] = wred(aB);
            }
            if (lane == 0) {
#pragma unroll
                for (int h = 0; h < 4; h++) {
                    sS[kl * 4 + h] = v0 ? SCALE * (ab0.x * dA[h] + ab0.y * C1[h] + C2[h]) : -1e30f;
                    sS[(kl + 1) * 4 + h] = v1 ? SCALE * (ab1.x * dB[h] + ab1.y * C1[h] + C2[h]) : -1e30f;
                }
                sS[128 + kl] = ab0.x;
                sS[128 + kl + 1] = ab1.x;
                sS[160 + kl] = ab0.y;
                sS[160 + kl + 1] = ab1.y;
            }
        }
        __syncthreads();
        // --- e/w compute: thread (k,h) = (t128>>2, t128&3) ---
        {
            int k = t128 >> 2, h = t128 & 3;
            float m = -1e30f;
#pragma unroll 8
            for (int j = 0; j < 32; j++) m = fmaxf(m, sS[j * 4 + h]);
            float e = __expf(sS[k * 4 + h] - m);
            sS[320 + k * 4 + h] = e;
            sS[192 + k * 4 + h] = e * sS[128 + k];
            if (k == 0) g_pm[ks][b][h] = m;
        }
        __syncthreads();
        // --- A accumulate ---
        int kv = L - k0;
        kv = kv < 0 ? 0 : (kv > 32 ? 32 : kv);
        float4 A0 = {0, 0, 0, 0}, A1 = A0, A2 = A0, A3 = A0;
        const float4* xb4 = (const float4*)(x + ((size_t)b * 512 + k0) * 512);
#pragma unroll 4
        for (int k = 0; k < kv; k++) {
            float4 w4 = *(const float4*)&sS[192 + k * 4];
            float4 xv = __ldg(xb4 + (size_t)k * 128 + t128);
            A0.x = fmaf(w4.x, xv.x, A0.x); A0.y = fmaf(w4.x, xv.y, A0.y);
            A0.z = fmaf(w4.x, xv.z, A0.z); A0.w = fmaf(w4.x, xv.w, A0.w);
            A1.x = fmaf(w4.y, xv.x, A1.x); A1.y = fmaf(w4.y, xv.y, A1.y);
            A1.z = fmaf(w4.y, xv.z, A1.z); A1.w = fmaf(w4.y, xv.w, A1.w);
            A2.x = fmaf(w4.z, xv.x, A2.x); A2.y = fmaf(w4.z, xv.y, A2.y);
            A2.z = fmaf(w4.z, xv.z, A2.z); A2.w = fmaf(w4.z, xv.w, A2.w);
            A3.x = fmaf(w4.w, xv.x, A3.x); A3.y = fmaf(w4.w, xv.y, A3.y);
            A3.z = fmaf(w4.w, xv.z, A3.z); A3.w = fmaf(w4.w, xv.w, A3.w);
        }
        int i = t128 * 4;
        *(float4*)&g_ppart[ks][b][0][i] = A0;
        *(float4*)&g_ppart[ks][b][1][i] = A1;
        *(float4*)&g_ppart[ks][b][2][i] = A2;
        *(float4*)&g_ppart[ks][b][3][i] = A3;
        if (t128 < 4) {
            float se = 0.f, ewb = 0.f;
#pragma unroll 8
            for (int k = 0; k < 32; k++) {
                float e = sS[320 + k * 4 + t128];
                se += e;
                ewb += e * sS[160 + k];
            }
            g_pse[ks][b][t128] = se;
            g_pewb[ks][b][t128] = ewb;
        }
    }
    gridbar(base, 3);

    // ============ T1': combine scalars + rescale + p @ Wv (512 vblocks, b-split 4) ============
    {
        int half = tid >> 7, t128 = tid & 127;
        int vb = bid * 2 + half;  // 0..511
        int bh = vb & 3, hh = (vb >> 2) & 3, iy = vb >> 4;  // iy 0..31
        int i0 = iy * 16, f = hh * 128 + t128;
        float* sb = SM + half * 160;        // fs[8][16], invS[8], Se[8], Ewb[8], ecls[8]
        float* sp = SM + 320 + half * 128;  // [8][16]
        if (t128 < 8) {
            int gb = bh * 8 + t128;
            float scls = 0.f;
#pragma unroll
            for (int j = 0; j < 64; j++) scls += g_cpart[j][8 + hh];
            scls *= SCALE;
            float ms[16];
            float M = scls;
#pragma unroll
            for (int s = 0; s < 16; s++) {
                ms[s] = g_pm[s][gb][hh];
                M = fmaxf(M, ms[s]);
            }
            float Se = 0.f, Ewb = 0.f;
#pragma unroll
            for (int s = 0; s < 16; s++) {
                float fs = __expf(ms[s] - M);
                sb[t128 * 16 + s] = fs;
                Se += fs * g_pse[s][gb][hh];
                Ewb += fs * g_pewb[s][gb][hh];
            }
            float ecls = __expf(scls - M);
            sb[128 + t128] = 1.f / (Se + ecls);
            sb[136 + t128] = Se;
            sb[144 + t128] = Ewb;
            sb[152 + t128] = ecls;
        }
        __syncthreads();
        {
            int bl = t128 >> 4, ii = t128 & 15;
            int gb = bh * 8 + bl;
            int i = i0 + ii;
            float A = 0.f;
#pragma unroll
            for (int s = 0; s < 16; s++) A = fmaf(sb[bl * 16 + s], g_ppart[s][gb][hh][i], A);
            sp[t128] = sb[128 + bl] *
                       (s1[i] * (A + sb[144 + bl]) + b1[i] * sb[136 + bl] + sb[152 + bl] * g_hl[i]);
        }
        __syncthreads();
        float acc[8];
#pragma unroll
        for (int bl = 0; bl < 8; bl++) acc[bl] = 0.f;
#pragma unroll
        for (int ii = 0; ii < 16; ii += 4) {
            int i = i0 + ii;
            float w0 = Wv[(size_t)i * 512 + f];
            float w1 = Wv[(size_t)(i + 1) * 512 + f];
            float w2 = Wv[(size_t)(i + 2) * 512 + f];
            float w3 = Wv[(size_t)(i + 3) * 512 + f];
#pragma unroll
            for (int bl = 0; bl < 8; bl++) {
                float4 p = *(const float4*)&sp[bl * 16 + ii];
                acc[bl] = fmaf(p.x, w0, fmaf(p.y, w1, fmaf(p.z, w2, fmaf(p.w, w3, acc[bl]))));
            }
        }
#pragma unroll
        for (int bl = 0; bl < 8; bl++) g_ctxpart[iy][bh * 8 + bl][f] = acc[bl];
    }
    gridbar(base, 4);

    // ============ T2: o partials = (ctx+bv) @ Wo (512 vblocks, b-split 4) ============
    {
        int half = tid >> 7, t128 = tid & 127;
        int vb = bid * 2 + half;
        int bh = vb & 3, cx = (vb >> 2) & 3, iy = vb >> 4;  // iy 0..31
        int i0 = iy * 16, f = cx * 128 + t128;
        float* sc = SM + half * 128;
        {
            int bl = t128 >> 4, ii = t128 & 15;
            int gb = bh * 8 + bl;
            int i = i0 + ii;
            float v = bv[i];
#pragma unroll
            for (int s = 0; s < 32; s++) v += g_ctxpart[s][gb][i];
            sc[t128] = v;
        }
        __syncthreads();
        float acc[8];
#pragma unroll
        for (int bl = 0; bl < 8; bl++) acc[bl] = 0.f;
#pragma unroll
        for (int ii = 0; ii < 16; ii += 4) {
            int i = i0 + ii;
            float w0 = Wo[(size_t)i * 512 + f];
            float w1 = Wo[(size_t)(i + 1) * 512 + f];
            float w2 = Wo[(size_t)(i + 2) * 512 + f];
            float w3 = Wo[(size_t)(i + 3) * 512 + f];
#pragma unroll
            for (int bl = 0; bl < 8; bl++) {
                float4 p = *(const float4*)&sc[bl * 16 + ii];
                acc[bl] = fmaf(p.x, w0, fmaf(p.y, w1, fmaf(p.z, w2, fmaf(p.w, w3, acc[bl]))));
            }
        }
#pragma unroll
        for (int bl = 0; bl < 8; bl++) g_wopart[iy][bh * 8 + bl][f] = acc[bl];
    }
    gridbar(base, 5);

    // ============ T3: h1 = token + o + bo; LN2 stats ============
    if (bid < 32) {
        int b = bid;
        float sum = 0.f, ssq = 0.f;
#pragma unroll
        for (int t = 0; t < 2; t++) {
            int c = tid + 256 * t;
            float v = token[c] + bo[c];
#pragma unroll
            for (int s = 0; s < 32; s++) v += g_wopart[s][b][c];
            g_h1[b][c] = v;
            sum += v;
            ssq += v * v;
        }
        float* r2 = SM;
        r2[tid * 2] = sum;
        r2[tid * 2 + 1] = ssq;
        __syncthreads();
        for (int o = 128; o; o >>= 1) {
            if (tid < o) {
                r2[tid * 2] += r2[(tid + o) * 2];
                r2[tid * 2 + 1] += r2[(tid + o) * 2 + 1];
            }
            __syncthreads();
        }
        if (tid == 0) {
            float m = r2[0] * (1.f / 512.f);
            float var = r2[1] * (1.f / 512.f) - m * m;
            g_ln2[b] = make_float2(m, rsqrtf(var + 1e-5f));
        }
    }
    gridbar(base, 6);

    // ============ T4: W1 partials (h2 @ W1), 512 vblocks ============
    {
        int half = tid >> 7, t128 = tid & 127;
        int vb = bid * 2 + half;         // 0..511
        int fx = vb & 15, iy = vb >> 4;  // iy 0..31
        int i0 = iy * 16, f = fx * 128 + t128;
        float* sh2 = SM + half * 512;
        for (int idx = t128; idx < 512; idx += 128) {
            int b = idx >> 4, ii = idx & 15, i = i0 + ii;
            float2 mr = g_ln2[b];
            sh2[b * 16 + ii] = (g_h1[b][i] - mr.x) * mr.y * s2[i] + b2l[i];
        }
        __syncthreads();
        float acc[32];
#pragma unroll
        for (int b = 0; b < 32; b++) acc[b] = 0.f;
#pragma unroll
        for (int ii = 0; ii < 16; ii += 4) {
            int i = i0 + ii;
            float w0 = W1[(size_t)i * 2048 + f];
            float w1 = W1[(size_t)(i + 1) * 2048 + f];
            float w2 = W1[(size_t)(i + 2) * 2048 + f];
            float w3 = W1[(size_t)(i + 3) * 2048 + f];
#pragma unroll
            for (int b = 0; b < 32; b++) {
                float4 p = *(const float4*)&sh2[b * 16 + ii];
                acc[b] = fmaf(p.x, w0, fmaf(p.y, w1, fmaf(p.z, w2, fmaf(p.w, w3, acc[b]))));
            }
        }
#pragma unroll
        for (int b = 0; b < 32; b++) g_w1part[iy][b][f] = acc[b];
    }
    gridbar(base, 7);

    // ============ T5: gelu + W2 partials, 512 vblocks ============
    {
        int half = tid >> 7, t128 = tid & 127;
        int vb = bid * 2 + half;        // 0..511
        int fx = vb & 3, iy = vb >> 2;  // iy 0..127
        int i0 = iy * 16, f = fx * 128 + t128;
        float* su = SM + half * 512;
        for (int idx = t128; idx < 512; idx += 128) {
            int b = idx >> 4, ii = idx & 15, i = i0 + ii;
            float u = b1f[i];
#pragma unroll
            for (int s = 0; s < 32; s++) u += g_w1part[s][b][i];
            su[b * 16 + ii] = geluf(u);
        }
        __syncthreads();
        float acc[32];
#pragma unroll
        for (int b = 0; b < 32; b++) acc[b] = 0.f;
#pragma unroll
        for (int ii = 0; ii < 16; ii += 4) {
            int i = i0 + ii;
            float w0 = W2[(size_t)i * 512 + f];
            float w1 = W2[(size_t)(i + 1) * 512 + f];
            float w2 = W2[(size_t)(i + 2) * 512 + f];
            float w3 = W2[(size_t)(i + 3) * 512 + f];
#pragma unroll
            for (int b = 0; b < 32; b++) {
                float4 p = *(const float4*)&su[b * 16 + ii];
                acc[b] = fmaf(p.x, w0, fmaf(p.y, w1, fmaf(p.z, w2, fmaf(p.w, w3, acc[b]))));
            }
        }
#pragma unroll
        for (int b = 0; b < 32; b++) g_w2part[iy][b][f] = acc[b];
    }
    gridbar(base, 8);

    // ============ OUT ============
    if (bid < 32) {
        int b = bid;
        int c0 = tid * 2;
        float2 acc;
        acc.x = g_h1[b][c0] + b2o[c0];
        acc.y = g_h1[b][c0 + 1] + b2o[c0 + 1];
#pragma unroll 16
        for (int s = 0; s < 128; s++) {
            float2 w = *(const float2*)&g_w2part[s][b][c0];
            acc.x += w.x;
            acc.y += w.y;
        }
        *(float2*)&out[b * 512 + c0] = acc;
    }
}

extern "C" void kernel_launch(void* const* d_in, const int* in_sizes, int n_in,
                              void* d_out, int out_size) {
    const float* x     = (const float*)d_in[0];
    const int*   mask  = (const int*)d_in[1];
    const float* token = (const float*)d_in[2];
    const float* Wq    = (const float*)d_in[3];
    const float* bq    = (const float*)d_in[4];
    const float* Wk    = (const float*)d_in[5];
    // d_in[6] = bk: uniform shift across keys -> cancels in softmax; unused
    const float* Wv    = (const float*)d_in[7];
    const float* bv    = (const float*)d_in[8];
    const float* Wo    = (const float*)d_in[9];
    const float* bo    = (const float*)d_in[10];
    const float* s1    = (const float*)d_in[11];
    const float* b1    = (const float*)d_in[12];
    const float* s2    = (const float*)d_in[13];
    const float* b2l   = (const float*)d_in[14];
    const float* W1    = (const float*)d_in[15];
    const float* b1f   = (const float*)d_in[16];
    const float* W2    = (const float*)d_in[17];
    const float* b2o   = (const float*)d_in[18];
    float* out = (float*)d_out;

    fused_kernel<<<NB, NT>>>(x, mask, token, Wq, bq, Wk, Wv, bv, Wo, bo,
                             s1, b1, s2, b2l, W1, b1f, W2, b2o, out);
}

// round 9
// speedup vs baseline: 1.9637x; 1.0759x over previous
#include <cuda_runtime.h>
#include <math.h>

#define SCALE 0.08838834764831845f  // 1/sqrt(128)
#define NB 256
#define NT 256

// ---------------- sync state (epoch-based; graph-replay safe) ----------------
__device__ unsigned g_count;
__device__ volatile unsigned g_release;
__device__ unsigned g_ctA;
__device__ volatile unsigned g_relA;
__device__ unsigned g_ctB;
__device__ volatile unsigned g_relB;
__device__ float g_dummy;

// ---------------- scratch ----------------
__device__ __align__(16) float g_hl[512];
__device__ __align__(16) float g_qpart[16][512];
__device__ __align__(16) float g_gs[4][512];
__device__ __align__(16) float2 g_stats[32][512];
__device__ __align__(16) float g_scores[32][512][4];
__device__ __align__(16) float g_cpart[64][12];
__device__ __align__(16) float g_C[12];
__device__ __align__(16) float g_pm[16][32][4];
__device__ __align__(16) float g_pse[16][32][4];
__device__ __align__(16) float g_pewb[16][32][4];
__device__ __align__(16) float g_ppart[16][32][4][512];
__device__ __align__(16) float g_ctxpart[32][32][512];
__device__ __align__(16) float g_wopart[32][32][512];
__device__ __align__(16) float g_h1[32][512];
__device__ __align__(16) float2 g_ln2[32];
__device__ __align__(16) float g_w1part[32][32][2048];
__device__ __align__(16) float g_w2part[128][32][512];

static __device__ __forceinline__ float wred(float v) {
#pragma unroll
    for (int o = 16; o; o >>= 1) v += __shfl_xor_sync(0xffffffffu, v, o);
    return v;
}

static __device__ __forceinline__ float geluf(float t) {
    float t3 = t * t * t;
    return 0.5f * t * (1.f + tanhf(0.7978845608028654f * (t + 0.044715f * t3)));
}

__device__ __forceinline__ void gridbar(unsigned base, unsigned idx) {
    __syncthreads();
    if (threadIdx.x == 0) {
        __threadfence();
        if (atomicAdd(&g_count, 1u) == NB - 1) {
            g_count = 0;
            __threadfence();
            g_release = base + idx;
        } else {
            while ((unsigned)(g_release - base) < idx) __nanosleep(32);
            __threadfence();
        }
    }
    __syncthreads();
}

__global__ void __launch_bounds__(NT, 2) fused_kernel(
    const float* __restrict__ x, const int* __restrict__ mask,
    const float* __restrict__ token,
    const float* __restrict__ Wq, const float* __restrict__ bq,
    const float* __restrict__ Wk,
    const float* __restrict__ Wv, const float* __restrict__ bv,
    const float* __restrict__ Wo, const float* __restrict__ bo,
    const float* __restrict__ s1, const float* __restrict__ b1,
    const float* __restrict__ s2, const float* __restrict__ b2l,
    const float* __restrict__ W1, const float* __restrict__ b1f,
    const float* __restrict__ W2, const float* __restrict__ b2o,
    float* __restrict__ out) {
    __shared__ float SM[3072];
    __shared__ unsigned s_base_sh;
    __shared__ int s_last;
    int tid = threadIdx.x;
    int bid = blockIdx.x;
    int wid = tid >> 5, lane = tid & 31;
    if (tid == 0) s_base_sh = g_release;
    __syncthreads();
    unsigned base = s_base_sh;

    // ================= PHASE I (flag-synced sub-stages) =================
    if (bid < 16) {
        // --- token LN + q partials ---
        float t0 = token[tid], t1 = token[tid + 256];
        float* red = SM;
        red[tid] = t0 + t1;
        __syncthreads();
#pragma unroll
        for (int o = 128; o; o >>= 1) {
            if (tid < o) red[tid] += red[tid + o];
            __syncthreads();
        }
        float mean = red[0] * (1.f / 512.f);
        __syncthreads();
        float d0 = t0 - mean, d1 = t1 - mean;
        red[tid] = d0 * d0 + d1 * d1;
        __syncthreads();
#pragma unroll
        for (int o = 128; o; o >>= 1) {
            if (tid < o) red[tid] += red[tid + o];
            __syncthreads();
        }
        float rstd = rsqrtf(red[0] * (1.f / 512.f) + 1e-5f);
        __syncthreads();
        float* shl = SM;
        float hl0 = d0 * rstd * s1[tid] + b1[tid];
        float hl1 = d1 * rstd * s1[tid + 256] + b1[tid + 256];
        shl[tid] = hl0;
        shl[tid + 256] = hl1;
        if (bid == 0) {
            g_hl[tid] = hl0;
            g_hl[tid + 256] = hl1;
        }
        __syncthreads();
        int j0 = bid * 32;
        float a0 = 0.f, a1 = 0.f;
#pragma unroll
        for (int j = 0; j < 32; j++) {
            float h = shl[j0 + j];
            a0 = fmaf(h, Wq[(size_t)(j0 + j) * 512 + tid], a0);
            a1 = fmaf(h, Wq[(size_t)(j0 + j) * 512 + tid + 256], a1);
        }
        g_qpart[bid][tid] = a0;
        g_qpart[bid][tid + 256] = a1;
        __threadfence();
        __syncthreads();
        if (tid == 0) {
            if (atomicAdd(&g_ctA, 1u) == 15) {
                g_ctA = 0;
                __threadfence();
                g_relA = base + 1;
            }
        }
        // --- prefetch weights into L2 ---
        {
            int pw = bid * 256 + tid;  // 0..20479 across blocks 0..79
            float acc = 0.f;
            const float4* a1p = (const float4*)Wv;
            const float4* a2p = (const float4*)Wo;
            const float4* a3p = (const float4*)W1;
            const float4* a4p = (const float4*)W2;
#pragma unroll 2
            for (int i = pw; i < 65536; i += 20480) acc += __ldg(a1p + i).x + __ldg(a2p + i).x;
#pragma unroll 4
            for (int i = pw; i < 262144; i += 20480) acc += __ldg(a3p + i).x + __ldg(a4p + i).x;
            if (acc == 1.2345e30f) g_dummy = acc;
        }
    } else if (bid < 80) {
        // --- wait q partials ---
        if (tid == 0) {
            while ((unsigned)(g_relA - base) < 1u) __nanosleep(32);
            __threadfence();
        }
        __syncthreads();
        // --- combine q; compute gs rows; C partials ---
        float* sq = SM;
        float q0 = bq[tid], q1 = bq[tid + 256];
#pragma unroll
        for (int s = 0; s < 16; s++) {
            q0 += g_qpart[s][tid];
            q1 += g_qpart[s][tid + 256];
        }
        sq[tid] = q0;
        sq[tid + 256] = q1;
        __syncthreads();
        int r = (bid - 16) * 8 + wid;
        const float4* wr = (const float4*)(Wk + (size_t)r * 512);
        const float4* q4 = (const float4*)sq;
        float dt[4];
#pragma unroll
        for (int t = 0; t < 4; t++) {
            float4 w = __ldg(wr + lane + 32 * t);
            float4 q = q4[lane + 32 * t];
            dt[t] = w.x * q.x + w.y * q.y + w.z * q.z + w.w * q.w;
        }
#pragma unroll
        for (int t = 0; t < 4; t++) dt[t] = wred(dt[t]);
        float* cred = SM + 512;  // [8][12]
        if (lane == 0) {
            float sr = s1[r], br = b1[r], hr = g_hl[r];
#pragma unroll
            for (int t = 0; t < 4; t++) {
                g_gs[t][r] = dt[t] * sr;
                cred[wid * 12 + t] = sr * dt[t];
                cred[wid * 12 + 4 + t] = br * dt[t];
                cred[wid * 12 + 8 + t] = hr * dt[t];
            }
        }
        __syncthreads();
        if (tid < 12) {
            float c = 0.f;
#pragma unroll
            for (int w = 0; w < 8; w++) c += cred[w * 12 + tid];
            g_cpart[bid - 16][tid] = c;
        }
        __threadfence();
        __syncthreads();
        if (tid == 0) s_last = (atomicAdd(&g_ctB, 1u) == 63) ? 1 : 0;
        __syncthreads();
        if (s_last) {
            if (tid < 12) {
                float c = 0.f;
#pragma unroll
                for (int j = 0; j < 64; j++) c += g_cpart[j][tid];
                g_C[tid] = c;
            }
            __threadfence();
            __syncthreads();
            if (tid == 0) {
                g_ctB = 0;
                __threadfence();
                g_relB = base + 1;
            }
        }
        // --- prefetch weights ---
        {
            int pw = bid * 256 + tid;
            float acc = 0.f;
            const float4* a1p = (const float4*)Wv;
            const float4* a2p = (const float4*)Wo;
            const float4* a3p = (const float4*)W1;
            const float4* a4p = (const float4*)W2;
#pragma unroll 2
            for (int i = pw; i < 65536; i += 20480) acc += __ldg(a1p + i).x + __ldg(a2p + i).x;
#pragma unroll 4
            for (int i = pw; i < 262144; i += 20480) acc += __ldg(a3p + i).x + __ldg(a4p + i).x;
            if (acc == 1.2345e30f) g_dummy = acc;
        }
    } else {
        // --- wait g/C ready ---
        if (tid == 0) {
            while ((unsigned)(g_relB - base) < 1u) __nanosleep(32);
            __threadfence();
        }
        __syncthreads();
        for (int i = tid; i < 2048; i += NT) SM[i] = ((const float*)g_gs)[i];
        if (tid < 12) SM[2048 + tid] = g_C[tid];
        __syncthreads();
        const float4* sgs4 = (const float4*)SM;
        float C1[4], C2[4];
#pragma unroll
        for (int h = 0; h < 4; h++) {
            C1[h] = SM[2048 + h];
            C2[h] = SM[2052 + h];
        }
        // --- stream x: stats + scores, strided pairs ---
        int sw = (bid - 80) * 8 + wid;  // 0..1407
#pragma unroll 1
        for (int it = 0; it < 6; it++) {
            int r = 2 * sw + it * 2816;
            if (r >= 16384) break;
            int bA = r >> 9, kA = r & 511;
            int bB = (r + 1) >> 9, kB = (r + 1) & 511;
            bool vA = kA < __ldg(&mask[bA]);
            bool vB = kB < __ldg(&mask[bB]);
            if (!vA && !vB) continue;
            float4 xa[4], xc[4];
#pragma unroll
            for (int t = 0; t < 4; t++) xa[t] = make_float4(0.f, 0.f, 0.f, 0.f);
#pragma unroll
            for (int t = 0; t < 4; t++) xc[t] = make_float4(0.f, 0.f, 0.f, 0.f);
            if (vA) {
                const float4* xr = (const float4*)(x + (size_t)r * 512);
#pragma unroll
                for (int t = 0; t < 4; t++) xa[t] = __ldg(xr + lane + 32 * t);
            }
            if (vB) {
                const float4* xr = (const float4*)(x + (size_t)(r + 1) * 512);
#pragma unroll
                for (int t = 0; t < 4; t++) xc[t] = __ldg(xr + lane + 32 * t);
            }
            float ssA = 0.f, smA = 0.f, ssB = 0.f, smB = 0.f;
#pragma unroll
            for (int t = 0; t < 4; t++) {
                ssA += xa[t].x * xa[t].x + xa[t].y * xa[t].y + xa[t].z * xa[t].z + xa[t].w * xa[t].w;
                smA += xa[t].x + xa[t].y + xa[t].z + xa[t].w;
                ssB += xc[t].x * xc[t].x + xc[t].y * xc[t].y + xc[t].z * xc[t].z + xc[t].w * xc[t].w;
                smB += xc[t].x + xc[t].y + xc[t].z + xc[t].w;
            }
            float dA[4], dB[4];
#pragma unroll
            for (int h = 0; h < 4; h++) {
                float aA = 0.f, aB = 0.f;
#pragma unroll
                for (int t = 0; t < 4; t++) {
                    float4 g = sgs4[h * 128 + lane + 32 * t];
                    aA += xa[t].x * g.x + xa[t].y * g.y + xa[t].z * g.z + xa[t].w * g.w;
                    aB += xc[t].x * g.x + xc[t].y * g.y + xc[t].z * g.z + xc[t].w * g.w;
                }
                dA[h] = wred(aA);
                dB[h] = wred(aB);
            }
            ssA = wred(ssA);
            smA = wred(smA);
            ssB = wred(ssB);
            smB = wred(smB);
            if (lane == 0) {
                if (vA) {
                    float inv = 1.f / fmaxf(sqrtf(ssA), 1e-12f);
                    float m = smA * inv * (1.f / 512.f);
                    float v = ssA * inv * inv * (1.f / 512.f) - m * m;
                    float rs = rsqrtf(v + 1e-5f);
                    float al = inv * rs, be = -m * rs;
                    g_stats[bA][kA] = make_float2(al, be);
                    float4 sc;
                    sc.x = SCALE * (al * dA[0] + be * C1[0] + C2[0]);
                    sc.y = SCALE * (al * dA[1] + be * C1[1] + C2[1]);
                    sc.z = SCALE * (al * dA[2] + be * C1[2] + C2[2]);
                    sc.w = SCALE * (al * dA[3] + be * C1[3] + C2[3]);
                    *(float4*)&g_scores[bA][kA][0] = sc;
                }
                if (vB) {
                    float inv = 1.f / fmaxf(sqrtf(ssB), 1e-12f);
                    float m = smB * inv * (1.f / 512.f);
                    float v = ssB * inv * inv * (1.f / 512.f) - m * m;
                    float rs = rsqrtf(v + 1e-5f);
                    float al = inv * rs, be = -m * rs;
                    g_stats[bB][kB] = make_float2(al, be);
                    float4 sc;
                    sc.x = SCALE * (al * dB[0] + be * C1[0] + C2[0]);
                    sc.y = SCALE * (al * dB[1] + be * C1[1] + C2[1]);
                    sc.z = SCALE * (al * dB[2] + be * C1[2] + C2[2]);
                    sc.w = SCALE * (al * dB[3] + be * C1[3] + C2[3]);
                    *(float4*)&g_scores[bB][kB][0] = sc;
                }
            }
        }
    }
    gridbar(base, 1);

    // ============ PHASE II: split softmax + A accumulate (512 vblocks) ============
    {
        int half = tid >> 7, t128 = tid & 127;
        float* sS = SM + half * 448;  // sc[128], al[32], be[32], w[128], e[128]
        int vb = bid * 2 + half;      // 0..511
        int ks = vb & 15, b = vb >> 4;
        int L = __ldg(&mask[b]);
        int k0 = ks * 32;
        {
            int kk = k0 + (t128 >> 2);
            sS[t128] = (kk < L) ? ((const float*)g_scores)[b * 2048 + kk * 4 + (t128 & 3)] : -1e30f;
            if (t128 < 32) {
                float2 ab = (k0 + t128 < L) ? g_stats[b][k0 + t128] : make_float2(0.f, 0.f);
                sS[128 + t128] = ab.x;
                sS[160 + t128] = ab.y;
            }
        }
        __syncthreads();
        {
            int k = t128 >> 2, h = t128 & 3;
            float m = -1e30f;
#pragma unroll 8
            for (int j = 0; j < 32; j++) m = fmaxf(m, sS[j * 4 + h]);
            float e = __expf(sS[k * 4 + h] - m);
            sS[320 + k * 4 + h] = e;
            sS[192 + k * 4 + h] = e * sS[128 + k];
            if (k == 0) g_pm[ks][b][h] = m;
        }
        __syncthreads();
        int kv = L - k0;
        kv = kv < 0 ? 0 : (kv > 32 ? 32 : kv);
        float4 A0 = {0, 0, 0, 0}, A1 = A0, A2 = A0, A3 = A0;
        const float4* xb4 = (const float4*)(x + ((size_t)b * 512 + k0) * 512);
#pragma unroll 4
        for (int k = 0; k < kv; k++) {
            float4 w4 = *(const float4*)&sS[192 + k * 4];
            float4 xv = __ldg(xb4 + (size_t)k * 128 + t128);
            A0.x = fmaf(w4.x, xv.x, A0.x); A0.y = fmaf(w4.x, xv.y, A0.y);
            A0.z = fmaf(w4.x, xv.z, A0.z); A0.w = fmaf(w4.x, xv.w, A0.w);
            A1.x = fmaf(w4.y, xv.x, A1.x); A1.y = fmaf(w4.y, xv.y, A1.y);
            A1.z = fmaf(w4.y, xv.z, A1.z); A1.w = fmaf(w4.y, xv.w, A1.w);
            A2.x = fmaf(w4.z, xv.x, A2.x); A2.y = fmaf(w4.z, xv.y, A2.y);
            A2.z = fmaf(w4.z, xv.z, A2.z); A2.w = fmaf(w4.z, xv.w, A2.w);
            A3.x = fmaf(w4.w, xv.x, A3.x); A3.y = fmaf(w4.w, xv.y, A3.y);
            A3.z = fmaf(w4.w, xv.z, A3.z); A3.w = fmaf(w4.w, xv.w, A3.w);
        }
        int i = t128 * 4;
        *(float4*)&g_ppart[ks][b][0][i] = A0;
        *(float4*)&g_ppart[ks][b][1][i] = A1;
        *(float4*)&g_ppart[ks][b][2][i] = A2;
        *(float4*)&g_ppart[ks][b][3][i] = A3;
        if (t128 < 4) {
            float se = 0.f, ewb = 0.f;
#pragma unroll 8
            for (int k = 0; k < 32; k++) {
                float e = sS[320 + k * 4 + t128];
                se += e;
                ewb += e * sS[160 + k];
            }
            g_pse[ks][b][t128] = se;
            g_pewb[ks][b][t128] = ewb;
        }
    }
    gridbar(base, 2);

    // ============ T1': combine scalars + rescale + p @ Wv (512 vblocks) ============
    {
        int half = tid >> 7, t128 = tid & 127;
        int vb = bid * 2 + half;
        int bh = vb & 3, hh = (vb >> 2) & 3, iy = vb >> 4;  // iy 0..31
        int i0 = iy * 16, f = hh * 128 + t128;
        float* sb = SM + half * 160;
        float* sp = SM + 320 + half * 128;
        if (t128 < 8) {
            int gb = bh * 8 + t128;
            float scls = SCALE * g_C[8 + hh];
            float ms[16];
            float M = scls;
#pragma unroll
            for (int s = 0; s < 16; s++) {
                ms[s] = g_pm[s][gb][hh];
                M = fmaxf(M, ms[s]);
            }
            float Se = 0.f, Ewb = 0.f;
#pragma unroll
            for (int s = 0; s < 16; s++) {
                float fs = __expf(ms[s] - M);
                sb[t128 * 16 + s] = fs;
                Se += fs * g_pse[s][gb][hh];
                Ewb += fs * g_pewb[s][gb][hh];
            }
            float ecls = __expf(scls - M);
            sb[128 + t128] = 1.f / (Se + ecls);
            sb[136 + t128] = Se;
            sb[144 + t128] = Ewb;
            sb[152 + t128] = ecls;
        }
        __syncthreads();
        {
            int bl = t128 >> 4, ii = t128 & 15;
            int gb = bh * 8 + bl;
            int i = i0 + ii;
            float A = 0.f;
#pragma unroll
            for (int s = 0; s < 16; s++) A = fmaf(sb[bl * 16 + s], g_ppart[s][gb][hh][i], A);
            sp[t128] = sb[128 + bl] *
                       (s1[i] * (A + sb[144 + bl]) + b1[i] * sb[136 + bl] + sb[152 + bl] * g_hl[i]);
        }
        __syncthreads();
        float acc[8];
#pragma unroll
        for (int bl = 0; bl < 8; bl++) acc[bl] = 0.f;
#pragma unroll
        for (int ii = 0; ii < 16; ii += 4) {
            int i = i0 + ii;
            float w0 = Wv[(size_t)i * 512 + f];
            float w1 = Wv[(size_t)(i + 1) * 512 + f];
            float w2 = Wv[(size_t)(i + 2) * 512 + f];
            float w3 = Wv[(size_t)(i + 3) * 512 + f];
#pragma unroll
            for (int bl = 0; bl < 8; bl++) {
                float4 p = *(const float4*)&sp[bl * 16 + ii];
                acc[bl] = fmaf(p.x, w0, fmaf(p.y, w1, fmaf(p.z, w2, fmaf(p.w, w3, acc[bl]))));
            }
        }
#pragma unroll
        for (int bl = 0; bl < 8; bl++) g_ctxpart[iy][bh * 8 + bl][f] = acc[bl];
    }
    gridbar(base, 3);

    // ============ T2: o partials = (ctx+bv) @ Wo (512 vblocks) ============
    {
        int half = tid >> 7, t128 = tid & 127;
        int vb = bid * 2 + half;
        int bh = vb & 3, cx = (vb >> 2) & 3, iy = vb >> 4;
        int i0 = iy * 16, f = cx * 128 + t128;
        float* sc = SM + half * 128;
        {
            int bl = t128 >> 4, ii = t128 & 15;
            int gb = bh * 8 + bl;
            int i = i0 + ii;
            float v = bv[i];
#pragma unroll
            for (int s = 0; s < 32; s++) v += g_ctxpart[s][gb][i];
            sc[t128] = v;
        }
        __syncthreads();
        float acc[8];
#pragma unroll
        for (int bl = 0; bl < 8; bl++) acc[bl] = 0.f;
#pragma unroll
        for (int ii = 0; ii < 16; ii += 4) {
            int i = i0 + ii;
            float w0 = Wo[(size_t)i * 512 + f];
            float w1 = Wo[(size_t)(i + 1) * 512 + f];
            float w2 = Wo[(size_t)(i + 2) * 512 + f];
            float w3 = Wo[(size_t)(i + 3) * 512 + f];
#pragma unroll
            for (int bl = 0; bl < 8; bl++) {
                float4 p = *(const float4*)&sc[bl * 16 + ii];
                acc[bl] = fmaf(p.x, w0, fmaf(p.y, w1, fmaf(p.z, w2, fmaf(p.w, w3, acc[bl]))));
            }
        }
#pragma unroll
        for (int bl = 0; bl < 8; bl++) g_wopart[iy][bh * 8 + bl][f] = acc[bl];
    }
    gridbar(base, 4);

    // ============ T3: h1 = token + o + bo; LN2 stats ============
    if (bid < 32) {
        int b = bid;
        float sum = 0.f, ssq = 0.f;
#pragma unroll
        for (int t = 0; t < 2; t++) {
            int c = tid + 256 * t;
            float v = token[c] + bo[c];
#pragma unroll
            for (int s = 0; s < 32; s++) v += g_wopart[s][b][c];
            g_h1[b][c] = v;
            sum += v;
            ssq += v * v;
        }
        float* r2 = SM;
        r2[tid * 2] = sum;
        r2[tid * 2 + 1] = ssq;
        __syncthreads();
        for (int o = 128; o; o >>= 1) {
            if (tid < o) {
                r2[tid * 2] += r2[(tid + o) * 2];
                r2[tid * 2 + 1] += r2[(tid + o) * 2 + 1];
            }
            __syncthreads();
        }
        if (tid == 0) {
            float m = r2[0] * (1.f / 512.f);
            float var = r2[1] * (1.f / 512.f) - m * m;
            g_ln2[b] = make_float2(m, rsqrtf(var + 1e-5f));
        }
    }
    gridbar(base, 5);

    // ============ T4: W1 partials (h2 @ W1), 512 vblocks ============
    {
        int half = tid >> 7, t128 = tid & 127;
        int vb = bid * 2 + half;
        int fx = vb & 15, iy = vb >> 4;  // iy 0..31
        int i0 = iy * 16, f = fx * 128 + t128;
        float* sh2 = SM + half * 512;
        for (int idx = t128; idx < 512; idx += 128) {
            int b = idx >> 4, ii = idx & 15, i = i0 + ii;
            float2 mr = g_ln2[b];
            sh2[b * 16 + ii] = (g_h1[b][i] - mr.x) * mr.y * s2[i] + b2l[i];
        }
        __syncthreads();
        float acc[32];
#pragma unroll
        for (int b = 0; b < 32; b++) acc[b] = 0.f;
#pragma unroll
        for (int ii = 0; ii < 16; ii += 4) {
            int i = i0 + ii;
            float w0 = W1[(size_t)i * 2048 + f];
            float w1 = W1[(size_t)(i + 1) * 2048 + f];
            float w2 = W1[(size_t)(i + 2) * 2048 + f];
            float w3 = W1[(size_t)(i + 3) * 2048 + f];
#pragma unroll
            for (int b = 0; b < 32; b++) {
                float4 p = *(const float4*)&sh2[b * 16 + ii];
                acc[b] = fmaf(p.x, w0, fmaf(p.y, w1, fmaf(p.z, w2, fmaf(p.w, w3, acc[b]))));
            }
        }
#pragma unroll
        for (int b = 0; b < 32; b++) g_w1part[iy][b][f] = acc[b];
    }
    gridbar(base, 6);

    // ============ T5: gelu + W2 partials, 512 vblocks ============
    {
        int half = tid >> 7, t128 = tid & 127;
        int vb = bid * 2 + half;
        int fx = vb & 3, iy = vb >> 2;  // iy 0..127
        int i0 = iy * 16, f = fx * 128 + t128;
        float* su = SM + half * 512;
        for (int idx = t128; idx < 512; idx += 128) {
            int b = idx >> 4, ii = idx & 15, i = i0 + ii;
            float u = b1f[i];
#pragma unroll
            for (int s = 0; s < 32; s++) u += g_w1part[s][b][i];
            su[b * 16 + ii] = geluf(u);
        }
        __syncthreads();
        float acc[32];
#pragma unroll
        for (int b = 0; b < 32; b++) acc[b] = 0.f;
#pragma unroll
        for (int ii = 0; ii < 16; ii += 4) {
            int i = i0 + ii;
            float w0 = W2[(size_t)i * 512 + f];
            float w1 = W2[(size_t)(i + 1) * 512 + f];
            float w2 = W2[(size_t)(i + 2) * 512 + f];
            float w3 = W2[(size_t)(i + 3) * 512 + f];
#pragma unroll
            for (int b = 0; b < 32; b++) {
                float4 p = *(const float4*)&su[b * 16 + ii];
                acc[b] = fmaf(p.x, w0, fmaf(p.y, w1, fmaf(p.z, w2, fmaf(p.w, w3, acc[b]))));
            }
        }
#pragma unroll
        for (int b = 0; b < 32; b++) g_w2part[iy][b][f] = acc[b];
    }
    gridbar(base, 7);

    // ============ OUT ============
    if (bid < 32) {
        int b = bid;
        int c0 = tid * 2;
        float2 acc;
        acc.x = g_h1[b][c0] + b2o[c0];
        acc.y = g_h1[b][c0 + 1] + b2o[c0 + 1];
#pragma unroll 16
        for (int s = 0; s < 128; s++) {
            float2 w = *(const float2*)&g_w2part[s][b][c0];
            acc.x += w.x;
            acc.y += w.y;
        }
        *(float2*)&out[b * 512 + c0] = acc;
    }
}

extern "C" void kernel_launch(void* const* d_in, const int* in_sizes, int n_in,
                              void* d_out, int out_size) {
    const float* x     = (const float*)d_in[0];
    const int*   mask  = (const int*)d_in[1];
    const float* token = (const float*)d_in[2];
    const float* Wq    = (const float*)d_in[3];
    const float* bq    = (const float*)d_in[4];
    const float* Wk    = (const float*)d_in[5];
    // d_in[6] = bk: uniform shift across keys -> cancels in softmax; unused
    const float* Wv    = (const float*)d_in[7];
    const float* bv    = (const float*)d_in[8];
    const float* Wo    = (const float*)d_in[9];
    const float* bo    = (const float*)d_in[10];
    const float* s1    = (const float*)d_in[11];
    const float* b1    = (const float*)d_in[12];
    const float* s2    = (const float*)d_in[13];
    const float* b2l   = (const float*)d_in[14];
    const float* W1    = (const float*)d_in[15];
    const float* b1f   = (const float*)d_in[16];
    const float* W2    = (const float*)d_in[17];
    const float* b2o   = (const float*)d_in[18];
    float* out = (float*)d_out;

    fused_kernel<<<NB, NT>>>(x, mask, token, Wq, bq, Wk, Wv, bv, Wo, bo,
                             s1, b1, s2, b2l, W1, b1f, W2, b2o, out);
}

// round 10
// speedup vs baseline: 2.0376x; 1.0376x over previous
#include <cuda_runtime.h>
#include <math.h>

#define SCALE 0.08838834764831845f  // 1/sqrt(128)
#define NB 256
#define NT 256

// ---------------- sync state (epoch-based; graph-replay safe) ----------------
__device__ unsigned g_count;
__device__ volatile unsigned g_release;
__device__ unsigned g_ctA;
__device__ volatile unsigned g_relA;
__device__ unsigned g_ctB;
__device__ volatile unsigned g_relB;
__device__ unsigned g_task;
__device__ float g_dummy;

// ---------------- scratch ----------------
__device__ __align__(16) float g_hl[512];
__device__ __align__(16) float g_qpart[16][512];
__device__ __align__(16) float g_gs[4][512];
__device__ __align__(16) float g_cpart[64][12];
__device__ __align__(16) float g_C[12];
__device__ __align__(16) float g_pm[16][32][4];
__device__ __align__(16) float g_pse[16][32][4];
__device__ __align__(16) float g_pewb[16][32][4];
__device__ __align__(16) float g_ppart[16][32][4][512];
__device__ __align__(16) float g_ctxpart[32][32][512];
__device__ __align__(16) float g_wopart[32][32][512];
__device__ __align__(16) float g_h1[32][512];
__device__ __align__(16) float2 g_ln2[32];
__device__ __align__(16) float g_w1part[32][32][2048];
__device__ __align__(16) float g_w2part[128][32][512];

static __device__ __forceinline__ float wred(float v) {
#pragma unroll
    for (int o = 16; o; o >>= 1) v += __shfl_xor_sync(0xffffffffu, v, o);
    return v;
}

static __device__ __forceinline__ float geluf(float t) {
    float t3 = t * t * t;
    return 0.5f * t * (1.f + tanhf(0.7978845608028654f * (t + 0.044715f * t3)));
}

__device__ __forceinline__ void gridbar(unsigned base, unsigned idx) {
    __syncthreads();
    if (threadIdx.x == 0) {
        __threadfence();
        if (atomicAdd(&g_count, 1u) == NB - 1) {
            g_count = 0;
            __threadfence();
            g_release = base + idx;
        } else {
            while ((unsigned)(g_release - base) < idx) __nanosleep(32);
            __threadfence();
        }
    }
    __syncthreads();
}

__global__ void __launch_bounds__(NT, 2) fused_kernel(
    const float* __restrict__ x, const int* __restrict__ mask,
    const float* __restrict__ token,
    const float* __restrict__ Wq, const float* __restrict__ bq,
    const float* __restrict__ Wk,
    const float* __restrict__ Wv, const float* __restrict__ bv,
    const float* __restrict__ Wo, const float* __restrict__ bo,
    const float* __restrict__ s1, const float* __restrict__ b1,
    const float* __restrict__ s2, const float* __restrict__ b2l,
    const float* __restrict__ W1, const float* __restrict__ b1f,
    const float* __restrict__ W2, const float* __restrict__ b2o,
    float* __restrict__ out) {
    __shared__ float SM[3072];
    __shared__ unsigned s_base_sh;
    __shared__ int s_last;
    __shared__ int s_task[2];
    int tid = threadIdx.x;
    int bid = blockIdx.x;
    int wid = tid >> 5, lane = tid & 31;
    if (tid == 0) s_base_sh = g_release;
    __syncthreads();
    unsigned base = s_base_sh;

    // ================= PHASE I: prologue (flag-synced) + split task loop =================
    if (bid < 16) {
        // --- token LN + q partials ---
        float t0 = token[tid], t1 = token[tid + 256];
        float* red = SM;
        red[tid] = t0 + t1;
        __syncthreads();
#pragma unroll
        for (int o = 128; o; o >>= 1) {
            if (tid < o) red[tid] += red[tid + o];
            __syncthreads();
        }
        float mean = red[0] * (1.f / 512.f);
        __syncthreads();
        float d0 = t0 - mean, d1 = t1 - mean;
        red[tid] = d0 * d0 + d1 * d1;
        __syncthreads();
#pragma unroll
        for (int o = 128; o; o >>= 1) {
            if (tid < o) red[tid] += red[tid + o];
            __syncthreads();
        }
        float rstd = rsqrtf(red[0] * (1.f / 512.f) + 1e-5f);
        __syncthreads();
        float* shl = SM;
        float hl0 = d0 * rstd * s1[tid] + b1[tid];
        float hl1 = d1 * rstd * s1[tid + 256] + b1[tid + 256];
        shl[tid] = hl0;
        shl[tid + 256] = hl1;
        if (bid == 0) {
            g_hl[tid] = hl0;
            g_hl[tid + 256] = hl1;
        }
        __syncthreads();
        int j0 = bid * 32;
        float a0 = 0.f, a1 = 0.f;
#pragma unroll
        for (int j = 0; j < 32; j++) {
            float h = shl[j0 + j];
            a0 = fmaf(h, Wq[(size_t)(j0 + j) * 512 + tid], a0);
            a1 = fmaf(h, Wq[(size_t)(j0 + j) * 512 + tid + 256], a1);
        }
        g_qpart[bid][tid] = a0;
        g_qpart[bid][tid + 256] = a1;
        __threadfence();
        __syncthreads();
        if (tid == 0) {
            if (atomicAdd(&g_ctA, 1u) == 15) {
                g_ctA = 0;
                __threadfence();
                g_relA = base + 1;
            }
        }
        // --- prefetch weights into L2 ---
        {
            int pw = bid * 256 + tid;
            float acc = 0.f;
            const float4* a1p = (const float4*)Wv;
            const float4* a2p = (const float4*)Wo;
            const float4* a3p = (const float4*)W1;
            const float4* a4p = (const float4*)W2;
#pragma unroll 2
            for (int i = pw; i < 65536; i += 20480) acc += __ldg(a1p + i).x + __ldg(a2p + i).x;
#pragma unroll 4
            for (int i = pw; i < 262144; i += 20480) acc += __ldg(a3p + i).x + __ldg(a4p + i).x;
            if (acc == 1.2345e30f) g_dummy = acc;
        }
    } else if (bid < 80) {
        // --- wait q partials ---
        if (tid == 0) {
            while ((unsigned)(g_relA - base) < 1u) __nanosleep(32);
            __threadfence();
        }
        __syncthreads();
        // --- combine q; gs rows; C partials ---
        float* sq = SM;
        float q0 = bq[tid], q1 = bq[tid + 256];
#pragma unroll
        for (int s = 0; s < 16; s++) {
            q0 += g_qpart[s][tid];
            q1 += g_qpart[s][tid + 256];
        }
        sq[tid] = q0;
        sq[tid + 256] = q1;
        __syncthreads();
        int r = (bid - 16) * 8 + wid;
        const float4* wr = (const float4*)(Wk + (size_t)r * 512);
        const float4* q4 = (const float4*)sq;
        float dt[4];
#pragma unroll
        for (int t = 0; t < 4; t++) {
            float4 w = __ldg(wr + lane + 32 * t);
            float4 q = q4[lane + 32 * t];
            dt[t] = w.x * q.x + w.y * q.y + w.z * q.z + w.w * q.w;
        }
#pragma unroll
        for (int t = 0; t < 4; t++) dt[t] = wred(dt[t]);
        float* cred = SM + 512;  // [8][12]
        if (lane == 0) {
            float sr = s1[r], br = b1[r], hr = g_hl[r];
#pragma unroll
            for (int t = 0; t < 4; t++) {
                g_gs[t][r] = dt[t] * sr;
                cred[wid * 12 + t] = sr * dt[t];
                cred[wid * 12 + 4 + t] = br * dt[t];
                cred[wid * 12 + 8 + t] = hr * dt[t];
            }
        }
        __syncthreads();
        if (tid < 12) {
            float c = 0.f;
#pragma unroll
            for (int w = 0; w < 8; w++) c += cred[w * 12 + tid];
            g_cpart[bid - 16][tid] = c;
        }
        __threadfence();
        __syncthreads();
        if (tid == 0) s_last = (atomicAdd(&g_ctB, 1u) == 63) ? 1 : 0;
        __syncthreads();
        if (s_last) {
            if (tid < 12) {
                float c = 0.f;
#pragma unroll
                for (int j = 0; j < 64; j++) c += g_cpart[j][tid];
                g_C[tid] = c;
            }
            __threadfence();
            __syncthreads();
            if (tid == 0) {
                g_ctB = 0;
                __threadfence();
                g_relB = base + 1;
            }
        }
        // --- prefetch weights ---
        {
            int pw = bid * 256 + tid;
            float acc = 0.f;
            const float4* a1p = (const float4*)Wv;
            const float4* a2p = (const float4*)Wo;
            const float4* a3p = (const float4*)W1;
            const float4* a4p = (const float4*)W2;
#pragma unroll 2
            for (int i = pw; i < 65536; i += 20480) acc += __ldg(a1p + i).x + __ldg(a2p + i).x;
#pragma unroll 4
            for (int i = pw; i < 262144; i += 20480) acc += __ldg(a3p + i).x + __ldg(a4p + i).x;
            if (acc == 1.2345e30f) g_dummy = acc;
        }
    }
    // --- all blocks: wait gs/C ready ---
    if (tid == 0) {
        while ((unsigned)(g_relB - base) < 1u) __nanosleep(32);
        __threadfence();
    }
    __syncthreads();
    // --- load gs + C to smem ---
    for (int i = tid; i < 2048; i += NT) SM[i] = ((const float*)g_gs)[i];
    if (tid < 12) SM[2048 + tid] = g_C[tid];
    __syncthreads();
    {
        const float4* sgs4 = (const float4*)SM;
        float C1[4], C2[4];
#pragma unroll
        for (int h = 0; h < 4; h++) {
            C1[h] = SM[2048 + h];
            C2[h] = SM[2052 + h];
        }
        int half = tid >> 7, t128 = tid & 127, w = t128 >> 5;
        float* sS = SM + 2064 + half * 464;  // sc[128], al[32], be[32], w[128], e[128]
        int nbar = 1 + half;
        // ---- task loop: each task = one (b, ks) split, processed end-to-end ----
        while (true) {
            if (t128 == 0) s_task[half] = (int)atomicAdd(&g_task, 1u);
            asm volatile("bar.sync %0, 128;" ::"r"(nbar));
            int t = s_task[half];
            if (t >= 512) break;
            int ks = t & 15, b = t >> 4;
            int L = __ldg(&mask[b]);
            int k0 = ks * 32;
            // --- score pass: each warp 8 rows, 2-batched; stats inline ---
#pragma unroll 1
            for (int it = 0; it < 4; it++) {
                int kl = w * 8 + it * 2;
                int kg = k0 + kl;
                bool v0 = kg < L, v1 = kg + 1 < L;
                const float4* xr0 = (const float4*)(x + ((size_t)b * 512 + kg) * 512);
                float4 xa[4], xc[4];
#pragma unroll
                for (int tt = 0; tt < 4; tt++) xa[tt] = make_float4(0.f, 0.f, 0.f, 0.f);
#pragma unroll
                for (int tt = 0; tt < 4; tt++) xc[tt] = make_float4(0.f, 0.f, 0.f, 0.f);
                if (v0) {
#pragma unroll
                    for (int tt = 0; tt < 4; tt++) xa[tt] = __ldg(xr0 + lane + 32 * tt);
                }
                if (v1) {
#pragma unroll
                    for (int tt = 0; tt < 4; tt++) xc[tt] = __ldg(xr0 + 128 + lane + 32 * tt);
                }
                float ssA = 0.f, smA = 0.f, ssB = 0.f, smB = 0.f;
#pragma unroll
                for (int tt = 0; tt < 4; tt++) {
                    ssA += xa[tt].x * xa[tt].x + xa[tt].y * xa[tt].y + xa[tt].z * xa[tt].z +
                           xa[tt].w * xa[tt].w;
                    smA += xa[tt].x + xa[tt].y + xa[tt].z + xa[tt].w;
                    ssB += xc[tt].x * xc[tt].x + xc[tt].y * xc[tt].y + xc[tt].z * xc[tt].z +
                           xc[tt].w * xc[tt].w;
                    smB += xc[tt].x + xc[tt].y + xc[tt].z + xc[tt].w;
                }
                float dA[4], dB[4];
#pragma unroll
                for (int h = 0; h < 4; h++) {
                    float aA = 0.f, aB = 0.f;
#pragma unroll
                    for (int tt = 0; tt < 4; tt++) {
                        float4 g = sgs4[h * 128 + lane + 32 * tt];
                        aA += xa[tt].x * g.x + xa[tt].y * g.y + xa[tt].z * g.z + xa[tt].w * g.w;
                        aB += xc[tt].x * g.x + xc[tt].y * g.y + xc[tt].z * g.z + xc[tt].w * g.w;
                    }
                    dA[h] = wred(aA);
                    dB[h] = wred(aB);
                }
                ssA = wred(ssA);
                smA = wred(smA);
                ssB = wred(ssB);
                smB = wred(smB);
                if (lane == 0) {
                    float al0 = 0.f, be0 = 0.f, al1 = 0.f, be1 = 0.f;
                    if (v0) {
                        float inv = 1.f / fmaxf(sqrtf(ssA), 1e-12f);
                        float m = smA * inv * (1.f / 512.f);
                        float v = ssA * inv * inv * (1.f / 512.f) - m * m;
                        float rs = rsqrtf(v + 1e-5f);
                        al0 = inv * rs;
                        be0 = -m * rs;
                    }
                    if (v1) {
                        float inv = 1.f / fmaxf(sqrtf(ssB), 1e-12f);
                        float m = smB * inv * (1.f / 512.f);
                        float v = ssB * inv * inv * (1.f / 512.f) - m * m;
                        float rs = rsqrtf(v + 1e-5f);
                        al1 = inv * rs;
                        be1 = -m * rs;
                    }
#pragma unroll
                    for (int h = 0; h < 4; h++) {
                        sS[kl * 4 + h] =
                            v0 ? SCALE * (al0 * dA[h] + be0 * C1[h] + C2[h]) : -1e30f;
                        sS[(kl + 1) * 4 + h] =
                            v1 ? SCALE * (al1 * dB[h] + be1 * C1[h] + C2[h]) : -1e30f;
                    }
                    sS[128 + kl] = al0;
                    sS[128 + kl + 1] = al1;
                    sS[160 + kl] = be0;
                    sS[160 + kl + 1] = be1;
                }
            }
            asm volatile("bar.sync %0, 128;" ::"r"(nbar));
            // --- e/w compute: thread (k,h) ---
            {
                int k = t128 >> 2, h = t128 & 3;
                float m = -1e30f;
#pragma unroll 8
                for (int j = 0; j < 32; j++) m = fmaxf(m, sS[j * 4 + h]);
                float e = __expf(sS[k * 4 + h] - m);
                sS[320 + k * 4 + h] = e;
                sS[192 + k * 4 + h] = e * sS[128 + k];
                if (k == 0) g_pm[ks][b][h] = m;
            }
            asm volatile("bar.sync %0, 128;" ::"r"(nbar));
            // --- A accumulate (x rows warm in L1) ---
            int kv = L - k0;
            kv = kv < 0 ? 0 : (kv > 32 ? 32 : kv);
            float4 A0 = {0, 0, 0, 0}, A1 = A0, A2 = A0, A3 = A0;
            const float4* xb4 = (const float4*)(x + ((size_t)b * 512 + k0) * 512);
#pragma unroll 4
            for (int k = 0; k < kv; k++) {
                float4 w4 = *(const float4*)&sS[192 + k * 4];
                float4 xv = __ldg(xb4 + (size_t)k * 128 + t128);
                A0.x = fmaf(w4.x, xv.x, A0.x); A0.y = fmaf(w4.x, xv.y, A0.y);
                A0.z = fmaf(w4.x, xv.z, A0.z); A0.w = fmaf(w4.x, xv.w, A0.w);
                A1.x = fmaf(w4.y, xv.x, A1.x); A1.y = fmaf(w4.y, xv.y, A1.y);
                A1.z = fmaf(w4.y, xv.z, A1.z); A1.w = fmaf(w4.y, xv.w, A1.w);
                A2.x = fmaf(w4.z, xv.x, A2.x); A2.y = fmaf(w4.z, xv.y, A2.y);
                A2.z = fmaf(w4.z, xv.z, A2.z); A2.w = fmaf(w4.z, xv.w, A2.w);
                A3.x = fmaf(w4.w, xv.x, A3.x); A3.y = fmaf(w4.w, xv.y, A3.y);
                A3.z = fmaf(w4.w, xv.z, A3.z); A3.w = fmaf(w4.w, xv.w, A3.w);
            }
            int i = t128 * 4;
            *(float4*)&g_ppart[ks][b][0][i] = A0;
            *(float4*)&g_ppart[ks][b][1][i] = A1;
            *(float4*)&g_ppart[ks][b][2][i] = A2;
            *(float4*)&g_ppart[ks][b][3][i] = A3;
            if (t128 < 4) {
                float se = 0.f, ewb = 0.f;
#pragma unroll 8
                for (int k = 0; k < 32; k++) {
                    float e = sS[320 + k * 4 + t128];
                    se += e;
                    ewb += e * sS[160 + k];
                }
                g_pse[ks][b][t128] = se;
                g_pewb[ks][b][t128] = ewb;
            }
            asm volatile("bar.sync %0, 128;" ::"r"(nbar));
        }
    }
    // ---- barrier 1 (leader also resets task counter) ----
    __syncthreads();
    if (tid == 0) {
        __threadfence();
        if (atomicAdd(&g_count, 1u) == NB - 1) {
            g_count = 0;
            g_task = 0;
            __threadfence();
            g_release = base + 1;
        } else {
            while ((unsigned)(g_release - base) < 1u) __nanosleep(32);
            __threadfence();
        }
    }
    __syncthreads();

    // ============ T1': combine scalars + rescale + p @ Wv (512 vblocks) ============
    {
        int half = tid >> 7, t128 = tid & 127;
        int vb = bid * 2 + half;
        int bh = vb & 3, hh = (vb >> 2) & 3, iy = vb >> 4;  // iy 0..31
        int i0 = iy * 16, f = hh * 128 + t128;
        float* sb = SM + half * 160;
        float* sp = SM + 320 + half * 128;
        if (t128 < 8) {
            int gb = bh * 8 + t128;
            float scls = SCALE * g_C[8 + hh];
            float ms[16];
            float M = scls;
#pragma unroll
            for (int s = 0; s < 16; s++) {
                ms[s] = g_pm[s][gb][hh];
                M = fmaxf(M, ms[s]);
            }
            float Se = 0.f, Ewb = 0.f;
#pragma unroll
            for (int s = 0; s < 16; s++) {
                float fs = __expf(ms[s] - M);
                sb[t128 * 16 + s] = fs;
                Se += fs * g_pse[s][gb][hh];
                Ewb += fs * g_pewb[s][gb][hh];
            }
            float ecls = __expf(scls - M);
            sb[128 + t128] = 1.f / (Se + ecls);
            sb[136 + t128] = Se;
            sb[144 + t128] = Ewb;
            sb[152 + t128] = ecls;
        }
        __syncthreads();
        {
            int bl = t128 >> 4, ii = t128 & 15;
            int gb = bh * 8 + bl;
            int i = i0 + ii;
            float A = 0.f;
#pragma unroll
            for (int s = 0; s < 16; s++) A = fmaf(sb[bl * 16 + s], g_ppart[s][gb][hh][i], A);
            sp[t128] = sb[128 + bl] *
                       (s1[i] * (A + sb[144 + bl]) + b1[i] * sb[136 + bl] + sb[152 + bl] * g_hl[i]);
        }
        __syncthreads();
        float acc[8];
#pragma unroll
        for (int bl = 0; bl < 8; bl++) acc[bl] = 0.f;
#pragma unroll
        for (int ii = 0; ii < 16; ii += 4) {
            int i = i0 + ii;
            float w0 = Wv[(size_t)i * 512 + f];
            float w1 = Wv[(size_t)(i + 1) * 512 + f];
            float w2 = Wv[(size_t)(i + 2) * 512 + f];
            float w3 = Wv[(size_t)(i + 3) * 512 + f];
#pragma unroll
            for (int bl = 0; bl < 8; bl++) {
                float4 p = *(const float4*)&sp[bl * 16 + ii];
                acc[bl] = fmaf(p.x, w0, fmaf(p.y, w1, fmaf(p.z, w2, fmaf(p.w, w3, acc[bl]))));
            }
        }
#pragma unroll
        for (int bl = 0; bl < 8; bl++) g_ctxpart[iy][bh * 8 + bl][f] = acc[bl];
    }
    gridbar(base, 2);

    // ============ T2: o partials = (ctx+bv) @ Wo (512 vblocks) ============
    {
        int half = tid >> 7, t128 = tid & 127;
        int vb = bid * 2 + half;
        int bh = vb & 3, cx = (vb >> 2) & 3, iy = vb >> 4;
        int i0 = iy * 16, f = cx * 128 + t128;
        float* sc = SM + half * 128;
        {
            int bl = t128 >> 4, ii = t128 & 15;
            int gb = bh * 8 + bl;
            int i = i0 + ii;
            float v = bv[i];
#pragma unroll
            for (int s = 0; s < 32; s++) v += g_ctxpart[s][gb][i];
            sc[t128] = v;
        }
        __syncthreads();
        float acc[8];
#pragma unroll
        for (int bl = 0; bl < 8; bl++) acc[bl] = 0.f;
#pragma unroll
        for (int ii = 0; ii < 16; ii += 4) {
            int i = i0 + ii;
            float w0 = Wo[(size_t)i * 512 + f];
            float w1 = Wo[(size_t)(i + 1) * 512 + f];
            float w2 = Wo[(size_t)(i + 2) * 512 + f];
            float w3 = Wo[(size_t)(i + 3) * 512 + f];
#pragma unroll
            for (int bl = 0; bl < 8; bl++) {
                float4 p = *(const float4*)&sc[bl * 16 + ii];
                acc[bl] = fmaf(p.x, w0, fmaf(p.y, w1, fmaf(p.z, w2, fmaf(p.w, w3, acc[bl]))));
            }
        }
#pragma unroll
        for (int bl = 0; bl < 8; bl++) g_wopart[iy][bh * 8 + bl][f] = acc[bl];
    }
    gridbar(base, 3);

    // ============ T3: h1 = token + o + bo; LN2 stats ============
    if (bid < 32) {
        int b = bid;
        float sum = 0.f, ssq = 0.f;
#pragma unroll
        for (int t = 0; t < 2; t++) {
            int c = tid + 256 * t;
            float v = token[c] + bo[c];
#pragma unroll
            for (int s = 0; s < 32; s++) v += g_wopart[s][b][c];
            g_h1[b][c] = v;
            sum += v;
            ssq += v * v;
        }
        float* r2 = SM;
        r2[tid * 2] = sum;
        r2[tid * 2 + 1] = ssq;
        __syncthreads();
        for (int o = 128; o; o >>= 1) {
            if (tid < o) {
                r2[tid * 2] += r2[(tid + o) * 2];
                r2[tid * 2 + 1] += r2[(tid + o) * 2 + 1];
            }
            __syncthreads();
        }
        if (tid == 0) {
            float m = r2[0] * (1.f / 512.f);
            float var = r2[1] * (1.f / 512.f) - m * m;
            g_ln2[b] = make_float2(m, rsqrtf(var + 1e-5f));
        }
    }
    gridbar(base, 4);

    // ============ T4: W1 partials (h2 @ W1), 512 vblocks ============
    {
        int half = tid >> 7, t128 = tid & 127;
        int vb = bid * 2 + half;
        int fx = vb & 15, iy = vb >> 4;  // iy 0..31
        int i0 = iy * 16, f = fx * 128 + t128;
        float* sh2 = SM + half * 512;
        for (int idx = t128; idx < 512; idx += 128) {
            int b = idx >> 4, ii = idx & 15, i = i0 + ii;
            float2 mr = g_ln2[b];
            sh2[b * 16 + ii] = (g_h1[b][i] - mr.x) * mr.y * s2[i] + b2l[i];
        }
        __syncthreads();
        float acc[32];
#pragma unroll
        for (int b = 0; b < 32; b++) acc[b] = 0.f;
#pragma unroll
        for (int ii = 0; ii < 16; ii += 4) {
            int i = i0 + ii;
            float w0 = W1[(size_t)i * 2048 + f];
            float w1 = W1[(size_t)(i + 1) * 2048 + f];
            float w2 = W1[(size_t)(i + 2) * 2048 + f];
            float w3 = W1[(size_t)(i + 3) * 2048 + f];
#pragma unroll
            for (int b = 0; b < 32; b++) {
                float4 p = *(const float4*)&sh2[b * 16 + ii];
                acc[b] = fmaf(p.x, w0, fmaf(p.y, w1, fmaf(p.z, w2, fmaf(p.w, w3, acc[b]))));
            }
        }
#pragma unroll
        for (int b = 0; b < 32; b++) g_w1part[iy][b][f] = acc[b];
    }
    gridbar(base, 5);

    // ============ T5: gelu + W2 partials, 512 vblocks ============
    {
        int half = tid >> 7, t128 = tid & 127;
        int vb = bid * 2 + half;
        int fx = vb & 3, iy = vb >> 2;  // iy 0..127
        int i0 = iy * 16, f = fx * 128 + t128;
        float* su = SM + half * 512;
        for (int idx = t128; idx < 512; idx += 128) {
            int b = idx >> 4, ii = idx & 15, i = i0 + ii;
            float u = b1f[i];
#pragma unroll
            for (int s = 0; s < 32; s++) u += g_w1part[s][b][i];
            su[b * 16 + ii] = geluf(u);
        }
        __syncthreads();
        float acc[32];
#pragma unroll
        for (int b = 0; b < 32; b++) acc[b] = 0.f;
#pragma unroll
        for (int ii = 0; ii < 16; ii += 4) {
            int i = i0 + ii;
            float w0 = W2[(size_t)i * 512 + f];
            float w1 = W2[(size_t)(i + 1) * 512 + f];
            float w2 = W2[(size_t)(i + 2) * 512 + f];
            float w3 = W2[(size_t)(i + 3) * 512 + f];
#pragma unroll
            for (int b = 0; b < 32; b++) {
                float4 p = *(const float4*)&su[b * 16 + ii];
                acc[b] = fmaf(p.x, w0, fmaf(p.y, w1, fmaf(p.z, w2, fmaf(p.w, w3, acc[b]))));
            }
        }
#pragma unroll
        for (int b = 0; b < 32; b++) g_w2part[iy][b][f] = acc[b];
    }
    gridbar(base, 6);

    // ============ OUT ============
    if (bid < 32) {
        int b = bid;
        int c0 = tid * 2;
        float2 acc;
        acc.x = g_h1[b][c0] + b2o[c0];
        acc.y = g_h1[b][c0 + 1] + b2o[c0 + 1];
#pragma unroll 16
        for (int s = 0; s < 128; s++) {
            float2 w = *(const float2*)&g_w2part[s][b][c0];
            acc.x += w.x;
            acc.y += w.y;
        }
        *(float2*)&out[b * 512 + c0] = acc;
    }
}

extern "C" void kernel_launch(void* const* d_in, const int* in_sizes, int n_in,
                              void* d_out, int out_size) {
    const float* x     = (const float*)d_in[0];
    const int*   mask  = (const int*)d_in[1];
    const float* token = (const float*)d_in[2];
    const float* Wq    = (const float*)d_in[3];
    const float* bq    = (const float*)d_in[4];
    const float* Wk    = (const float*)d_in[5];
    // d_in[6] = bk: uniform shift across keys -> cancels in softmax; unused
    const float* Wv    = (const float*)d_in[7];
    const float* bv    = (const float*)d_in[8];
    const float* Wo    = (const float*)d_in[9];
    const float* bo    = (const float*)d_in[10];
    const float* s1    = (const float*)d_in[11];
    const float* b1    = (const float*)d_in[12];
    const float* s2    = (const float*)d_in[13];
    const float* b2l   = (const float*)d_in[14];
    const float* W1    = (const float*)d_in[15];
    const float* b1f   = (const float*)d_in[16];
    const float* W2    = (const float*)d_in[17];
    const float* b2o   = (const float*)d_in[18];
    float* out = (float*)d_out;

    fused_kernel<<<NB, NT>>>(x, mask, token, Wq, bq, Wk, Wv, bv, Wo, bo,
                             s1, b1, s2, b2l, W1, b1f, W2, b2o, out);
}

// round 11
// speedup vs baseline: 2.3060x; 1.1317x over previous
#include <cuda_runtime.h>
#include <math.h>

#define SCALE 0.08838834764831845f  // 1/sqrt(128)
#define NB 256
#define NT 256

// ---------------- sync state (epoch-based; graph-replay safe) ----------------
__device__ unsigned g_count;
__device__ volatile unsigned g_release;
__device__ unsigned g_ctA;
__device__ volatile unsigned g_relA;
__device__ unsigned g_ctB;
__device__ volatile unsigned g_relB;
__device__ unsigned g_task;
__device__ float g_dummy;

// ---------------- scratch ----------------
__device__ __align__(16) float g_hl[512];
__device__ __align__(16) float g_qpart[16][512];
__device__ __align__(16) float g_gs[4][512];
__device__ __align__(16) float g_cpart[64][12];
__device__ __align__(16) float g_C[12];
__device__ __align__(16) float g_pm[16][32][4];
__device__ __align__(16) float g_pse[16][32][4];
__device__ __align__(16) float g_pewb[16][32][4];
__device__ __align__(16) float g_ppart[16][32][4][512];
__device__ __align__(16) float g_ctxpart[32][32][512];
__device__ __align__(16) float g_wopart[32][32][512];
__device__ __align__(16) float g_h1[32][512];
__device__ __align__(16) float2 g_ln2[32];
__device__ __align__(16) float g_w1part[8][32][2048];

static __device__ __forceinline__ float wred(float v) {
#pragma unroll
    for (int o = 16; o; o >>= 1) v += __shfl_xor_sync(0xffffffffu, v, o);
    return v;
}

static __device__ __forceinline__ float geluf(float t) {
    float t3 = t * t * t;
    return 0.5f * t * (1.f + tanhf(0.7978845608028654f * (t + 0.044715f * t3)));
}

__device__ __forceinline__ void gridbar(unsigned base, unsigned idx) {
    __syncthreads();
    if (threadIdx.x == 0) {
        __threadfence();
        if (atomicAdd(&g_count, 1u) == NB - 1) {
            g_count = 0;
            __threadfence();
            g_release = base + idx;
        } else {
            while ((unsigned)(g_release - base) < idx) __nanosleep(32);
            __threadfence();
        }
    }
    __syncthreads();
}

__global__ void __launch_bounds__(NT, 2) fused_kernel(
    const float* __restrict__ x, const int* __restrict__ mask,
    const float* __restrict__ token,
    const float* __restrict__ Wq, const float* __restrict__ bq,
    const float* __restrict__ Wk,
    const float* __restrict__ Wv, const float* __restrict__ bv,
    const float* __restrict__ Wo, const float* __restrict__ bo,
    const float* __restrict__ s1, const float* __restrict__ b1,
    const float* __restrict__ s2, const float* __restrict__ b2l,
    const float* __restrict__ W1, const float* __restrict__ b1f,
    const float* __restrict__ W2, const float* __restrict__ b2o,
    float* __restrict__ out) {
    __shared__ float SM[3072];
    __shared__ unsigned s_base_sh;
    __shared__ int s_last;
    __shared__ int s_task[2];
    int tid = threadIdx.x;
    int bid = blockIdx.x;
    int wid = tid >> 5, lane = tid & 31;
    if (tid == 0) s_base_sh = g_release;
    __syncthreads();
    unsigned base = s_base_sh;

    // ================= PHASE I: prologue (flag-synced) + split task loop =================
    if (bid < 16) {
        // --- token LN + q partials ---
        float t0 = token[tid], t1 = token[tid + 256];
        float* red = SM;
        red[tid] = t0 + t1;
        __syncthreads();
#pragma unroll
        for (int o = 128; o; o >>= 1) {
            if (tid < o) red[tid] += red[tid + o];
            __syncthreads();
        }
        float mean = red[0] * (1.f / 512.f);
        __syncthreads();
        float d0 = t0 - mean, d1 = t1 - mean;
        red[tid] = d0 * d0 + d1 * d1;
        __syncthreads();
#pragma unroll
        for (int o = 128; o; o >>= 1) {
            if (tid < o) red[tid] += red[tid + o];
            __syncthreads();
        }
        float rstd = rsqrtf(red[0] * (1.f / 512.f) + 1e-5f);
        __syncthreads();
        float* shl = SM;
        float hl0 = d0 * rstd * s1[tid] + b1[tid];
        float hl1 = d1 * rstd * s1[tid + 256] + b1[tid + 256];
        shl[tid] = hl0;
        shl[tid + 256] = hl1;
        if (bid == 0) {
            g_hl[tid] = hl0;
            g_hl[tid + 256] = hl1;
        }
        __syncthreads();
        int j0 = bid * 32;
        float a0 = 0.f, a1 = 0.f;
#pragma unroll
        for (int j = 0; j < 32; j++) {
            float h = shl[j0 + j];
            a0 = fmaf(h, Wq[(size_t)(j0 + j) * 512 + tid], a0);
            a1 = fmaf(h, Wq[(size_t)(j0 + j) * 512 + tid + 256], a1);
        }
        g_qpart[bid][tid] = a0;
        g_qpart[bid][tid + 256] = a1;
        __threadfence();
        __syncthreads();
        if (tid == 0) {
            if (atomicAdd(&g_ctA, 1u) == 15) {
                g_ctA = 0;
                __threadfence();
                g_relA = base + 1;
            }
        }
        // --- prefetch weights into L2 ---
        {
            int pw = bid * 256 + tid;
            float acc = 0.f;
            const float4* a1p = (const float4*)Wv;
            const float4* a2p = (const float4*)Wo;
            const float4* a3p = (const float4*)W1;
            const float4* a4p = (const float4*)W2;
#pragma unroll 2
            for (int i = pw; i < 65536; i += 20480) acc += __ldg(a1p + i).x + __ldg(a2p + i).x;
#pragma unroll 4
            for (int i = pw; i < 262144; i += 20480) acc += __ldg(a3p + i).x + __ldg(a4p + i).x;
            if (acc == 1.2345e30f) g_dummy = acc;
        }
    } else if (bid < 80) {
        // --- wait q partials ---
        if (tid == 0) {
            while ((unsigned)(g_relA - base) < 1u) __nanosleep(32);
            __threadfence();
        }
        __syncthreads();
        // --- combine q; gs rows; C partials ---
        float* sq = SM;
        float q0 = bq[tid], q1 = bq[tid + 256];
#pragma unroll
        for (int s = 0; s < 16; s++) {
            q0 += g_qpart[s][tid];
            q1 += g_qpart[s][tid + 256];
        }
        sq[tid] = q0;
        sq[tid + 256] = q1;
        __syncthreads();
        int r = (bid - 16) * 8 + wid;
        const float4* wr = (const float4*)(Wk + (size_t)r * 512);
        const float4* q4 = (const float4*)sq;
        float dt[4];
#pragma unroll
        for (int t = 0; t < 4; t++) {
            float4 w = __ldg(wr + lane + 32 * t);
            float4 q = q4[lane + 32 * t];
            dt[t] = w.x * q.x + w.y * q.y + w.z * q.z + w.w * q.w;
        }
#pragma unroll
        for (int t = 0; t < 4; t++) dt[t] = wred(dt[t]);
        float* cred = SM + 512;  // [8][12]
        if (lane == 0) {
            float sr = s1[r], br = b1[r], hr = g_hl[r];
#pragma unroll
            for (int t = 0; t < 4; t++) {
                g_gs[t][r] = dt[t] * sr;
                cred[wid * 12 + t] = sr * dt[t];
                cred[wid * 12 + 4 + t] = br * dt[t];
                cred[wid * 12 + 8 + t] = hr * dt[t];
            }
        }
        __syncthreads();
        if (tid < 12) {
            float c = 0.f;
#pragma unroll
            for (int w = 0; w < 8; w++) c += cred[w * 12 + tid];
            g_cpart[bid - 16][tid] = c;
        }
        __threadfence();
        __syncthreads();
        if (tid == 0) s_last = (atomicAdd(&g_ctB, 1u) == 63) ? 1 : 0;
        __syncthreads();
        if (s_last) {
            if (tid < 12) {
                float c = 0.f;
#pragma unroll
                for (int j = 0; j < 64; j++) c += g_cpart[j][tid];
                g_C[tid] = c;
            }
            __threadfence();
            __syncthreads();
            if (tid == 0) {
                g_ctB = 0;
                __threadfence();
                g_relB = base + 1;
            }
        }
        // --- prefetch weights ---
        {
            int pw = bid * 256 + tid;
            float acc = 0.f;
            const float4* a1p = (const float4*)Wv;
            const float4* a2p = (const float4*)Wo;
            const float4* a3p = (const float4*)W1;
            const float4* a4p = (const float4*)W2;
#pragma unroll 2
            for (int i = pw; i < 65536; i += 20480) acc += __ldg(a1p + i).x + __ldg(a2p + i).x;
#pragma unroll 4
            for (int i = pw; i < 262144; i += 20480) acc += __ldg(a3p + i).x + __ldg(a4p + i).x;
            if (acc == 1.2345e30f) g_dummy = acc;
        }
    }
    // --- all blocks: wait gs/C ready ---
    if (tid == 0) {
        while ((unsigned)(g_relB - base) < 1u) __nanosleep(32);
        __threadfence();
    }
    __syncthreads();
    // --- load gs + C to smem ---
    for (int i = tid; i < 2048; i += NT) SM[i] = ((const float*)g_gs)[i];
    if (tid < 12) SM[2048 + tid] = g_C[tid];
    __syncthreads();
    {
        const float4* sgs4 = (const float4*)SM;
        float C1[4], C2[4];
#pragma unroll
        for (int h = 0; h < 4; h++) {
            C1[h] = SM[2048 + h];
            C2[h] = SM[2052 + h];
        }
        int half = tid >> 7, t128 = tid & 127, w = t128 >> 5;
        float* sS = SM + 2064 + half * 464;  // sc[128], al[32], be[32], w[128], e[128]
        int nbar = 1 + half;
        // ---- task loop: each task = one (b, ks) split, processed end-to-end ----
        while (true) {
            if (t128 == 0) s_task[half] = (int)atomicAdd(&g_task, 1u);
            asm volatile("bar.sync %0, 128;" ::"r"(nbar));
            int t = s_task[half];
            if (t >= 512) break;
            int ks = t & 15, b = t >> 4;
            int L = __ldg(&mask[b]);
            int k0 = ks * 32;
            // --- score pass: each warp 8 rows, 2-batched; stats inline ---
#pragma unroll 1
            for (int it = 0; it < 4; it++) {
                int kl = w * 8 + it * 2;
                int kg = k0 + kl;
                bool v0 = kg < L, v1 = kg + 1 < L;
                const float4* xr0 = (const float4*)(x + ((size_t)b * 512 + kg) * 512);
                float4 xa[4], xc[4];
#pragma unroll
                for (int tt = 0; tt < 4; tt++) xa[tt] = make_float4(0.f, 0.f, 0.f, 0.f);
#pragma unroll
                for (int tt = 0; tt < 4; tt++) xc[tt] = make_float4(0.f, 0.f, 0.f, 0.f);
                if (v0) {
#pragma unroll
                    for (int tt = 0; tt < 4; tt++) xa[tt] = __ldg(xr0 + lane + 32 * tt);
                }
                if (v1) {
#pragma unroll
                    for (int tt = 0; tt < 4; tt++) xc[tt] = __ldg(xr0 + 128 + lane + 32 * tt);
                }
                float ssA = 0.f, smA = 0.f, ssB = 0.f, smB = 0.f;
#pragma unroll
                for (int tt = 0; tt < 4; tt++) {
                    ssA += xa[tt].x * xa[tt].x + xa[tt].y * xa[tt].y + xa[tt].z * xa[tt].z +
                           xa[tt].w * xa[tt].w;
                    smA += xa[tt].x + xa[tt].y + xa[tt].z + xa[tt].w;
                    ssB += xc[tt].x * xc[tt].x + xc[tt].y * xc[tt].y + xc[tt].z * xc[tt].z +
                           xc[tt].w * xc[tt].w;
                    smB += xc[tt].x + xc[tt].y + xc[tt].z + xc[tt].w;
                }
                float dA[4], dB[4];
#pragma unroll
                for (int h = 0; h < 4; h++) {
                    float aA = 0.f, aB = 0.f;
#pragma unroll
                    for (int tt = 0; tt < 4; tt++) {
                        float4 g = sgs4[h * 128 + lane + 32 * tt];
                        aA += xa[tt].x * g.x + xa[tt].y * g.y + xa[tt].z * g.z + xa[tt].w * g.w;
                        aB += xc[tt].x * g.x + xc[tt].y * g.y + xc[tt].z * g.z + xc[tt].w * g.w;
                    }
                    dA[h] = wred(aA);
                    dB[h] = wred(aB);
                }
                ssA = wred(ssA);
                smA = wred(smA);
                ssB = wred(ssB);
                smB = wred(smB);
                if (lane == 0) {
                    float al0 = 0.f, be0 = 0.f, al1 = 0.f, be1 = 0.f;
                    if (v0) {
                        float inv = 1.f / fmaxf(sqrtf(ssA), 1e-12f);
                        float m = smA * inv * (1.f / 512.f);
                        float v = ssA * inv * inv * (1.f / 512.f) - m * m;
                        float rs = rsqrtf(v + 1e-5f);
                        al0 = inv * rs;
                        be0 = -m * rs;
                    }
                    if (v1) {
                        float inv = 1.f / fmaxf(sqrtf(ssB), 1e-12f);
                        float m = smB * inv * (1.f / 512.f);
                        float v = ssB * inv * inv * (1.f / 512.f) - m * m;
                        float rs = rsqrtf(v + 1e-5f);
                        al1 = inv * rs;
                        be1 = -m * rs;
                    }
#pragma unroll
                    for (int h = 0; h < 4; h++) {
                        sS[kl * 4 + h] =
                            v0 ? SCALE * (al0 * dA[h] + be0 * C1[h] + C2[h]) : -1e30f;
                        sS[(kl + 1) * 4 + h] =
                            v1 ? SCALE * (al1 * dB[h] + be1 * C1[h] + C2[h]) : -1e30f;
                    }
                    sS[128 + kl] = al0;
                    sS[128 + kl + 1] = al1;
                    sS[160 + kl] = be0;
                    sS[160 + kl + 1] = be1;
                }
            }
            asm volatile("bar.sync %0, 128;" ::"r"(nbar));
            // --- e/w compute: thread (k,h) ---
            {
                int k = t128 >> 2, h = t128 & 3;
                float m = -1e30f;
#pragma unroll 8
                for (int j = 0; j < 32; j++) m = fmaxf(m, sS[j * 4 + h]);
                float e = __expf(sS[k * 4 + h] - m);
                sS[320 + k * 4 + h] = e;
                sS[192 + k * 4 + h] = e * sS[128 + k];
                if (k == 0) g_pm[ks][b][h] = m;
            }
            asm volatile("bar.sync %0, 128;" ::"r"(nbar));
            // --- A accumulate (x rows warm in L1) ---
            int kv = L - k0;
            kv = kv < 0 ? 0 : (kv > 32 ? 32 : kv);
            float4 A0 = {0, 0, 0, 0}, A1 = A0, A2 = A0, A3 = A0;
            const float4* xb4 = (const float4*)(x + ((size_t)b * 512 + k0) * 512);
#pragma unroll 4
            for (int k = 0; k < kv; k++) {
                float4 w4 = *(const float4*)&sS[192 + k * 4];
                float4 xv = __ldg(xb4 + (size_t)k * 128 + t128);
                A0.x = fmaf(w4.x, xv.x, A0.x); A0.y = fmaf(w4.x, xv.y, A0.y);
                A0.z = fmaf(w4.x, xv.z, A0.z); A0.w = fmaf(w4.x, xv.w, A0.w);
                A1.x = fmaf(w4.y, xv.x, A1.x); A1.y = fmaf(w4.y, xv.y, A1.y);
                A1.z = fmaf(w4.y, xv.z, A1.z); A1.w = fmaf(w4.y, xv.w, A1.w);
                A2.x = fmaf(w4.z, xv.x, A2.x); A2.y = fmaf(w4.z, xv.y, A2.y);
                A2.z = fmaf(w4.z, xv.z, A2.z); A2.w = fmaf(w4.z, xv.w, A2.w);
                A3.x = fmaf(w4.w, xv.x, A3.x); A3.y = fmaf(w4.w, xv.y, A3.y);
                A3.z = fmaf(w4.w, xv.z, A3.z); A3.w = fmaf(w4.w, xv.w, A3.w);
            }
            int i = t128 * 4;
            *(float4*)&g_ppart[ks][b][0][i] = A0;
            *(float4*)&g_ppart[ks][b][1][i] = A1;
            *(float4*)&g_ppart[ks][b][2][i] = A2;
            *(float4*)&g_ppart[ks][b][3][i] = A3;
            if (t128 < 4) {
                float se = 0.f, ewb = 0.f;
#pragma unroll 8
                for (int k = 0; k < 32; k++) {
                    float e = sS[320 + k * 4 + t128];
                    se += e;
                    ewb += e * sS[160 + k];
                }
                g_pse[ks][b][t128] = se;
                g_pewb[ks][b][t128] = ewb;
            }
            asm volatile("bar.sync %0, 128;" ::"r"(nbar));
        }
    }
    // ---- barrier 1 (leader also resets task counter) ----
    __syncthreads();
    if (tid == 0) {
        __threadfence();
        if (atomicAdd(&g_count, 1u) == NB - 1) {
            g_count = 0;
            g_task = 0;
            __threadfence();
            g_release = base + 1;
        } else {
            while ((unsigned)(g_release - base) < 1u) __nanosleep(32);
            __threadfence();
        }
    }
    __syncthreads();

    // ============ T1': combine scalars + rescale + p @ Wv (512 vblocks) ============
    {
        int half = tid >> 7, t128 = tid & 127;
        int vb = bid * 2 + half;
        int bh = vb & 3, hh = (vb >> 2) & 3, iy = vb >> 4;  // iy 0..31
        int i0 = iy * 16, f = hh * 128 + t128;
        float* sb = SM + half * 160;
        float* sp = SM + 320 + half * 128;
        if (t128 < 8) {
            int gb = bh * 8 + t128;
            float scls = SCALE * g_C[8 + hh];
            float ms[16];
            float M = scls;
#pragma unroll
            for (int s = 0; s < 16; s++) {
                ms[s] = g_pm[s][gb][hh];
                M = fmaxf(M, ms[s]);
            }
            float Se = 0.f, Ewb = 0.f;
#pragma unroll
            for (int s = 0; s < 16; s++) {
                float fs = __expf(ms[s] - M);
                sb[t128 * 16 + s] = fs;
                Se += fs * g_pse[s][gb][hh];
                Ewb += fs * g_pewb[s][gb][hh];
            }
            float ecls = __expf(scls - M);
            sb[128 + t128] = 1.f / (Se + ecls);
            sb[136 + t128] = Se;
            sb[144 + t128] = Ewb;
            sb[152 + t128] = ecls;
        }
        __syncthreads();
        {
            int bl = t128 >> 4, ii = t128 & 15;
            int gb = bh * 8 + bl;
            int i = i0 + ii;
            float A = 0.f;
#pragma unroll
            for (int s = 0; s < 16; s++) A = fmaf(sb[bl * 16 + s], g_ppart[s][gb][hh][i], A);
            sp[t128] = sb[128 + bl] *
                       (s1[i] * (A + sb[144 + bl]) + b1[i] * sb[136 + bl] + sb[152 + bl] * g_hl[i]);
        }
        __syncthreads();
        float acc[8];
#pragma unroll
        for (int bl = 0; bl < 8; bl++) acc[bl] = 0.f;
#pragma unroll
        for (int ii = 0; ii < 16; ii += 4) {
            int i = i0 + ii;
            float w0 = Wv[(size_t)i * 512 + f];
            float w1 = Wv[(size_t)(i + 1) * 512 + f];
            float w2 = Wv[(size_t)(i + 2) * 512 + f];
            float w3 = Wv[(size_t)(i + 3) * 512 + f];
#pragma unroll
            for (int bl = 0; bl < 8; bl++) {
                float4 p = *(const float4*)&sp[bl * 16 + ii];
                acc[bl] = fmaf(p.x, w0, fmaf(p.y, w1, fmaf(p.z, w2, fmaf(p.w, w3, acc[bl]))));
            }
        }
#pragma unroll
        for (int bl = 0; bl < 8; bl++) g_ctxpart[iy][bh * 8 + bl][f] = acc[bl];
    }
    gridbar(base, 2);

    // ============ T2: o partials = (ctx+bv) @ Wo (512 vblocks) ============
    {
        int half = tid >> 7, t128 = tid & 127;
        int vb = bid * 2 + half;
        int bh = vb & 3, cx = (vb >> 2) & 3, iy = vb >> 4;
        int i0 = iy * 16, f = cx * 128 + t128;
        float* sc = SM + half * 128;
        {
            int bl = t128 >> 4, ii = t128 & 15;
            int gb = bh * 8 + bl;
            int i = i0 + ii;
            float v = bv[i];
#pragma unroll
            for (int s = 0; s < 32; s++) v += g_ctxpart[s][gb][i];
            sc[t128] = v;
        }
        __syncthreads();
        float acc[8];
#pragma unroll
        for (int bl = 0; bl < 8; bl++) acc[bl] = 0.f;
#pragma unroll
        for (int ii = 0; ii < 16; ii += 4) {
            int i = i0 + ii;
            float w0 = Wo[(size_t)i * 512 + f];
            float w1 = Wo[(size_t)(i + 1) * 512 + f];
            float w2 = Wo[(size_t)(i + 2) * 512 + f];
            float w3 = Wo[(size_t)(i + 3) * 512 + f];
#pragma unroll
            for (int bl = 0; bl < 8; bl++) {
                float4 p = *(const float4*)&sc[bl * 16 + ii];
                acc[bl] = fmaf(p.x, w0, fmaf(p.y, w1, fmaf(p.z, w2, fmaf(p.w, w3, acc[bl]))));
            }
        }
#pragma unroll
        for (int bl = 0; bl < 8; bl++) g_wopart[iy][bh * 8 + bl][f] = acc[bl];
    }
    gridbar(base, 3);

    // ============ T3: h1 = token + o + bo; LN2 stats ============
    if (bid < 32) {
        int b = bid;
        float sum = 0.f, ssq = 0.f;
#pragma unroll
        for (int t = 0; t < 2; t++) {
            int c = tid + 256 * t;
            float v = token[c] + bo[c];
#pragma unroll
            for (int s = 0; s < 32; s++) v += g_wopart[s][b][c];
            g_h1[b][c] = v;
            sum += v;
            ssq += v * v;
        }
        float* r2 = SM;
        r2[tid * 2] = sum;
        r2[tid * 2 + 1] = ssq;
        __syncthreads();
        for (int o = 128; o; o >>= 1) {
            if (tid < o) {
                r2[tid * 2] += r2[(tid + o) * 2];
                r2[tid * 2 + 1] += r2[(tid + o) * 2 + 1];
            }
            __syncthreads();
        }
        if (tid == 0) {
            float m = r2[0] * (1.f / 512.f);
            float var = r2[1] * (1.f / 512.f) - m * m;
            g_ln2[b] = make_float2(m, rsqrtf(var + 1e-5f));
        }
    }
    gridbar(base, 4);

    // ============ T4: W1 partials (h2 @ W1), 512 vblocks; also init out = h1 + b2o ============
    {
        // init out (h1 is final after T3's barrier)
        if (tid < 64) {
            int idx = bid * 64 + tid;  // = b*512 + c
            out[idx] = g_h1[idx >> 9][idx & 511] + b2o[idx & 511];
        }
        int half = tid >> 7, t128 = tid & 127;
        int vb = bid * 2 + half;  // 0..511
        int fx = vb & 15, bh = (vb >> 4) & 3, iy = vb >> 6;  // iy 0..7
        int i0 = iy * 64, f = fx * 128 + t128;
        float* sh2 = SM + half * 512;  // [8 b][64 i]
        {
#pragma unroll
            for (int j = 0; j < 4; j++) {
                int idx = t128 + j * 128;
                int bl = idx >> 6, ii = idx & 63;
                int b = bh * 8 + bl, i = i0 + ii;
                float2 mr = g_ln2[b];
                sh2[idx] = (g_h1[b][i] - mr.x) * mr.y * s2[i] + b2l[i];
            }
        }
        __syncthreads();
        float acc[8];
#pragma unroll
        for (int bl = 0; bl < 8; bl++) acc[bl] = 0.f;
#pragma unroll 4
        for (int ii = 0; ii < 64; ii += 4) {
            int i = i0 + ii;
            float w0 = W1[(size_t)i * 2048 + f];
            float w1 = W1[(size_t)(i + 1) * 2048 + f];
            float w2 = W1[(size_t)(i + 2) * 2048 + f];
            float w3 = W1[(size_t)(i + 3) * 2048 + f];
#pragma unroll
            for (int bl = 0; bl < 8; bl++) {
                float4 p = *(const float4*)&sh2[bl * 64 + ii];
                acc[bl] = fmaf(p.x, w0, fmaf(p.y, w1, fmaf(p.z, w2, fmaf(p.w, w3, acc[bl]))));
            }
        }
#pragma unroll
        for (int bl = 0; bl < 8; bl++) g_w1part[iy][bh * 8 + bl][f] = acc[bl];
    }
    gridbar(base, 5);

    // ============ T5: gelu + W2, atomic-accumulate into out (512 vblocks) ============
    {
        int half = tid >> 7, t128 = tid & 127;
        int vb = bid * 2 + half;  // 0..511
        int fx = vb & 3, bh = (vb >> 2) & 7, iy = vb >> 5;  // iy 0..15
        int i0 = iy * 128, f = fx * 128 + t128;
        float* su = SM + half * 512;  // [4 b][128 i]
        {
#pragma unroll
            for (int j = 0; j < 4; j++) {
                int idx = t128 + j * 128;
                int bl = idx >> 7, ii = idx & 127;
                int b = bh * 4 + bl, i = i0 + ii;
                float u = b1f[i];
#pragma unroll
                for (int s = 0; s < 8; s++) u += g_w1part[s][b][i];
                su[idx] = geluf(u);
            }
        }
        __syncthreads();
        float acc[4];
#pragma unroll
        for (int bl = 0; bl < 4; bl++) acc[bl] = 0.f;
#pragma unroll 4
        for (int ii = 0; ii < 128; ii += 4) {
            int i = i0 + ii;
            float w0 = W2[(size_t)i * 512 + f];
            float w1 = W2[(size_t)(i + 1) * 512 + f];
            float w2 = W2[(size_t)(i + 2) * 512 + f];
            float w3 = W2[(size_t)(i + 3) * 512 + f];
#pragma unroll
            for (int bl = 0; bl < 4; bl++) {
                float4 p = *(const float4*)&su[bl * 128 + ii];
                acc[bl] = fmaf(p.x, w0, fmaf(p.y, w1, fmaf(p.z, w2, fmaf(p.w, w3, acc[bl]))));
            }
        }
#pragma unroll
        for (int bl = 0; bl < 4; bl++) atomicAdd(&out[(bh * 4 + bl) * 512 + f], acc[bl]);
    }
}

extern "C" void kernel_launch(void* const* d_in, const int* in_sizes, int n_in,
                              void* d_out, int out_size) {
    const float* x     = (const float*)d_in[0];
    const int*   mask  = (const int*)d_in[1];
    const float* token = (const float*)d_in[2];
    const float* Wq    = (const float*)d_in[3];
    const float* bq    = (const float*)d_in[4];
    const float* Wk    = (const float*)d_in[5];
    // d_in[6] = bk: uniform shift across keys -> cancels in softmax; unused
    const float* Wv    = (const float*)d_in[7];
    const float* bv    = (const float*)d_in[8];
    const float* Wo    = (const float*)d_in[9];
    const float* bo    = (const float*)d_in[10];
    const float* s1    = (const float*)d_in[11];
    const float* b1    = (const float*)d_in[12];
    const float* s2    = (const float*)d_in[13];
    const float* b2l   = (const float*)d_in[14];
    const float* W1    = (const float*)d_in[15];
    const float* b1f   = (const float*)d_in[16];
    const float* W2    = (const float*)d_in[17];
    const float* b2o   = (const float*)d_in[18];
    float* out = (float*)d_out;

    fused_kernel<<<NB, NT>>>(x, mask, token, Wq, bq, Wk, Wv, bv, Wo, bo,
                             s1, b1, s2, b2l, W1, b1f, W2, b2o, out);
}

// round 12
// speedup vs baseline: 2.3538x; 1.0207x over previous
#include <cuda_runtime.h>
#include <math.h>

#define SCALE 0.08838834764831845f  // 1/sqrt(128)
#define NB 256
#define NT 256

// ---------------- sync state (epoch-based; graph-replay safe) ----------------
__device__ unsigned g_count;
__device__ volatile unsigned g_release;
__device__ unsigned g_ctA;
__device__ volatile unsigned g_relA;
__device__ unsigned g_ctB;
__device__ volatile unsigned g_relB;
__device__ unsigned g_task;
__device__ float g_dummy;

// ---------------- scratch ----------------
__device__ __align__(16) float g_hl[512];
__device__ __align__(16) float g_qpart[16][512];
__device__ __align__(16) float g_gs[4][512];
__device__ __align__(16) float g_cpart[64][12];
__device__ __align__(16) float g_C[12];
__device__ __align__(16) float g_pm[16][32][4];
__device__ __align__(16) float g_pse[16][32][4];
__device__ __align__(16) float g_pewb[16][32][4];
__device__ __align__(16) float g_ppart[16][32][4][512];
__device__ __align__(16) float g_ctxpart[32][32][512];
__device__ __align__(16) float g_h1[32][512];
__device__ __align__(16) float g_w1part[8][32][2048];

static __device__ __forceinline__ float wred(float v) {
#pragma unroll
    for (int o = 16; o; o >>= 1) v += __shfl_xor_sync(0xffffffffu, v, o);
    return v;
}

static __device__ __forceinline__ float geluf(float t) {
    float t3 = t * t * t;
    return 0.5f * t * (1.f + tanhf(0.7978845608028654f * (t + 0.044715f * t3)));
}

__device__ __forceinline__ void gridbar(unsigned base, unsigned idx) {
    __syncthreads();
    if (threadIdx.x == 0) {
        __threadfence();
        if (atomicAdd(&g_count, 1u) == NB - 1) {
            g_count = 0;
            __threadfence();
            g_release = base + idx;
        } else {
            while ((unsigned)(g_release - base) < idx) __nanosleep(32);
            __threadfence();
        }
    }
    __syncthreads();
}

__global__ void __launch_bounds__(NT, 2) fused_kernel(
    const float* __restrict__ x, const int* __restrict__ mask,
    const float* __restrict__ token,
    const float* __restrict__ Wq, const float* __restrict__ bq,
    const float* __restrict__ Wk,
    const float* __restrict__ Wv, const float* __restrict__ bv,
    const float* __restrict__ Wo, const float* __restrict__ bo,
    const float* __restrict__ s1, const float* __restrict__ b1,
    const float* __restrict__ s2, const float* __restrict__ b2l,
    const float* __restrict__ W1, const float* __restrict__ b1f,
    const float* __restrict__ W2, const float* __restrict__ b2o,
    float* __restrict__ out) {
    __shared__ float SM[3072];
    __shared__ unsigned s_base_sh;
    __shared__ int s_last;
    __shared__ int s_task[2];
    int tid = threadIdx.x;
    int bid = blockIdx.x;
    int wid = tid >> 5, lane = tid & 31;
    if (tid == 0) s_base_sh = g_release;
    __syncthreads();
    unsigned base = s_base_sh;

    // ================= PHASE I: prologue (flag-synced) + split task loop =================
    if (bid < 16) {
        // --- token LN + q partials ---
        float t0 = token[tid], t1 = token[tid + 256];
        float* red = SM;
        red[tid] = t0 + t1;
        __syncthreads();
#pragma unroll
        for (int o = 128; o; o >>= 1) {
            if (tid < o) red[tid] += red[tid + o];
            __syncthreads();
        }
        float mean = red[0] * (1.f / 512.f);
        __syncthreads();
        float d0 = t0 - mean, d1 = t1 - mean;
        red[tid] = d0 * d0 + d1 * d1;
        __syncthreads();
#pragma unroll
        for (int o = 128; o; o >>= 1) {
            if (tid < o) red[tid] += red[tid + o];
            __syncthreads();
        }
        float rstd = rsqrtf(red[0] * (1.f / 512.f) + 1e-5f);
        __syncthreads();
        float* shl = SM;
        float hl0 = d0 * rstd * s1[tid] + b1[tid];
        float hl1 = d1 * rstd * s1[tid + 256] + b1[tid + 256];
        shl[tid] = hl0;
        shl[tid + 256] = hl1;
        if (bid == 0) {
            g_hl[tid] = hl0;
            g_hl[tid + 256] = hl1;
        }
        __syncthreads();
        int j0 = bid * 32;
        float a0 = 0.f, a1 = 0.f;
#pragma unroll
        for (int j = 0; j < 32; j++) {
            float h = shl[j0 + j];
            a0 = fmaf(h, Wq[(size_t)(j0 + j) * 512 + tid], a0);
            a1 = fmaf(h, Wq[(size_t)(j0 + j) * 512 + tid + 256], a1);
        }
        g_qpart[bid][tid] = a0;
        g_qpart[bid][tid + 256] = a1;
        __threadfence();
        __syncthreads();
        if (tid == 0) {
            if (atomicAdd(&g_ctA, 1u) == 15) {
                g_ctA = 0;
                __threadfence();
                g_relA = base + 1;
            }
        }
        // --- prefetch weights into L2 ---
        {
            int pw = bid * 256 + tid;
            float acc = 0.f;
            const float4* a1p = (const float4*)Wv;
            const float4* a2p = (const float4*)Wo;
            const float4* a3p = (const float4*)W1;
            const float4* a4p = (const float4*)W2;
#pragma unroll 2
            for (int i = pw; i < 65536; i += 20480) acc += __ldg(a1p + i).x + __ldg(a2p + i).x;
#pragma unroll 4
            for (int i = pw; i < 262144; i += 20480) acc += __ldg(a3p + i).x + __ldg(a4p + i).x;
            if (acc == 1.2345e30f) g_dummy = acc;
        }
    } else if (bid < 80) {
        // --- wait q partials ---
        if (tid == 0) {
            while ((unsigned)(g_relA - base) < 1u) __nanosleep(32);
            __threadfence();
        }
        __syncthreads();
        // --- combine q; gs rows; C partials ---
        float* sq = SM;
        float q0 = bq[tid], q1 = bq[tid + 256];
#pragma unroll
        for (int s = 0; s < 16; s++) {
            q0 += g_qpart[s][tid];
            q1 += g_qpart[s][tid + 256];
        }
        sq[tid] = q0;
        sq[tid + 256] = q1;
        __syncthreads();
        int r = (bid - 16) * 8 + wid;
        const float4* wr = (const float4*)(Wk + (size_t)r * 512);
        const float4* q4 = (const float4*)sq;
        float dt[4];
#pragma unroll
        for (int t = 0; t < 4; t++) {
            float4 w = __ldg(wr + lane + 32 * t);
            float4 q = q4[lane + 32 * t];
            dt[t] = w.x * q.x + w.y * q.y + w.z * q.z + w.w * q.w;
        }
#pragma unroll
        for (int t = 0; t < 4; t++) dt[t] = wred(dt[t]);
        float* cred = SM + 512;  // [8][12]
        if (lane == 0) {
            float sr = s1[r], br = b1[r], hr = g_hl[r];
#pragma unroll
            for (int t = 0; t < 4; t++) {
                g_gs[t][r] = dt[t] * sr;
                cred[wid * 12 + t] = sr * dt[t];
                cred[wid * 12 + 4 + t] = br * dt[t];
                cred[wid * 12 + 8 + t] = hr * dt[t];
            }
        }
        __syncthreads();
        if (tid < 12) {
            float c = 0.f;
#pragma unroll
            for (int w = 0; w < 8; w++) c += cred[w * 12 + tid];
            g_cpart[bid - 16][tid] = c;
        }
        __threadfence();
        __syncthreads();
        if (tid == 0) s_last = (atomicAdd(&g_ctB, 1u) == 63) ? 1 : 0;
        __syncthreads();
        if (s_last) {
            if (tid < 12) {
                float c = 0.f;
#pragma unroll
                for (int j = 0; j < 64; j++) c += g_cpart[j][tid];
                g_C[tid] = c;
            }
            __threadfence();
            __syncthreads();
            if (tid == 0) {
                g_ctB = 0;
                __threadfence();
                g_relB = base + 1;
            }
        }
        // --- prefetch weights ---
        {
            int pw = bid * 256 + tid;
            float acc = 0.f;
            const float4* a1p = (const float4*)Wv;
            const float4* a2p = (const float4*)Wo;
            const float4* a3p = (const float4*)W1;
            const float4* a4p = (const float4*)W2;
#pragma unroll 2
            for (int i = pw; i < 65536; i += 20480) acc += __ldg(a1p + i).x + __ldg(a2p + i).x;
#pragma unroll 4
            for (int i = pw; i < 262144; i += 20480) acc += __ldg(a3p + i).x + __ldg(a4p + i).x;
            if (acc == 1.2345e30f) g_dummy = acc;
        }
    } else {
        // --- prefetch x into L2 while prologue runs (2-row batches, MLP 8) ---
        int pw = (bid - 80) * 8 + wid;  // 0..1407
        float acc = 0.f;
        for (int rr = pw; rr < 8192; rr += 1408) {
            int r = rr * 2;  // even -> r and r+1 share the same batch
            int bA = r >> 9, kA = r & 511;
            int L = __ldg(&mask[bA]);
            bool vA = kA < L, vB = (kA + 1) < L;
            const float4* xr = (const float4*)(x + (size_t)r * 512);
            if (vA) {
#pragma unroll
                for (int t = 0; t < 4; t++) acc += __ldg(xr + lane + 32 * t).x;
            }
            if (vB) {
#pragma unroll
                for (int t = 0; t < 4; t++) acc += __ldg(xr + 128 + lane + 32 * t).x;
            }
        }
        if (acc == 1.2345e30f) g_dummy = acc;
    }
    // --- all blocks: wait gs/C ready ---
    if (tid == 0) {
        while ((unsigned)(g_relB - base) < 1u) __nanosleep(32);
        __threadfence();
    }
    __syncthreads();
    // --- load gs + C to smem ---
    for (int i = tid; i < 2048; i += NT) SM[i] = ((const float*)g_gs)[i];
    if (tid < 12) SM[2048 + tid] = g_C[tid];
    __syncthreads();
    {
        const float4* sgs4 = (const float4*)SM;
        float C1[4], C2[4];
#pragma unroll
        for (int h = 0; h < 4; h++) {
            C1[h] = SM[2048 + h];
            C2[h] = SM[2052 + h];
        }
        int half = tid >> 7, t128 = tid & 127, w = t128 >> 5;
        float* sS = SM + 2064 + half * 464;  // sc[128], al[32], be[32], w[128], e[128]
        int nbar = 1 + half;
        // ---- task loop: each task = one (b, ks) split, processed end-to-end ----
        while (true) {
            if (t128 == 0) s_task[half] = (int)atomicAdd(&g_task, 1u);
            asm volatile("bar.sync %0, 128;" ::"r"(nbar));
            int t = s_task[half];
            if (t >= 512) break;
            int ks = t & 15, b = t >> 4;
            int L = __ldg(&mask[b]);
            int k0 = ks * 32;
            // --- score pass: each warp 8 rows, 2-batched; stats inline ---
#pragma unroll 1
            for (int it = 0; it < 4; it++) {
                int kl = w * 8 + it * 2;
                int kg = k0 + kl;
                bool v0 = kg < L, v1 = kg + 1 < L;
                const float4* xr0 = (const float4*)(x + ((size_t)b * 512 + kg) * 512);
                float4 xa[4], xc[4];
#pragma unroll
                for (int tt = 0; tt < 4; tt++) xa[tt] = make_float4(0.f, 0.f, 0.f, 0.f);
#pragma unroll
                for (int tt = 0; tt < 4; tt++) xc[tt] = make_float4(0.f, 0.f, 0.f, 0.f);
                if (v0) {
#pragma unroll
                    for (int tt = 0; tt < 4; tt++) xa[tt] = __ldg(xr0 + lane + 32 * tt);
                }
                if (v1) {
#pragma unroll
                    for (int tt = 0; tt < 4; tt++) xc[tt] = __ldg(xr0 + 128 + lane + 32 * tt);
                }
                float ssA = 0.f, smA = 0.f, ssB = 0.f, smB = 0.f;
#pragma unroll
                for (int tt = 0; tt < 4; tt++) {
                    ssA += xa[tt].x * xa[tt].x + xa[tt].y * xa[tt].y + xa[tt].z * xa[tt].z +
                           xa[tt].w * xa[tt].w;
                    smA += xa[tt].x + xa[tt].y + xa[tt].z + xa[tt].w;
                    ssB += xc[tt].x * xc[tt].x + xc[tt].y * xc[tt].y + xc[tt].z * xc[tt].z +
                           xc[tt].w * xc[tt].w;
                    smB += xc[tt].x + xc[tt].y + xc[tt].z + xc[tt].w;
                }
                float dA[4], dB[4];
#pragma unroll
                for (int h = 0; h < 4; h++) {
                    float aA = 0.f, aB = 0.f;
#pragma unroll
                    for (int tt = 0; tt < 4; tt++) {
                        float4 g = sgs4[h * 128 + lane + 32 * tt];
                        aA += xa[tt].x * g.x + xa[tt].y * g.y + xa[tt].z * g.z + xa[tt].w * g.w;
                        aB += xc[tt].x * g.x + xc[tt].y * g.y + xc[tt].z * g.z + xc[tt].w * g.w;
                    }
                    dA[h] = wred(aA);
                    dB[h] = wred(aB);
                }
                ssA = wred(ssA);
                smA = wred(smA);
                ssB = wred(ssB);
                smB = wred(smB);
                if (lane == 0) {
                    float al0 = 0.f, be0 = 0.f, al1 = 0.f, be1 = 0.f;
                    if (v0) {
                        float inv = 1.f / fmaxf(sqrtf(ssA), 1e-12f);
                        float m = smA * inv * (1.f / 512.f);
                        float v = ssA * inv * inv * (1.f / 512.f) - m * m;
                        float rs = rsqrtf(v + 1e-5f);
                        al0 = inv * rs;
                        be0 = -m * rs;
                    }
                    if (v1) {
                        float inv = 1.f / fmaxf(sqrtf(ssB), 1e-12f);
                        float m = smB * inv * (1.f / 512.f);
                        float v = ssB * inv * inv * (1.f / 512.f) - m * m;
                        float rs = rsqrtf(v + 1e-5f);
                        al1 = inv * rs;
                        be1 = -m * rs;
                    }
#pragma unroll
                    for (int h = 0; h < 4; h++) {
                        sS[kl * 4 + h] =
                            v0 ? SCALE * (al0 * dA[h] + be0 * C1[h] + C2[h]) : -1e30f;
                        sS[(kl + 1) * 4 + h] =
                            v1 ? SCALE * (al1 * dB[h] + be1 * C1[h] + C2[h]) : -1e30f;
                    }
                    sS[128 + kl] = al0;
                    sS[128 + kl + 1] = al1;
                    sS[160 + kl] = be0;
                    sS[160 + kl + 1] = be1;
                }
            }
            asm volatile("bar.sync %0, 128;" ::"r"(nbar));
            // --- e/w compute: thread (k,h) ---
            {
                int k = t128 >> 2, h = t128 & 3;
                float m = -1e30f;
#pragma unroll 8
                for (int j = 0; j < 32; j++) m = fmaxf(m, sS[j * 4 + h]);
                float e = __expf(sS[k * 4 + h] - m);
                sS[320 + k * 4 + h] = e;
                sS[192 + k * 4 + h] = e * sS[128 + k];
                if (k == 0) g_pm[ks][b][h] = m;
            }
            asm volatile("bar.sync %0, 128;" ::"r"(nbar));
            // --- A accumulate (x rows warm in L1) ---
            int kv = L - k0;
            kv = kv < 0 ? 0 : (kv > 32 ? 32 : kv);
            float4 A0 = {0, 0, 0, 0}, A1 = A0, A2 = A0, A3 = A0;
            const float4* xb4 = (const float4*)(x + ((size_t)b * 512 + k0) * 512);
#pragma unroll 4
            for (int k = 0; k < kv; k++) {
                float4 w4 = *(const float4*)&sS[192 + k * 4];
                float4 xv = __ldg(xb4 + (size_t)k * 128 + t128);
                A0.x = fmaf(w4.x, xv.x, A0.x); A0.y = fmaf(w4.x, xv.y, A0.y);
                A0.z = fmaf(w4.x, xv.z, A0.z); A0.w = fmaf(w4.x, xv.w, A0.w);
                A1.x = fmaf(w4.y, xv.x, A1.x); A1.y = fmaf(w4.y, xv.y, A1.y);
                A1.z = fmaf(w4.y, xv.z, A1.z); A1.w = fmaf(w4.y, xv.w, A1.w);
                A2.x = fmaf(w4.z, xv.x, A2.x); A2.y = fmaf(w4.z, xv.y, A2.y);
                A2.z = fmaf(w4.z, xv.z, A2.z); A2.w = fmaf(w4.z, xv.w, A2.w);
                A3.x = fmaf(w4.w, xv.x, A3.x); A3.y = fmaf(w4.w, xv.y, A3.y);
                A3.z = fmaf(w4.w, xv.z, A3.z); A3.w = fmaf(w4.w, xv.w, A3.w);
            }
            int i = t128 * 4;
            *(float4*)&g_ppart[ks][b][0][i] = A0;
            *(float4*)&g_ppart[ks][b][1][i] = A1;
            *(float4*)&g_ppart[ks][b][2][i] = A2;
            *(float4*)&g_ppart[ks][b][3][i] = A3;
            if (t128 < 4) {
                float se = 0.f, ewb = 0.f;
#pragma unroll 8
                for (int k = 0; k < 32; k++) {
                    float e = sS[320 + k * 4 + t128];
                    se += e;
                    ewb += e * sS[160 + k];
                }
                g_pse[ks][b][t128] = se;
                g_pewb[ks][b][t128] = ewb;
            }
            asm volatile("bar.sync %0, 128;" ::"r"(nbar));
        }
    }
    // ---- barrier 1 (leader also resets task counter) ----
    __syncthreads();
    if (tid == 0) {
        __threadfence();
        if (atomicAdd(&g_count, 1u) == NB - 1) {
            g_count = 0;
            g_task = 0;
            __threadfence();
            g_release = base + 1;
        } else {
            while ((unsigned)(g_release - base) < 1u) __nanosleep(32);
            __threadfence();
        }
    }
    __syncthreads();

    // ============ T1': init h1; combine scalars + rescale + p @ Wv (512 vblocks) ============
    {
        // init h1 = token + bo (finalized by T2's atomics)
        if (tid < 64) {
            int idx = bid * 64 + tid;
            g_h1[idx >> 9][idx & 511] = token[idx & 511] + bo[idx & 511];
        }
        int half = tid >> 7, t128 = tid & 127;
        int vb = bid * 2 + half;
        int bh = vb & 3, hh = (vb >> 2) & 3, iy = vb >> 4;  // iy 0..31
        int i0 = iy * 16, f = hh * 128 + t128;
        float* sb = SM + half * 160;
        float* sp = SM + 320 + half * 128;
        if (t128 < 8) {
            int gb = bh * 8 + t128;
            float scls = SCALE * g_C[8 + hh];
            float ms[16];
            float M = scls;
#pragma unroll
            for (int s = 0; s < 16; s++) {
                ms[s] = g_pm[s][gb][hh];
                M = fmaxf(M, ms[s]);
            }
            float Se = 0.f, Ewb = 0.f;
#pragma unroll
            for (int s = 0; s < 16; s++) {
                float fs = __expf(ms[s] - M);
                sb[t128 * 16 + s] = fs;
                Se += fs * g_pse[s][gb][hh];
                Ewb += fs * g_pewb[s][gb][hh];
            }
            float ecls = __expf(scls - M);
            sb[128 + t128] = 1.f / (Se + ecls);
            sb[136 + t128] = Se;
            sb[144 + t128] = Ewb;
            sb[152 + t128] = ecls;
        }
        __syncthreads();
        {
            int bl = t128 >> 4, ii = t128 & 15;
            int gb = bh * 8 + bl;
            int i = i0 + ii;
            float A = 0.f;
#pragma unroll
            for (int s = 0; s < 16; s++) A = fmaf(sb[bl * 16 + s], g_ppart[s][gb][hh][i], A);
            sp[t128] = sb[128 + bl] *
                       (s1[i] * (A + sb[144 + bl]) + b1[i] * sb[136 + bl] + sb[152 + bl] * g_hl[i]);
        }
        __syncthreads();
        float acc[8];
#pragma unroll
        for (int bl = 0; bl < 8; bl++) acc[bl] = 0.f;
#pragma unroll
        for (int ii = 0; ii < 16; ii += 4) {
            int i = i0 + ii;
            float w0 = Wv[(size_t)i * 512 + f];
            float w1 = Wv[(size_t)(i + 1) * 512 + f];
            float w2 = Wv[(size_t)(i + 2) * 512 + f];
            float w3 = Wv[(size_t)(i + 3) * 512 + f];
#pragma unroll
            for (int bl = 0; bl < 8; bl++) {
                float4 p = *(const float4*)&sp[bl * 16 + ii];
                acc[bl] = fmaf(p.x, w0, fmaf(p.y, w1, fmaf(p.z, w2, fmaf(p.w, w3, acc[bl]))));
            }
        }
#pragma unroll
        for (int bl = 0; bl < 8; bl++) g_ctxpart[iy][bh * 8 + bl][f] = acc[bl];
    }
    gridbar(base, 2);

    // ============ T2: o = (ctx+bv) @ Wo, atomic-accumulate into h1 (512 vblocks) ============
    {
        int half = tid >> 7, t128 = tid & 127;
        int vb = bid * 2 + half;
        int bh = vb & 3, cx = (vb >> 2) & 3, iy = vb >> 4;
        int i0 = iy * 16, f = cx * 128 + t128;
        float* sc = SM + half * 128;
        {
            int bl = t128 >> 4, ii = t128 & 15;
            int gb = bh * 8 + bl;
            int i = i0 + ii;
            float v = bv[i];
#pragma unroll
            for (int s = 0; s < 32; s++) v += g_ctxpart[s][gb][i];
            sc[t128] = v;
        }
        __syncthreads();
        float acc[8];
#pragma unroll
        for (int bl = 0; bl < 8; bl++) acc[bl] = 0.f;
#pragma unroll
        for (int ii = 0; ii < 16; ii += 4) {
            int i = i0 + ii;
            float w0 = Wo[(size_t)i * 512 + f];
            float w1 = Wo[(size_t)(i + 1) * 512 + f];
            float w2 = Wo[(size_t)(i + 2) * 512 + f];
            float w3 = Wo[(size_t)(i + 3) * 512 + f];
#pragma unroll
            for (int bl = 0; bl < 8; bl++) {
                float4 p = *(const float4*)&sc[bl * 16 + ii];
                acc[bl] = fmaf(p.x, w0, fmaf(p.y, w1, fmaf(p.z, w2, fmaf(p.w, w3, acc[bl]))));
            }
        }
#pragma unroll
        for (int bl = 0; bl < 8; bl++) atomicAdd(&g_h1[bh * 8 + bl][f], acc[bl]);
    }
    gridbar(base, 3);

    // ============ T4: inline LN2 stats + W1 partials (512 vblocks); init out ============
    {
        // init out = h1 + b2o (h1 final after barrier 3)
        if (tid < 64) {
            int idx = bid * 64 + tid;
            out[idx] = g_h1[idx >> 9][idx & 511] + b2o[idx & 511];
        }
        int half = tid >> 7, t128 = tid & 127;
        int vb = bid * 2 + half;  // 0..511
        int fx = vb & 15, bh = (vb >> 4) & 3, iy = vb >> 6;  // iy 0..7
        int i0 = iy * 64, f = fx * 128 + t128;
        float* sh2 = SM + half * 512;        // [8 b][64 i]
        float* sln = SM + 1024 + half * 16;  // [8 b][2]
        // inline LN2 stats (16 threads per batch)
        {
            int bl = t128 >> 4, sub = t128 & 15;
            int b = bh * 8 + bl;
            const float4* hb = (const float4*)g_h1[b];
            float sum = 0.f, ssq = 0.f;
#pragma unroll
            for (int j = 0; j < 8; j++) {
                float4 v = hb[sub * 8 + j];
                sum += v.x + v.y + v.z + v.w;
                ssq += v.x * v.x + v.y * v.y + v.z * v.z + v.w * v.w;
            }
#pragma unroll
            for (int o = 8; o; o >>= 1) {
                sum += __shfl_xor_sync(0xffffffffu, sum, o);
                ssq += __shfl_xor_sync(0xffffffffu, ssq, o);
            }
            if (sub == 0) {
                float m = sum * (1.f / 512.f);
                float var = ssq * (1.f / 512.f) - m * m;
                sln[bl * 2] = m;
                sln[bl * 2 + 1] = rsqrtf(var + 1e-5f);
            }
        }
        __syncthreads();
#pragma unroll
        for (int j = 0; j < 4; j++) {
            int idx = t128 + j * 128;
            int bl = idx >> 6, ii = idx & 63;
            int b = bh * 8 + bl, i = i0 + ii;
            sh2[idx] = (g_h1[b][i] - sln[bl * 2]) * sln[bl * 2 + 1] * s2[i] + b2l[i];
        }
        __syncthreads();
        float acc[8];
#pragma unroll
        for (int bl = 0; bl < 8; bl++) acc[bl] = 0.f;
#pragma unroll 4
        for (int ii = 0; ii < 64; ii += 4) {
            int i = i0 + ii;
            float w0 = W1[(size_t)i * 2048 + f];
            float w1 = W1[(size_t)(i + 1) * 2048 + f];
            float w2 = W1[(size_t)(i + 2) * 2048 + f];
            float w3 = W1[(size_t)(i + 3) * 2048 + f];
#pragma unroll
            for (int bl = 0; bl < 8; bl++) {
                float4 p = *(const float4*)&sh2[bl * 64 + ii];
                acc[bl] = fmaf(p.x, w0, fmaf(p.y, w1, fmaf(p.z, w2, fmaf(p.w, w3, acc[bl]))));
            }
        }
#pragma unroll
        for (int bl = 0; bl < 8; bl++) g_w1part[iy][bh * 8 + bl][f] = acc[bl];
    }
    gridbar(base, 4);

    // ============ T5: gelu + W2, atomic-accumulate into out (512 vblocks) ============
    {
        int half = tid >> 7, t128 = tid & 127;
        int vb = bid * 2 + half;  // 0..511
        int fx = vb & 3, bh = (vb >> 2) & 7, iy = vb >> 5;  // iy 0..15
        int i0 = iy * 128, f = fx * 128 + t128;
        float* su = SM + half * 512;  // [4 b][128 i]
        {
#pragma unroll
            for (int j = 0; j < 4; j++) {
                int idx = t128 + j * 128;
                int bl = idx >> 7, ii = idx & 127;
                int b = bh * 4 + bl, i = i0 + ii;
                float u = b1f[i];
#pragma unroll
                for (int s = 0; s < 8; s++) u += g_w1part[s][b][i];
                su[idx] = geluf(u);
            }
        }
        __syncthreads();
        float acc[4];
#pragma unroll
        for (int bl = 0; bl < 4; bl++) acc[bl] = 0.f;
#pragma unroll 4
        for (int ii = 0; ii < 128; ii += 4) {
            int i = i0 + ii;
            float w0 = W2[(size_t)i * 512 + f];
            float w1 = W2[(size_t)(i + 1) * 512 + f];
            float w2 = W2[(size_t)(i + 2) * 512 + f];
            float w3 = W2[(size_t)(i + 3) * 512 + f];
#pragma unroll
            for (int bl = 0; bl < 4; bl++) {
                float4 p = *(const float4*)&su[bl * 128 + ii];
                acc[bl] = fmaf(p.x, w0, fmaf(p.y, w1, fmaf(p.z, w2, fmaf(p.w, w3, acc[bl]))));
            }
        }
#pragma unroll
        for (int bl = 0; bl < 4; bl++) atomicAdd(&out[(bh * 4 + bl) * 512 + f], acc[bl]);
    }
}

extern "C" void kernel_launch(void* const* d_in, const int* in_sizes, int n_in,
                              void* d_out, int out_size) {
    const float* x     = (const float*)d_in[0];
    const int*   mask  = (const int*)d_in[1];
    const float* token = (const float*)d_in[2];
    const float* Wq    = (const float*)d_in[3];
    const float* bq    = (const float*)d_in[4];
    const float* Wk    = (const float*)d_in[5];
    // d_in[6] = bk: uniform shift across keys -> cancels in softmax; unused
    const float* Wv    = (const float*)d_in[7];
    const float* bv    = (const float*)d_in[8];
    const float* Wo    = (const float*)d_in[9];
    const float* bo    = (const float*)d_in[10];
    const float* s1    = (const float*)d_in[11];
    const float* b1    = (const float*)d_in[12];
    const float* s2    = (const float*)d_in[13];
    const float* b2l   = (const float*)d_in[14];
    const float* W1    = (const float*)d_in[15];
    const float* b1f   = (const float*)d_in[16];
    const float* W2    = (const float*)d_in[17];
    const float* b2o   = (const float*)d_in[18];
    float* out = (float*)d_out;

    fused_kernel<<<NB, NT>>>(x, mask, token, Wq, bq, Wk, Wv, bv, Wo, bo,
                             s1, b1, s2, b2l, W1, b1f, W2, b2o, out);
}

// round 13
// speedup vs baseline: 2.3988x; 1.0191x over previous
#include <cuda_runtime.h>
#include <math.h>

#define SCALE 0.08838834764831845f  // 1/sqrt(128)
#define NB 256
#define NT 256

typedef unsigned long long ull;

// ---------------- f32x2 packed helpers (sm_100a) ----------------
__device__ __forceinline__ ull pk(float lo, float hi) {
    ull r;
    asm("mov.b64 %0,{%1,%2};" : "=l"(r) : "f"(lo), "f"(hi));
    return r;
}
__device__ __forceinline__ float2 upk(ull v) {
    float2 r;
    asm("mov.b64 {%0,%1},%2;" : "=f"(r.x), "=f"(r.y) : "l"(v));
    return r;
}
__device__ __forceinline__ void fma2(ull& d, ull a, ull b) {
    asm("fma.rn.f32x2 %0,%1,%2,%0;" : "+l"(d) : "l"(a), "l"(b));
}
__device__ __forceinline__ void add2(ull& d, ull a) {
    asm("add.rn.f32x2 %0,%1,%0;" : "+l"(d) : "l"(a));
}

// ---------------- sync state (epoch-based; graph-replay safe) ----------------
__device__ unsigned g_count;
__device__ volatile unsigned g_release;
__device__ unsigned g_ctA;
__device__ volatile unsigned g_relA;
__device__ unsigned g_ctB;
__device__ volatile unsigned g_relB;
__device__ unsigned g_task;
__device__ float g_dummy;

// ---------------- scratch ----------------
__device__ __align__(16) float g_hl[512];
__device__ __align__(16) float g_qpart[16][512];
__device__ __align__(16) float g_gs[4][512];
__device__ __align__(16) float g_cpart[64][12];
__device__ __align__(16) float g_C[12];
__device__ __align__(16) float g_pm[16][32][4];
__device__ __align__(16) float g_pse[16][32][4];
__device__ __align__(16) float g_pewb[16][32][4];
__device__ __align__(16) float g_ppart[16][32][4][512];
__device__ __align__(16) float g_ctxpart[32][32][512];
__device__ __align__(16) float g_h1[32][512];
__device__ __align__(16) float g_w1part[8][32][2048];

static __device__ __forceinline__ float wred(float v) {
#pragma unroll
    for (int o = 16; o; o >>= 1) v += __shfl_xor_sync(0xffffffffu, v, o);
    return v;
}

static __device__ __forceinline__ float geluf(float t) {
    float t3 = t * t * t;
    return 0.5f * t * (1.f + tanhf(0.7978845608028654f * (t + 0.044715f * t3)));
}

__device__ __forceinline__ void gridbar(unsigned base, unsigned idx) {
    __syncthreads();
    if (threadIdx.x == 0) {
        __threadfence();
        if (atomicAdd(&g_count, 1u) == NB - 1) {
            g_count = 0;
            __threadfence();
            g_release = base + idx;
        } else {
            while ((unsigned)(g_release - base) < idx) __nanosleep(32);
            __threadfence();
        }
    }
    __syncthreads();
}

__global__ void __launch_bounds__(NT, 2) fused_kernel(
    const float* __restrict__ x, const int* __restrict__ mask,
    const float* __restrict__ token,
    const float* __restrict__ Wq, const float* __restrict__ bq,
    const float* __restrict__ Wk,
    const float* __restrict__ Wv, const float* __restrict__ bv,
    const float* __restrict__ Wo, const float* __restrict__ bo,
    const float* __restrict__ s1, const float* __restrict__ b1,
    const float* __restrict__ s2, const float* __restrict__ b2l,
    const float* __restrict__ W1, const float* __restrict__ b1f,
    const float* __restrict__ W2, const float* __restrict__ b2o,
    float* __restrict__ out) {
    __shared__ float SM[3072];
    __shared__ unsigned s_base_sh;
    __shared__ int s_last;
    __shared__ int s_task[2];
    int tid = threadIdx.x;
    int bid = blockIdx.x;
    int wid = tid >> 5, lane = tid & 31;
    if (tid == 0) s_base_sh = g_release;
    __syncthreads();
    unsigned base = s_base_sh;

    // ================= PHASE I: prologue (flag-synced) + split task loop =================
    if (bid < 16) {
        // --- token LN + q partials ---
        float t0 = token[tid], t1 = token[tid + 256];
        float* red = SM;
        red[tid] = t0 + t1;
        __syncthreads();
#pragma unroll
        for (int o = 128; o; o >>= 1) {
            if (tid < o) red[tid] += red[tid + o];
            __syncthreads();
        }
        float mean = red[0] * (1.f / 512.f);
        __syncthreads();
        float d0 = t0 - mean, d1 = t1 - mean;
        red[tid] = d0 * d0 + d1 * d1;
        __syncthreads();
#pragma unroll
        for (int o = 128; o; o >>= 1) {
            if (tid < o) red[tid] += red[tid + o];
            __syncthreads();
        }
        float rstd = rsqrtf(red[0] * (1.f / 512.f) + 1e-5f);
        __syncthreads();
        float* shl = SM;
        float hl0 = d0 * rstd * s1[tid] + b1[tid];
        float hl1 = d1 * rstd * s1[tid + 256] + b1[tid + 256];
        shl[tid] = hl0;
        shl[tid + 256] = hl1;
        if (bid == 0) {
            g_hl[tid] = hl0;
            g_hl[tid + 256] = hl1;
        }
        __syncthreads();
        int j0 = bid * 32;
        float a0 = 0.f, a1 = 0.f;
#pragma unroll
        for (int j = 0; j < 32; j++) {
            float h = shl[j0 + j];
            a0 = fmaf(h, Wq[(size_t)(j0 + j) * 512 + tid], a0);
            a1 = fmaf(h, Wq[(size_t)(j0 + j) * 512 + tid + 256], a1);
        }
        g_qpart[bid][tid] = a0;
        g_qpart[bid][tid + 256] = a1;
        __threadfence();
        __syncthreads();
        if (tid == 0) {
            if (atomicAdd(&g_ctA, 1u) == 15) {
                g_ctA = 0;
                __threadfence();
                g_relA = base + 1;
            }
        }
        // --- prefetch weights into L2 ---
        {
            int pw = bid * 256 + tid;
            float acc = 0.f;
            const float4* a1p = (const float4*)Wv;
            const float4* a2p = (const float4*)Wo;
            const float4* a3p = (const float4*)W1;
            const float4* a4p = (const float4*)W2;
#pragma unroll 2
            for (int i = pw; i < 65536; i += 20480) acc += __ldg(a1p + i).x + __ldg(a2p + i).x;
#pragma unroll 4
            for (int i = pw; i < 262144; i += 20480) acc += __ldg(a3p + i).x + __ldg(a4p + i).x;
            if (acc == 1.2345e30f) g_dummy = acc;
        }
    } else if (bid < 80) {
        // --- wait q partials ---
        if (tid == 0) {
            while ((unsigned)(g_relA - base) < 1u) __nanosleep(32);
            __threadfence();
        }
        __syncthreads();
        // --- combine q; gs rows; C partials ---
        float* sq = SM;
        float q0 = bq[tid], q1 = bq[tid + 256];
#pragma unroll
        for (int s = 0; s < 16; s++) {
            q0 += g_qpart[s][tid];
            q1 += g_qpart[s][tid + 256];
        }
        sq[tid] = q0;
        sq[tid + 256] = q1;
        __syncthreads();
        int r = (bid - 16) * 8 + wid;
        const float4* wr = (const float4*)(Wk + (size_t)r * 512);
        const float4* q4 = (const float4*)sq;
        float dt[4];
#pragma unroll
        for (int t = 0; t < 4; t++) {
            float4 w = __ldg(wr + lane + 32 * t);
            float4 q = q4[lane + 32 * t];
            dt[t] = w.x * q.x + w.y * q.y + w.z * q.z + w.w * q.w;
        }
#pragma unroll
        for (int t = 0; t < 4; t++) dt[t] = wred(dt[t]);
        float* cred = SM + 512;  // [8][12]
        if (lane == 0) {
            float sr = s1[r], br = b1[r], hr = g_hl[r];
#pragma unroll
            for (int t = 0; t < 4; t++) {
                g_gs[t][r] = dt[t] * sr;
                cred[wid * 12 + t] = sr * dt[t];
                cred[wid * 12 + 4 + t] = br * dt[t];
                cred[wid * 12 + 8 + t] = hr * dt[t];
            }
        }
        __syncthreads();
        if (tid < 12) {
            float c = 0.f;
#pragma unroll
            for (int w = 0; w < 8; w++) c += cred[w * 12 + tid];
            g_cpart[bid - 16][tid] = c;
        }
        __threadfence();
        __syncthreads();
        if (tid == 0) s_last = (atomicAdd(&g_ctB, 1u) == 63) ? 1 : 0;
        __syncthreads();
        if (s_last) {
            if (tid < 12) {
                float c = 0.f;
#pragma unroll
                for (int j = 0; j < 64; j++) c += g_cpart[j][tid];
                g_C[tid] = c;
            }
            __threadfence();
            __syncthreads();
            if (tid == 0) {
                g_ctB = 0;
                __threadfence();
                g_relB = base + 1;
            }
        }
        // --- prefetch weights ---
        {
            int pw = bid * 256 + tid;
            float acc = 0.f;
            const float4* a1p = (const float4*)Wv;
            const float4* a2p = (const float4*)Wo;
            const float4* a3p = (const float4*)W1;
            const float4* a4p = (const float4*)W2;
#pragma unroll 2
            for (int i = pw; i < 65536; i += 20480) acc += __ldg(a1p + i).x + __ldg(a2p + i).x;
#pragma unroll 4
            for (int i = pw; i < 262144; i += 20480) acc += __ldg(a3p + i).x + __ldg(a4p + i).x;
            if (acc == 1.2345e30f) g_dummy = acc;
        }
    } else {
        // --- prefetch x into L2 while prologue runs (2-row batches, MLP 8) ---
        int pw = (bid - 80) * 8 + wid;  // 0..1407
        float acc = 0.f;
        for (int rr = pw; rr < 8192; rr += 1408) {
            int r = rr * 2;
            int bA = r >> 9, kA = r & 511;
            int L = __ldg(&mask[bA]);
            bool vA = kA < L, vB = (kA + 1) < L;
            const float4* xr = (const float4*)(x + (size_t)r * 512);
            if (vA) {
#pragma unroll
                for (int t = 0; t < 4; t++) acc += __ldg(xr + lane + 32 * t).x;
            }
            if (vB) {
#pragma unroll
                for (int t = 0; t < 4; t++) acc += __ldg(xr + 128 + lane + 32 * t).x;
            }
        }
        if (acc == 1.2345e30f) g_dummy = acc;
    }
    // --- all blocks: wait gs/C ready ---
    if (tid == 0) {
        while ((unsigned)(g_relB - base) < 1u) __nanosleep(32);
        __threadfence();
    }
    __syncthreads();
    // --- load gs + C to smem ---
    for (int i = tid; i < 2048; i += NT) SM[i] = ((const float*)g_gs)[i];
    if (tid < 12) SM[2048 + tid] = g_C[tid];
    __syncthreads();
    {
        const ulonglong2* sgs2 = (const ulonglong2*)SM;
        float C1[4], C2[4];
#pragma unroll
        for (int h = 0; h < 4; h++) {
            C1[h] = SM[2048 + h];
            C2[h] = SM[2052 + h];
        }
        int half = tid >> 7, t128 = tid & 127, w = t128 >> 5;
        float* sS = SM + 2064 + half * 464;  // sc[128], al[32], be[32], w[128], e[128]
        int nbar = 1 + half;
        // ---- task loop: each task = one (b, ks) split, processed end-to-end ----
        while (true) {
            if (t128 == 0) s_task[half] = (int)atomicAdd(&g_task, 1u);
            asm volatile("bar.sync %0, 128;" ::"r"(nbar));
            int t = s_task[half];
            if (t >= 512) break;
            int ks = t & 15, b = t >> 4;
            int L = __ldg(&mask[b]);
            int k0 = ks * 32;
            if (k0 >= L) {
                // empty split: fs=exp(-1e30-M)=0 zeroes any stale g_ppart contribution
                if (t128 < 4) {
                    g_pm[ks][b][t128] = -1e30f;
                    g_pse[ks][b][t128] = 0.f;
                    g_pewb[ks][b][t128] = 0.f;
                }
                continue;
            }
            // --- score pass: each warp 8 rows, 2-batched; stats inline; f32x2 packed ---
#pragma unroll 1
            for (int it = 0; it < 4; it++) {
                int kl = w * 8 + it * 2;
                int kg = k0 + kl;
                bool v0 = kg < L, v1 = kg + 1 < L;
                const ulonglong2* xr0 = (const ulonglong2*)(x + ((size_t)b * 512 + kg) * 512);
                ulonglong2 xa[4], xc[4];
#pragma unroll
                for (int tt = 0; tt < 4; tt++) {
                    xa[tt].x = 0ull;
                    xa[tt].y = 0ull;
                    xc[tt].x = 0ull;
                    xc[tt].y = 0ull;
                }
                if (v0) {
#pragma unroll
                    for (int tt = 0; tt < 4; tt++) xa[tt] = __ldg(xr0 + lane + 32 * tt);
                }
                if (v1) {
#pragma unroll
                    for (int tt = 0; tt < 4; tt++) xc[tt] = __ldg(xr0 + 128 + lane + 32 * tt);
                }
                ull ssA2 = 0ull, smA2 = 0ull, ssB2 = 0ull, smB2 = 0ull;
#pragma unroll
                for (int tt = 0; tt < 4; tt++) {
                    fma2(ssA2, xa[tt].x, xa[tt].x);
                    fma2(ssA2, xa[tt].y, xa[tt].y);
                    add2(smA2, xa[tt].x);
                    add2(smA2, xa[tt].y);
                    fma2(ssB2, xc[tt].x, xc[tt].x);
                    fma2(ssB2, xc[tt].y, xc[tt].y);
                    add2(smB2, xc[tt].x);
                    add2(smB2, xc[tt].y);
                }
                ull dA2[4] = {0ull, 0ull, 0ull, 0ull};
                ull dB2[4] = {0ull, 0ull, 0ull, 0ull};
#pragma unroll
                for (int h = 0; h < 4; h++) {
#pragma unroll
                    for (int tt = 0; tt < 4; tt++) {
                        ulonglong2 g = sgs2[h * 128 + lane + 32 * tt];
                        fma2(dA2[h], xa[tt].x, g.x);
                        fma2(dA2[h], xa[tt].y, g.y);
                        fma2(dB2[h], xc[tt].x, g.x);
                        fma2(dB2[h], xc[tt].y, g.y);
                    }
                }
                float dA[4], dB[4];
#pragma unroll
                for (int h = 0; h < 4; h++) {
                    float2 pa = upk(dA2[h]);
                    dA[h] = wred(pa.x + pa.y);
                    float2 pb = upk(dB2[h]);
                    dB[h] = wred(pb.x + pb.y);
                }
                float2 u;
                u = upk(ssA2);
                float ssA = wred(u.x + u.y);
                u = upk(smA2);
                float smA = wred(u.x + u.y);
                u = upk(ssB2);
                float ssB = wred(u.x + u.y);
                u = upk(smB2);
                float smB = wred(u.x + u.y);
                if (lane == 0) {
                    float al0 = 0.f, be0 = 0.f, al1 = 0.f, be1 = 0.f;
                    if (v0) {
                        float inv = 1.f / fmaxf(sqrtf(ssA), 1e-12f);
                        float m = smA * inv * (1.f / 512.f);
                        float v = ssA * inv * inv * (1.f / 512.f) - m * m;
                        float rs = rsqrtf(v + 1e-5f);
                        al0 = inv * rs;
                        be0 = -m * rs;
                    }
                    if (v1) {
                        float inv = 1.f / fmaxf(sqrtf(ssB), 1e-12f);
                        float m = smB * inv * (1.f / 512.f);
                        float v = ssB * inv * inv * (1.f / 512.f) - m * m;
                        float rs = rsqrtf(v + 1e-5f);
                        al1 = inv * rs;
                        be1 = -m * rs;
                    }
#pragma unroll
                    for (int h = 0; h < 4; h++) {
                        sS[kl * 4 + h] =
                            v0 ? SCALE * (al0 * dA[h] + be0 * C1[h] + C2[h]) : -1e30f;
                        sS[(kl + 1) * 4 + h] =
                            v1 ? SCALE * (al1 * dB[h] + be1 * C1[h] + C2[h]) : -1e30f;
                    }
                    sS[128 + kl] = al0;
                    sS[128 + kl + 1] = al1;
                    sS[160 + kl] = be0;
                    sS[160 + kl + 1] = be1;
                }
            }
            asm volatile("bar.sync %0, 128;" ::"r"(nbar));
            // --- e/w compute: thread (k,h) ---
            {
                int k = t128 >> 2, h = t128 & 3;
                float m = -1e30f;
#pragma unroll 8
                for (int j = 0; j < 32; j++) m = fmaxf(m, sS[j * 4 + h]);
                float e = __expf(sS[k * 4 + h] - m);
                sS[320 + k * 4 + h] = e;
                sS[192 + k * 4 + h] = e * sS[128 + k];
                if (k == 0) g_pm[ks][b][h] = m;
            }
            asm volatile("bar.sync %0, 128;" ::"r"(nbar));
            // --- A accumulate (x rows warm in L1), f32x2 packed ---
            int kv = L - k0;
            kv = kv > 32 ? 32 : kv;
            ull A0a = 0ull, A0b = 0ull, A1a = 0ull, A1b = 0ull;
            ull A2a = 0ull, A2b = 0ull, A3a = 0ull, A3b = 0ull;
            const ulonglong2* xb2 = (const ulonglong2*)(x + ((size_t)b * 512 + k0) * 512);
#pragma unroll 4
            for (int k = 0; k < kv; k++) {
                float4 w4 = *(const float4*)&sS[192 + k * 4];
                ull wx = pk(w4.x, w4.x), wy = pk(w4.y, w4.y);
                ull wz = pk(w4.z, w4.z), ww = pk(w4.w, w4.w);
                ulonglong2 xv = __ldg(xb2 + (size_t)k * 128 + t128);
                fma2(A0a, wx, xv.x);
                fma2(A0b, wx, xv.y);
                fma2(A1a, wy, xv.x);
                fma2(A1b, wy, xv.y);
                fma2(A2a, wz, xv.x);
                fma2(A2b, wz, xv.y);
                fma2(A3a, ww, xv.x);
                fma2(A3b, ww, xv.y);
            }
            int i = t128 * 4;
            {
                ulonglong2 st;
                st.x = A0a; st.y = A0b;
                *(ulonglong2*)&g_ppart[ks][b][0][i] = st;
                st.x = A1a; st.y = A1b;
                *(ulonglong2*)&g_ppart[ks][b][1][i] = st;
                st.x = A2a; st.y = A2b;
                *(ulonglong2*)&g_ppart[ks][b][2][i] = st;
                st.x = A3a; st.y = A3b;
                *(ulonglong2*)&g_ppart[ks][b][3][i] = st;
            }
            if (t128 < 4) {
                float se = 0.f, ewb = 0.f;
#pragma unroll 8
                for (int k = 0; k < 32; k++) {
                    float e = sS[320 + k * 4 + t128];
                    se += e;
                    ewb += e * sS[160 + k];
                }
                g_pse[ks][b][t128] = se;
                g_pewb[ks][b][t128] = ewb;
            }
            asm volatile("bar.sync %0, 128;" ::"r"(nbar));
        }
    }
    // ---- barrier 1 (leader also resets task counter) ----
    __syncthreads();
    if (tid == 0) {
        __threadfence();
        if (atomicAdd(&g_count, 1u) == NB - 1) {
            g_count = 0;
            g_task = 0;
            __threadfence();
            g_release = base + 1;
        } else {
            while ((unsigned)(g_release - base) < 1u) __nanosleep(32);
            __threadfence();
        }
    }
    __syncthreads();

    // ============ T1': init h1; combine scalars + rescale + p @ Wv (512 vblocks) ============
    {
        // init h1 = token + bo (finalized by T2's atomics)
        if (tid < 64) {
            int idx = bid * 64 + tid;
            g_h1[idx >> 9][idx & 511] = token[idx & 511] + bo[idx & 511];
        }
        int half = tid >> 7, t128 = tid & 127;
        int vb = bid * 2 + half;
        int bh = vb & 3, hh = (vb >> 2) & 3, iy = vb >> 4;  // iy 0..31
        int i0 = iy * 16, f = hh * 128 + t128;
        float* sb = SM + half * 160;
        float* sp = SM + 320 + half * 128;
        if (t128 < 8) {
            int gb = bh * 8 + t128;
            float scls = SCALE * g_C[8 + hh];
            float ms[16];
            float M = scls;
#pragma unroll
            for (int s = 0; s < 16; s++) {
                ms[s] = g_pm[s][gb][hh];
                M = fmaxf(M, ms[s]);
            }
            float Se = 0.f, Ewb = 0.f;
#pragma unroll
            for (int s = 0; s < 16; s++) {
                float fs = __expf(ms[s] - M);
                sb[t128 * 16 + s] = fs;
                Se += fs * g_pse[s][gb][hh];
                Ewb += fs * g_pewb[s][gb][hh];
            }
            float ecls = __expf(scls - M);
            sb[128 + t128] = 1.f / (Se + ecls);
            sb[136 + t128] = Se;
            sb[144 + t128] = Ewb;
            sb[152 + t128] = ecls;
        }
        __syncthreads();
        {
            int bl = t128 >> 4, ii = t128 & 15;
            int gb = bh * 8 + bl;
            int i = i0 + ii;
            float A = 0.f;
#pragma unroll
            for (int s = 0; s < 16; s++) A = fmaf(sb[bl * 16 + s], g_ppart[s][gb][hh][i], A);
            sp[t128] = sb[128 + bl] *
                       (s1[i] * (A + sb[144 + bl]) + b1[i] * sb[136 + bl] + sb[152 + bl] * g_hl[i]);
        }
        __syncthreads();
        float acc[8];
#pragma unroll
        for (int bl = 0; bl < 8; bl++) acc[bl] = 0.f;
#pragma unroll
        for (int ii = 0; ii < 16; ii += 4) {
            int i = i0 + ii;
            float w0 = Wv[(size_t)i * 512 + f];
            float w1 = Wv[(size_t)(i + 1) * 512 + f];
            float w2 = Wv[(size_t)(i + 2) * 512 + f];
            float w3 = Wv[(size_t)(i + 3) * 512 + f];
#pragma unroll
            for (int bl = 0; bl < 8; bl++) {
                float4 p = *(const float4*)&sp[bl * 16 + ii];
                acc[bl] = fmaf(p.x, w0, fmaf(p.y, w1, fmaf(p.z, w2, fmaf(p.w, w3, acc[bl]))));
            }
        }
#pragma unroll
        for (int bl = 0; bl < 8; bl++) g_ctxpart[iy][bh * 8 + bl][f] = acc[bl];
    }
    gridbar(base, 2);

    // ============ T2: o = (ctx+bv) @ Wo, atomic-accumulate into h1 (512 vblocks) ============
    {
        int half = tid >> 7, t128 = tid & 127;
        int vb = bid * 2 + half;
        int bh = vb & 3, cx = (vb >> 2) & 3, iy = vb >> 4;
        int i0 = iy * 16, f = cx * 128 + t128;
        float* sc = SM + half * 128;
        {
            int bl = t128 >> 4, ii = t128 & 15;
            int gb = bh * 8 + bl;
            int i = i0 + ii;
            float v = bv[i];
#pragma unroll
            for (int s = 0; s < 32; s++) v += g_ctxpart[s][gb][i];
            sc[t128] = v;
        }
        __syncthreads();
        float acc[8];
#pragma unroll
        for (int bl = 0; bl < 8; bl++) acc[bl] = 0.f;
#pragma unroll
        for (int ii = 0; ii < 16; ii += 4) {
            int i = i0 + ii;
            float w0 = Wo[(size_t)i * 512 + f];
            float w1 = Wo[(size_t)(i + 1) * 512 + f];
            float w2 = Wo[(size_t)(i + 2) * 512 + f];
            float w3 = Wo[(size_t)(i + 3) * 512 + f];
#pragma unroll
            for (int bl = 0; bl < 8; bl++) {
                float4 p = *(const float4*)&sc[bl * 16 + ii];
                acc[bl] = fmaf(p.x, w0, fmaf(p.y, w1, fmaf(p.z, w2, fmaf(p.w, w3, acc[bl]))));
            }
        }
#pragma unroll
        for (int bl = 0; bl < 8; bl++) atomicAdd(&g_h1[bh * 8 + bl][f], acc[bl]);
    }
    gridbar(base, 3);

    // ============ T4: inline LN2 stats + W1 partials (512 vblocks); init out ============
    {
        // init out = h1 + b2o (h1 final after barrier 3)
        if (tid < 64) {
            int idx = bid * 64 + tid;
            out[idx] = g_h1[idx >> 9][idx & 511] + b2o[idx & 511];
        }
        int half = tid >> 7, t128 = tid & 127;
        int vb = bid * 2 + half;  // 0..511
        int fx = vb & 15, bh = (vb >> 4) & 3, iy = vb >> 6;  // iy 0..7
        int i0 = iy * 64, f = fx * 128 + t128;
        float* sh2 = SM + half * 512;        // [8 b][64 i]
        float* sln = SM + 1024 + half * 16;  // [8 b][2]
        // inline LN2 stats (16 threads per batch)
        {
            int bl = t128 >> 4, sub = t128 & 15;
            int b = bh * 8 + bl;
            const float4* hb = (const float4*)g_h1[b];
            float sum = 0.f, ssq = 0.f;
#pragma unroll
            for (int j = 0; j < 8; j++) {
                float4 v = hb[sub * 8 + j];
                sum += v.x + v.y + v.z + v.w;
                ssq += v.x * v.x + v.y * v.y + v.z * v.z + v.w * v.w;
            }
#pragma unroll
            for (int o = 8; o; o >>= 1) {
                sum += __shfl_xor_sync(0xffffffffu, sum, o);
                ssq += __shfl_xor_sync(0xffffffffu, ssq, o);
            }
            if (sub == 0) {
                float m = sum * (1.f / 512.f);
                float var = ssq * (1.f / 512.f) - m * m;
                sln[bl * 2] = m;
                sln[bl * 2 + 1] = rsqrtf(var + 1e-5f);
            }
        }
        __syncthreads();
#pragma unroll
        for (int j = 0; j < 4; j++) {
            int idx = t128 + j * 128;
            int bl = idx >> 6, ii = idx & 63;
            int b = bh * 8 + bl, i = i0 + ii;
            sh2[idx] = (g_h1[b][i] - sln[bl * 2]) * sln[bl * 2 + 1] * s2[i] + b2l[i];
        }
        __syncthreads();
        ull acc2[8];
#pragma unroll
        for (int bl = 0; bl < 8; bl++) acc2[bl] = 0ull;
#pragma unroll 4
        for (int ii = 0; ii < 64; ii += 4) {
            int i = i0 + ii;
            float w0 = W1[(size_t)i * 2048 + f];
            float w1 = W1[(size_t)(i + 1) * 2048 + f];
            float w2 = W1[(size_t)(i + 2) * 2048 + f];
            float w3 = W1[(size_t)(i + 3) * 2048 + f];
            ull w01 = pk(w0, w1), w23 = pk(w2, w3);
#pragma unroll
            for (int bl = 0; bl < 8; bl++) {
                const ull* pp = (const ull*)&sh2[bl * 64 + ii];
                fma2(acc2[bl], pp[0], w01);
                fma2(acc2[bl], pp[1], w23);
            }
        }
#pragma unroll
        for (int bl = 0; bl < 8; bl++) {
            float2 r = upk(acc2[bl]);
            g_w1part[iy][bh * 8 + bl][f] = r.x + r.y;
        }
    }
    gridbar(base, 4);

    // ============ T5: gelu + W2, atomic-accumulate into out (512 vblocks) ============
    {
        int half = tid >> 7, t128 = tid & 127;
        int vb = bid * 2 + half;  // 0..511
        int fx = vb & 3, bh = (vb >> 2) & 7, iy = vb >> 5;  // iy 0..15
        int i0 = iy * 128, f = fx * 128 + t128;
        float* su = SM + half * 512;  // [4 b][128 i]
        {
#pragma unroll
            for (int j = 0; j < 4; j++) {
                int idx = t128 + j * 128;
                int bl = idx >> 7, ii = idx & 127;
                int b = bh * 4 + bl, i = i0 + ii;
                float u = b1f[i];
#pragma unroll
                for (int s = 0; s < 8; s++) u += g_w1part[s][b][i];
                su[idx] = geluf(u);
            }
        }
        __syncthreads();
        ull acc2[4];
#pragma unroll
        for (int bl = 0; bl < 4; bl++) acc2[bl] = 0ull;
#pragma unroll 4
        for (int ii = 0; ii < 128; ii += 4) {
            int i = i0 + ii;
            float w0 = W2[(size_t)i * 512 + f];
            float w1 = W2[(size_t)(i + 1) * 512 + f];
            float w2 = W2[(size_t)(i + 2) * 512 + f];
            float w3 = W2[(size_t)(i + 3) * 512 + f];
            ull w01 = pk(w0, w1), w23 = pk(w2, w3);
#pragma unroll
            for (int bl = 0; bl < 4; bl++) {
                const ull* pp = (const ull*)&su[bl * 128 + ii];
                fma2(acc2[bl], pp[0], w01);
                fma2(acc2[bl], pp[1], w23);
            }
        }
#pragma unroll
        for (int bl = 0; bl < 4; bl++) {
            float2 r = upk(acc2[bl]);
            atomicAdd(&out[(bh * 4 + bl) * 512 + f], r.x + r.y);
        }
    }
}

extern "C" void kernel_launch(void* const* d_in, const int* in_sizes, int n_in,
                              void* d_out, int out_size) {
    const float* x     = (const float*)d_in[0];
    const int*   mask  = (const int*)d_in[1];
    const float* token = (const float*)d_in[2];
    const float* Wq    = (const float*)d_in[3];
    const float* bq    = (const float*)d_in[4];
    const float* Wk    = (const float*)d_in[5];
    // d_in[6] = bk: uniform shift across keys -> cancels in softmax; unused
    const float* Wv    = (const float*)d_in[7];
    const float* bv    = (const float*)d_in[8];
    const float* Wo    = (const float*)d_in[9];
    const float* bo    = (const float*)d_in[10];
    const float* s1    = (const float*)d_in[11];
    const float* b1    = (const float*)d_in[12];
    const float* s2    = (const float*)d_in[13];
    const float* b2l   = (const float*)d_in[14];
    const float* W1    = (const float*)d_in[15];
    const float* b1f   = (const float*)d_in[16];
    const float* W2    = (const float*)d_in[17];
    const float* b2o   = (const float*)d_in[18];
    float* out = (float*)d_out;

    fused_kernel<<<NB, NT>>>(x, mask, token, Wq, bq, Wk, Wv, bv, Wo, bo,
                             s1, b1, s2, b2l, W1, b1f, W2, b2o, out);
}